// round 13
// baseline (speedup 1.0000x reference)
#include <cuda_runtime.h>
#include <cuda_bf16.h>
#include <math.h>
#include <stddef.h>
#include <stdint.h>

// ---------------- problem constants ----------------
#define BATCH 4
#define SQL   1024
#define SKV   1024
#define DIM   1024
#define NH    16
#define DH    64
#define NEXP  8
#define HDIM  4096
#define NTOK  (BATCH*SQL)       // 4096
#define BH    (BATCH*NH)        // 64
#define OUT_MAIN (NTOK*DIM)
#define THRESH 0.05f
#define COEF   0.01f
#define KCH   64                // K chunk
#define RS    72                // smem row stride in u16 (64 data + 8 pad)

typedef unsigned short u16;
typedef unsigned int   u32;

// ---------------- static device scratch (fp32) ----------------
__device__ float g_qh[NTOK*DIM];
__device__ float g_kh[NTOK*DIM];
__device__ float g_vh[NTOK*DIM];
__device__ float g_ot[NTOK*DIM];
__device__ float g_a [NTOK*DIM];
__device__ float g_x [NTOK*DIM];
__device__ float g_e2[(size_t)NEXP*NTOK*DIM];   // 128 MB
__device__ int   g_cnt[NEXP];
__device__ int   g_tok[NEXP*NTOK];
__device__ float g_probs[NTOK*NEXP];
__device__ int   g_tcnt[NTOK];
__device__ int   g_te  [NTOK*3];
__device__ int   g_tslot[NTOK*3];
__device__ float g_tgate[NTOK*3];

// ---------------- bf16 hi/lo split buffers ----------------
__device__ u16 s_query_h[NTOK*DIM], s_query_l[NTOK*DIM];
__device__ u16 s_kv_h[NTOK*DIM],    s_kv_l[NTOK*DIM];
__device__ u16 s_q_h[NTOK*DIM],     s_q_l[NTOK*DIM];
__device__ u16 s_k_h[NTOK*DIM],     s_k_l[NTOK*DIM];
__device__ u16 s_v_h[NTOK*DIM],     s_v_l[NTOK*DIM];
__device__ u16 s_qt_h[NTOK*DIM],    s_qt_l[NTOK*DIM];    // [bh][sq][dh]
__device__ u16 s_kt_h[NTOK*DIM],    s_kt_l[NTOK*DIM];    // [bh][skv][dh]
__device__ u16 s_vt_h[NTOK*DIM],    s_vt_l[NTOK*DIM];    // [bh][dh][skv]
__device__ u16 s_o_h[NTOK*DIM],     s_o_l[NTOK*DIM];
__device__ u16 s_op_h[NTOK*DIM],    s_op_l[NTOK*DIM];
__device__ u16 s_x_h[NTOK*DIM],     s_x_l[NTOK*DIM];
__device__ u16 s_hh [(size_t)NEXP*NTOK*HDIM], s_hl[(size_t)NEXP*NTOK*HDIM];
// weights
__device__ u16 s_wq_h[DIM*DIM],   s_wq_l[DIM*DIM];
__device__ u16 s_wk_h[DIM*DIM],   s_wk_l[DIM*DIM];
__device__ u16 s_wv_h[DIM*DIM],   s_wv_l[DIM*DIM];
__device__ u16 s_win_h[3*DIM*DIM],s_win_l[3*DIM*DIM];
__device__ u16 s_wo_h[DIM*DIM],   s_wo_l[DIM*DIM];
__device__ u16 s_wa_h[DIM*DIM],   s_wa_l[DIM*DIM];
__device__ u16 s_e1_h[(size_t)NEXP*HDIM*DIM], s_e1_l[(size_t)NEXP*HDIM*DIM]; // [e][n=HDIM][k=DIM]
__device__ u16 s_e2_h[(size_t)NEXP*DIM*HDIM], s_e2_l[(size_t)NEXP*DIM*HDIM]; // [e][n=DIM][k=HDIM]

// ---------------- helpers ----------------
__device__ __forceinline__ u16 f2bf(float v) { __nv_bfloat16 b = __float2bfloat16(v); return *(u16*)&b; }
__device__ __forceinline__ float bf2f(u16 u) { __nv_bfloat16 b; *(u16*)&b = u; return __bfloat162float(b); }
__device__ __forceinline__ void split2(float v, u16& h, u16& l) {
    u16 hu = f2bf(v); h = hu; l = f2bf(v - bf2f(hu));
}
__device__ __forceinline__ void split_pack2(float v0, float v1, u32& h, u32& l) {
    u16 h0, l0, h1, l1;
    split2(v0, h0, l0); split2(v1, h1, l1);
    h = (u32)h0 | ((u32)h1 << 16);
    l = (u32)l0 | ((u32)l1 << 16);
}
__device__ __forceinline__ float gelu_exact(float v) {
    return 0.5f * v * (1.0f + erff(v * 0.70710678118654752f));
}
__device__ __forceinline__ u32 smem_u32(const void* p) {
    u32 a;
    asm("{ .reg .u64 t; cvta.to.shared.u64 t, %1; cvt.u32.u64 %0, t; }" : "=r"(a) : "l"(p));
    return a;
}
__device__ __forceinline__ float blk_reduce_sum(float v, float* sm) {
    int lane = threadIdx.x & 31, w = threadIdx.x >> 5;
    #pragma unroll
    for (int o = 16; o; o >>= 1) v += __shfl_down_sync(0xffffffffu, v, o);
    if (!lane) sm[w] = v;
    __syncthreads();
    if (threadIdx.x < 32) {
        v = (threadIdx.x < 8) ? sm[threadIdx.x] : 0.f;
        #pragma unroll
        for (int o = 4; o; o >>= 1) v += __shfl_down_sync(0xffffffffu, v, o);
        if (!threadIdx.x) sm[0] = v;
    }
    __syncthreads();
    float r = sm[0];
    __syncthreads();
    return r;
}

__device__ __forceinline__ void mma_bf16(float* c, const u32* a, const u32* b) {
    asm volatile(
        "mma.sync.aligned.m16n8k16.row.col.f32.bf16.bf16.f32 "
        "{%0,%1,%2,%3}, {%4,%5,%6,%7}, {%8,%9}, {%0,%1,%2,%3};"
        : "+f"(c[0]), "+f"(c[1]), "+f"(c[2]), "+f"(c[3])
        : "r"(a[0]), "r"(a[1]), "r"(a[2]), "r"(a[3]), "r"(b[0]), "r"(b[1]));
}

#define CP16(dst, src) \
    asm volatile("cp.async.cg.shared.global [%0], [%1], 16;" :: "r"(dst), "l"(src) : "memory")
#define CP_COMMIT() asm volatile("cp.async.commit_group;" ::: "memory")
#define CP_WAIT1()  asm volatile("cp.async.wait_group 1;" ::: "memory")
#define CP_WAIT2()  asm volatile("cp.async.wait_group 2;" ::: "memory")
#define LDMX4(r, addr) \
    asm volatile("ldmatrix.sync.aligned.m8n8.x4.shared.b16 {%0,%1,%2,%3}, [%4];" \
        : "=r"((r)[0]), "=r"((r)[1]), "=r"((r)[2]), "=r"((r)[3]) : "r"(addr))

// =====================================================================
// bf16-split tensor-core GEMM — 512 threads, 16 warps as 8(M) x 2(N),
// warp tile 32 x 64 (MI=2, NF=8). BM=256, BN=128. 2-stage cp.async.
// =====================================================================
template<int BM, int BN, bool GELU_, bool WF32, bool WSPLIT, bool GATHER>
__global__ __launch_bounds__(512, 1)
void gemm_tc(const u16* __restrict__ Ah_, const u16* __restrict__ Al_,
             const u16* __restrict__ Bh_, const u16* __restrict__ Bl_,
             int K, long long As, long long Bs, long long Cs,
             const int* __restrict__ rowmap, const int* __restrict__ cntArr,
             const float* __restrict__ bias, long long biasStride, float alpha,
             float* __restrict__ Cf, u16* __restrict__ Ch, u16* __restrict__ Cl, int ldc)
{
    extern __shared__ __align__(16) u16 smem[];
    const int z = blockIdx.z;
    const int cnt = cntArr ? cntArr[z] : 0x40000000;
    const int m0 = blockIdx.y * BM;
    if (m0 >= cnt) return;
    const int n0 = blockIdx.x * BN;

    const u16* Ah = Ah_ + (size_t)z * As;
    const u16* Al = Al_ + (size_t)z * As;
    const u16* Bh = Bh_ + (size_t)z * Bs;
    const u16* Bl = Bl_ + (size_t)z * Bs;
    if (WF32)   Cf += (size_t)z * Cs;
    if (WSPLIT) { Ch += (size_t)z * Cs; Cl += (size_t)z * Cs; }
    const float* bptr = bias ? bias + (size_t)z * biasStride : nullptr;
    const int* rmap = GATHER ? (rowmap + (size_t)z * NTOK) : nullptr;

    constexpr int ASZ = BM * RS;
    constexpr int BSZ = BN * RS;
    constexpr int STG = 2 * ASZ + 2 * BSZ;
    constexpr int WMR = BM / 8;              // 32 rows per warp
    constexpr int MI  = WMR / 16;            // 2
    constexpr int WN  = BN / 2;              // 64
    constexpr int NF  = WN / 8;              // 8
    constexpr int AIT = BM / 64;             // A loader iters (512 thr)
    constexpr int NBI = BN / 64;             // B loader iters

    const int tid = threadIdx.x;
    const int wid = tid >> 5, lane = tid & 31;
    const int wm = wid & 7, wn = wid >> 3;
    const u32 sb = smem_u32(smem);

    u32 aOff[AIT], aDst[AIT];
    #pragma unroll
    for (int it = 0; it < AIT; it++) {
        int idx = tid + it * 512;
        int row = idx >> 3, blk = idx & 7;
        int srow;
        if (GATHER) { int gm = m0 + row; if (gm >= cnt) gm = cnt - 1; srow = rmap[gm]; }
        else srow = m0 + row;
        aOff[it] = (u32)srow * (u32)K + blk * 8;
        aDst[it] = (u32)(row * RS + blk * 8) * 2;
    }
    u32 bOff[NBI], bDst[NBI];
    #pragma unroll
    for (int it = 0; it < NBI; it++) {
        int idx = tid + it * 512;
        int row = idx >> 3, blk = idx & 7;
        bOff[it] = (u32)(n0 + row) * (u32)K + blk * 8;
        bDst[it] = (u32)(2 * ASZ + row * RS + blk * 8) * 2;
    }

    auto load_chunk = [&](int c, int s) {
        const int k0 = c * KCH;
        const u32 base = sb + (u32)(s * STG) * 2;
        #pragma unroll
        for (int it = 0; it < AIT; it++) {
            CP16(base + aDst[it],           Ah + aOff[it] + k0);
            CP16(base + aDst[it] + ASZ * 2, Al + aOff[it] + k0);
        }
        #pragma unroll
        for (int it = 0; it < NBI; it++) {
            CP16(base + bDst[it],           Bh + bOff[it] + k0);
            CP16(base + bDst[it] + BSZ * 2, Bl + bOff[it] + k0);
        }
    };

    const int aRowO = ((lane >> 3) & 1) * 8 + (lane & 7);
    const int aKO   = ((lane >> 4) & 1) * 8;
    const int bRowO = ((lane >> 4) & 1) * 8 + (lane & 7);
    const int bKO   = ((lane >> 3) & 1) * 8;

    float acc[MI][NF][4];
    #pragma unroll
    for (int i = 0; i < MI; i++)
        #pragma unroll
        for (int j = 0; j < NF; j++)
            #pragma unroll
            for (int q = 0; q < 4; q++) acc[i][j][q] = 0.f;

    const int nch = K / KCH;

    load_chunk(0, 0);
    CP_COMMIT();
    if (nch > 1) load_chunk(1, 1);
    CP_COMMIT();

    for (int c = 0; c < nch; c++) {
        CP_WAIT1();
        __syncthreads();

        const u32 stB = sb + (u32)((c & 1) * STG) * 2;
        #pragma unroll
        for (int ks = 0; ks < 4; ks++) {
            u32 ah[MI][4], al[MI][4];
            #pragma unroll
            for (int mi = 0; mi < MI; mi++) {
                u32 ad = stB + (u32)((wm * WMR + mi * 16 + aRowO) * RS + ks * 16 + aKO) * 2;
                LDMX4(ah[mi], ad);
                LDMX4(al[mi], ad + ASZ * 2);
            }
            #pragma unroll
            for (int j = 0; j < NF / 2; j++) {
                u32 bd = stB + (u32)(2 * ASZ + (wn * WN + j * 16 + bRowO) * RS + ks * 16 + bKO) * 2;
                u32 th[4], tl[4];
                LDMX4(th, bd);
                LDMX4(tl, bd + BSZ * 2);
                u32 b0h[2] = { th[0], th[1] }, b1h[2] = { th[2], th[3] };
                u32 b0l[2] = { tl[0], tl[1] }, b1l[2] = { tl[2], tl[3] };
                // 4 distinct accumulators between same-acc reissues
                #pragma unroll
                for (int mi = 0; mi < MI; mi++) {
                    mma_bf16(acc[mi][2*j],   ah[mi], b0h);
                    mma_bf16(acc[mi][2*j+1], ah[mi], b1h);
                }
                #pragma unroll
                for (int mi = 0; mi < MI; mi++) {
                    mma_bf16(acc[mi][2*j],   al[mi], b0h);
                    mma_bf16(acc[mi][2*j+1], al[mi], b1h);
                }
                #pragma unroll
                for (int mi = 0; mi < MI; mi++) {
                    mma_bf16(acc[mi][2*j],   ah[mi], b0l);
                    mma_bf16(acc[mi][2*j+1], ah[mi], b1l);
                }
            }
        }
        __syncthreads();
        if (c + 2 < nch) load_chunk(c + 2, c & 1);
        CP_COMMIT();
    }

    const int gid = lane >> 2, tg = lane & 3;
    #pragma unroll
    for (int mi = 0; mi < MI; mi++) {
        #pragma unroll
        for (int nf = 0; nf < NF; nf++) {
            int mA  = m0 + wm * WMR + mi * 16 + gid;
            int col = n0 + wn * WN + nf * 8 + tg * 2;
            #pragma unroll
            for (int half = 0; half < 2; half++) {
                int m = mA + half * 8;
                if (m < cnt) {
                    float v0 = acc[mi][nf][half * 2 + 0] * alpha;
                    float v1 = acc[mi][nf][half * 2 + 1] * alpha;
                    if (bptr) { v0 += bptr[col]; v1 += bptr[col + 1]; }
                    if (GELU_) { v0 = gelu_exact(v0); v1 = gelu_exact(v1); }
                    size_t o = (size_t)m * ldc + col;
                    if (WF32) { Cf[o] = v0; Cf[o + 1] = v1; }
                    if (WSPLIT) {
                        u16 h0, l0, h1, l1;
                        split2(v0, h0, l0); split2(v1, h1, l1);
                        Ch[o] = h0; Ch[o + 1] = h1;
                        Cl[o] = l0; Cl[o + 1] = l1;
                    }
                }
            }
        }
    }
}

// =====================================================================
// Flash attention (unchanged from R12 winner)
// =====================================================================
__global__ __launch_bounds__(256, 1)
void flash_attn()
{
    extern __shared__ __align__(16) u16 smem[];
    const int z  = blockIdx.y;
    const int q0 = blockIdx.x * 128;
    const int tid = threadIdx.x, wid = tid >> 5, lane = tid & 31;
    const u32 sb = smem_u32(smem);

    constexpr int QSZ = 128 * RS;
    constexpr int KSZ = 64 * RS;
    constexpr int STG = 4 * KSZ;
    const u32 kvB = 2 * QSZ;

    #pragma unroll
    for (int j = 0; j < 4; j++) {
        int idx = tid + j * 256;
        int row = idx >> 3, blk = idx & 7;
        size_t src = ((size_t)(z * 1024 + q0 + row)) * 64 + blk * 8;
        u32 dst = sb + (u32)(row * RS + blk * 8) * 2;
        CP16(dst,           s_qt_h + src);
        CP16(dst + QSZ * 2, s_qt_l + src);
    }
    CP_COMMIT();

    auto load_kv = [&](int c, int s) {
        const int kv0 = c * 64;
        const u32 base = sb + (kvB + (u32)s * STG) * 2;
        #pragma unroll
        for (int j = 0; j < 2; j++) {
            int idx = tid + j * 256;
            int row = idx >> 3, blk = idx & 7;
            size_t ksrc = ((size_t)(z * 1024 + kv0 + row)) * 64 + blk * 8;
            size_t vsrc = ((size_t)(z * 64 + row)) * 1024 + kv0 + blk * 8;
            u32 d = (u32)(row * RS + blk * 8) * 2;
            CP16(base + d,               s_kt_h + ksrc);
            CP16(base + d + KSZ * 2,     s_kt_l + ksrc);
            CP16(base + d + 2 * KSZ * 2, s_vt_h + vsrc);
            CP16(base + d + 3 * KSZ * 2, s_vt_l + vsrc);
        }
    };

    load_kv(0, 0); CP_COMMIT();
    load_kv(1, 1); CP_COMMIT();

    const int aRowO = ((lane >> 3) & 1) * 8 + (lane & 7);
    const int aKO   = ((lane >> 4) & 1) * 8;
    const int bRowO = ((lane >> 4) & 1) * 8 + (lane & 7);
    const int bKO   = ((lane >> 3) & 1) * 8;

    CP_WAIT2();
    __syncthreads();
    u32 qhf[4][4], qlf[4][4];
    #pragma unroll
    for (int ks = 0; ks < 4; ks++) {
        u32 ad = sb + (u32)((wid * 16 + aRowO) * RS + ks * 16 + aKO) * 2;
        LDMX4(qhf[ks], ad);
        LDMX4(qlf[ks], ad + QSZ * 2);
    }

    float of[8][4];
    #pragma unroll
    for (int n = 0; n < 8; n++)
        #pragma unroll
        for (int q = 0; q < 4; q++) of[n][q] = 0.f;
    float m0 = -1e30f, m1 = -1e30f, l0 = 0.f, l1 = 0.f;

    for (int c = 0; c < 16; c++) {
        CP_WAIT1();
        __syncthreads();
        const u32 stB = sb + (kvB + (u32)((c & 1) * STG)) * 2;

        float sacc[8][4];
        #pragma unroll
        for (int n = 0; n < 8; n++)
            #pragma unroll
            for (int q = 0; q < 4; q++) sacc[n][q] = 0.f;

        #pragma unroll
        for (int ks = 0; ks < 4; ks++) {
            u32 b0h[4][2], b1h[4][2], b0l[4][2], b1l[4][2];
            #pragma unroll
            for (int j = 0; j < 4; j++) {
                u32 bd = stB + (u32)((j * 16 + bRowO) * RS + ks * 16 + bKO) * 2;
                u32 th[4], tl[4];
                LDMX4(th, bd);
                LDMX4(tl, bd + KSZ * 2);
                b0h[j][0] = th[0]; b0h[j][1] = th[1];
                b1h[j][0] = th[2]; b1h[j][1] = th[3];
                b0l[j][0] = tl[0]; b0l[j][1] = tl[1];
                b1l[j][0] = tl[2]; b1l[j][1] = tl[3];
            }
            #pragma unroll
            for (int j = 0; j < 4; j++) {
                mma_bf16(sacc[2*j],   qhf[ks], b0h[j]);
                mma_bf16(sacc[2*j+1], qhf[ks], b1h[j]);
            }
            #pragma unroll
            for (int j = 0; j < 4; j++) {
                mma_bf16(sacc[2*j],   qlf[ks], b0h[j]);
                mma_bf16(sacc[2*j+1], qlf[ks], b1h[j]);
            }
            #pragma unroll
            for (int j = 0; j < 4; j++) {
                mma_bf16(sacc[2*j],   qhf[ks], b0l[j]);
                mma_bf16(sacc[2*j+1], qhf[ks], b1l[j]);
            }
        }

        float mx0 = -1e30f, mx1 = -1e30f;
        #pragma unroll
        for (int n = 0; n < 8; n++) {
            #pragma unroll
            for (int q = 0; q < 4; q++) sacc[n][q] *= 0.125f;
            mx0 = fmaxf(mx0, fmaxf(sacc[n][0], sacc[n][1]));
            mx1 = fmaxf(mx1, fmaxf(sacc[n][2], sacc[n][3]));
        }
        mx0 = fmaxf(mx0, __shfl_xor_sync(0xffffffffu, mx0, 1));
        mx0 = fmaxf(mx0, __shfl_xor_sync(0xffffffffu, mx0, 2));
        mx1 = fmaxf(mx1, __shfl_xor_sync(0xffffffffu, mx1, 1));
        mx1 = fmaxf(mx1, __shfl_xor_sync(0xffffffffu, mx1, 2));
        float mn0 = fmaxf(m0, mx0), mn1 = fmaxf(m1, mx1);
        float sc0 = __expf(m0 - mn0), sc1 = __expf(m1 - mn1);
        m0 = mn0; m1 = mn1;
        float ps0 = 0.f, ps1 = 0.f;
        #pragma unroll
        for (int n = 0; n < 8; n++) {
            sacc[n][0] = __expf(sacc[n][0] - mn0);
            sacc[n][1] = __expf(sacc[n][1] - mn0);
            sacc[n][2] = __expf(sacc[n][2] - mn1);
            sacc[n][3] = __expf(sacc[n][3] - mn1);
            ps0 += sacc[n][0] + sacc[n][1];
            ps1 += sacc[n][2] + sacc[n][3];
        }
        ps0 += __shfl_xor_sync(0xffffffffu, ps0, 1);
        ps0 += __shfl_xor_sync(0xffffffffu, ps0, 2);
        ps1 += __shfl_xor_sync(0xffffffffu, ps1, 1);
        ps1 += __shfl_xor_sync(0xffffffffu, ps1, 2);
        l0 = l0 * sc0 + ps0;
        l1 = l1 * sc1 + ps1;
        #pragma unroll
        for (int n = 0; n < 8; n++) {
            of[n][0] *= sc0; of[n][1] *= sc0;
            of[n][2] *= sc1; of[n][3] *= sc1;
        }

        #pragma unroll
        for (int kk = 0; kk < 4; kk++) {
            u32 ph[4], pl[4];
            split_pack2(sacc[2*kk][0],   sacc[2*kk][1],   ph[0], pl[0]);
            split_pack2(sacc[2*kk][2],   sacc[2*kk][3],   ph[1], pl[1]);
            split_pack2(sacc[2*kk+1][0], sacc[2*kk+1][1], ph[2], pl[2]);
            split_pack2(sacc[2*kk+1][2], sacc[2*kk+1][3], ph[3], pl[3]);
            u32 b0h[4][2], b1h[4][2], b0l[4][2], b1l[4][2];
            #pragma unroll
            for (int j2 = 0; j2 < 4; j2++) {
                u32 vd = stB + (u32)(2 * KSZ) * 2
                       + (u32)((j2 * 16 + bRowO) * RS + kk * 16 + bKO) * 2;
                u32 th[4], tl[4];
                LDMX4(th, vd);
                LDMX4(tl, vd + KSZ * 2);
                b0h[j2][0] = th[0]; b0h[j2][1] = th[1];
                b1h[j2][0] = th[2]; b1h[j2][1] = th[3];
                b0l[j2][0] = tl[0]; b0l[j2][1] = tl[1];
                b1l[j2][0] = tl[2]; b1l[j2][1] = tl[3];
            }
            #pragma unroll
            for (int j2 = 0; j2 < 4; j2++) {
                mma_bf16(of[2*j2],   ph, b0h[j2]);
                mma_bf16(of[2*j2+1], ph, b1h[j2]);
            }
            #pragma unroll
            for (int j2 = 0; j2 < 4; j2++) {
                mma_bf16(of[2*j2],   pl, b0h[j2]);
                mma_bf16(of[2*j2+1], pl, b1h[j2]);
            }
            #pragma unroll
            for (int j2 = 0; j2 < 4; j2++) {
                mma_bf16(of[2*j2],   ph, b0l[j2]);
                mma_bf16(of[2*j2+1], ph, b1l[j2]);
            }
        }
        __syncthreads();
        if (c + 2 < 16) load_kv(c + 2, c & 1);
        CP_COMMIT();
    }

    const int gid = lane >> 2, tg = lane & 3;
    float inv0 = 1.f / l0, inv1 = 1.f / l1;
    int qr = q0 + wid * 16 + gid;
    #pragma unroll
    for (int n = 0; n < 8; n++) {
        int dh = n * 8 + tg * 2;
        float2 v0 = make_float2(of[n][0] * inv0, of[n][1] * inv0);
        float2 v1 = make_float2(of[n][2] * inv1, of[n][3] * inv1);
        *(float2*)&g_ot[((size_t)(z * 1024 + qr)) * 64 + dh]     = v0;
        *(float2*)&g_ot[((size_t)(z * 1024 + qr + 8)) * 64 + dh] = v1;
    }
}

// ---------------- fused conversion: split all inputs/weights in ONE launch ----------------
struct SplitSegs {
    const float4* s[8];
    uint2* h[8];
    uint2* l[8];
    int end4[8];
};
__global__ void split_all(SplitSegs g) {
    const int total = g.end4[7];
    for (int i = blockIdx.x * blockDim.x + threadIdx.x; i < total; i += gridDim.x * blockDim.x) {
        int k = 0;
        #pragma unroll
        for (int t = 0; t < 7; t++) k += (i >= g.end4[t]) ? 1 : 0;
        int j = i - (k ? g.end4[k - 1] : 0);
        float4 v = g.s[k][j];
        u16 hh[4], ll[4];
        split2(v.x, hh[0], ll[0]); split2(v.y, hh[1], ll[1]);
        split2(v.z, hh[2], ll[2]); split2(v.w, hh[3], ll[3]);
        g.h[k][j] = *(uint2*)hh;
        g.l[k][j] = *(uint2*)ll;
    }
}

__global__ void transpose_split(const float* __restrict__ s, u16* __restrict__ oh, u16* __restrict__ ol,
                                int R, int C) {
    __shared__ float t[32][33];
    size_t zo = (size_t)blockIdx.z * R * C;
    const float* src = s + zo;
    int c0 = blockIdx.x * 32, r0 = blockIdx.y * 32;
    int tx = threadIdx.x & 31, ty = threadIdx.x >> 5;
    #pragma unroll
    for (int dy = 0; dy < 32; dy += 8)
        t[ty + dy][tx] = src[(size_t)(r0 + ty + dy) * C + c0 + tx];
    __syncthreads();
    #pragma unroll
    for (int dy = 0; dy < 32; dy += 8) {
        float v = t[tx][ty + dy];
        size_t o = zo + (size_t)(c0 + ty + dy) * R + r0 + tx;
        u16 hh, ll; split2(v, hh, ll);
        oh[o] = hh; ol[o] = ll;
    }
}

__global__ void headsplit_qk(const float* __restrict__ in, u16* __restrict__ oh, u16* __restrict__ ol) {
    for (int i = blockIdx.x * blockDim.x + threadIdx.x; i < NTOK * DIM; i += gridDim.x * blockDim.x) {
        int d = i & 63, s = (i >> 6) & 1023, h = (i >> 16) & 15, b = i >> 20;
        float v = in[(size_t)((b << 10) + s) * DIM + (h << 6) + d];
        u16 hh, ll; split2(v, hh, ll);
        oh[i] = hh; ol[i] = ll;
    }
}

__global__ void headsplit_vT(const float* __restrict__ in, u16* __restrict__ oh, u16* __restrict__ ol) {
    __shared__ float t[32][33];
    int z = blockIdx.z;
    int b = z >> 4, h = z & 15;
    int s0 = blockIdx.x * 32, d0 = blockIdx.y * 32;
    int tx = threadIdx.x & 31, ty = threadIdx.x >> 5;
    #pragma unroll
    for (int dy = 0; dy < 32; dy += 8)
        t[ty + dy][tx] = in[(size_t)((b << 10) + s0 + ty + dy) * DIM + h * 64 + d0 + tx];
    __syncthreads();
    #pragma unroll
    for (int dy = 0; dy < 32; dy += 8) {
        float v = t[tx][ty + dy];
        size_t o = (size_t)(z * 64 + d0 + ty + dy) * 1024 + s0 + tx;
        u16 hh, ll; split2(v, hh, ll);
        oh[o] = hh; ol[o] = ll;
    }
}

__global__ void head_merge_split(const float* __restrict__ in, u16* __restrict__ oh, u16* __restrict__ ol) {
    for (int i = blockIdx.x * blockDim.x + threadIdx.x; i < NTOK * DIM; i += gridDim.x * blockDim.x) {
        int col = i & 1023, h = col >> 6, d = col & 63;
        int s = (i >> 10) & 1023, b = i >> 20;
        float v = in[(size_t)(((b << 4) + h) * 1024 + s) * 64 + d];
        u16 hh, ll; split2(v, hh, ll);
        oh[i] = hh; ol[i] = ll;
    }
}

__global__ void ln_res_split(const float* __restrict__ a, const float* __restrict__ res,
                             const float* __restrict__ g, const float* __restrict__ b,
                             float* __restrict__ of, u16* __restrict__ oh, u16* __restrict__ ol) {
    __shared__ float sm[32];
    const size_t base = (size_t)blockIdx.x * DIM;
    int t = threadIdx.x;
    float v[4];
    float s = 0.f;
    #pragma unroll
    for (int j = 0; j < 4; j++) {
        int c = t + j * 256;
        v[j] = a[base + c] + res[base + c];
        s += v[j];
    }
    s = blk_reduce_sum(s, sm);
    float mean = s * (1.0f / DIM);
    float s2 = 0.f;
    #pragma unroll
    for (int j = 0; j < 4; j++) { float d = v[j] - mean; s2 += d * d; }
    s2 = blk_reduce_sum(s2, sm);
    float rs = rsqrtf(s2 * (1.0f / DIM) + 1e-5f);
    #pragma unroll
    for (int j = 0; j < 4; j++) {
        int c = t + j * 256;
        float o = (v[j] - mean) * rs * g[c] + b[c];
        of[base + c] = o;
        u16 hh, ll; split2(o, hh, ll);
        oh[base + c] = hh; ol[base + c] = ll;
    }
}

__global__ void combine_ln(const float* __restrict__ g, const float* __restrict__ b,
                           float* __restrict__ out) {
    __shared__ float sm[32];
    const int tok = blockIdx.x;
    const size_t base = (size_t)tok * DIM;
    int t = threadIdx.x;
    float v[4];
    #pragma unroll
    for (int j = 0; j < 4; j++) v[j] = g_x[base + t + j * 256];
    const int nl = g_tcnt[tok];
    for (int l = 0; l < nl; l++) {
        int   e    = g_te[tok * 3 + l];
        int   slot = g_tslot[tok * 3 + l];
        float gt   = g_tgate[tok * 3 + l];
        const float* row = g_e2 + ((size_t)e * NTOK + slot) * DIM;
        #pragma unroll
        for (int j = 0; j < 4; j++) v[j] += gt * row[t + j * 256];
    }
    float s = 0.f;
    #pragma unroll
    for (int j = 0; j < 4; j++) s += v[j];
    s = blk_reduce_sum(s, sm);
    float mean = s * (1.0f / DIM);
    float s2 = 0.f;
    #pragma unroll
    for (int j = 0; j < 4; j++) { float d = v[j] - mean; s2 += d * d; }
    s2 = blk_reduce_sum(s2, sm);
    float rs = rsqrtf(s2 * (1.0f / DIM) + 1e-5f);
    #pragma unroll
    for (int j = 0; j < 4; j++) {
        int c = t + j * 256;
        out[base + c] = (v[j] - mean) * rs * g[c] + b[c];
    }
}

__global__ void gating(const float* __restrict__ Wg) {
    __shared__ float logits[NEXP];
    const int tok = blockIdx.x;
    const float* xr = g_x + (size_t)tok * DIM;
    int w = threadIdx.x >> 5, lane = threadIdx.x & 31;
    float s = 0.f;
    for (int i = lane; i < DIM; i += 32) s += xr[i] * Wg[i * NEXP + w];
    #pragma unroll
    for (int o = 16; o; o >>= 1) s += __shfl_down_sync(0xffffffffu, s, o);
    if (!lane) logits[w] = s;
    __syncthreads();
    if (threadIdx.x == 0) {
        float p[NEXP];
        float mx = -1e30f;
        for (int e = 0; e < NEXP; e++) mx = fmaxf(mx, logits[e]);
        float sum = 0.f;
        for (int e = 0; e < NEXP; e++) { p[e] = __expf(logits[e] - mx); sum += p[e]; }
        float inv = 1.f / sum;
        for (int e = 0; e < NEXP; e++) { p[e] *= inv; g_probs[tok * NEXP + e] = p[e]; }
        int i0 = 0;
        for (int e = 1; e < NEXP; e++) if (p[e] > p[i0]) i0 = e;
        int i1 = -1;
        for (int e = 0; e < NEXP; e++) if (e != i0 && (i1 < 0 || p[e] > p[i1])) i1 = e;
        int i2 = -1;
        for (int e = 0; e < NEXP; e++) if (e != i0 && e != i1 && (i2 < 0 || p[e] > p[i2])) i2 = e;
        int   ids[3] = { i0, i1, i2 };
        float gts[3] = { p[i0],
                         (p[i1] >= THRESH) ? p[i1] : 0.f,
                         (p[i2] >= THRESH) ? p[i2] : 0.f };
        int nl = 0;
        #pragma unroll
        for (int j = 0; j < 3; j++) {
            if (gts[j] > 0.f) {
                int slot = atomicAdd(&g_cnt[ids[j]], 1);
                g_tok  [ids[j] * NTOK + slot] = tok;
                g_te   [tok * 3 + nl] = ids[j];
                g_tslot[tok * 3 + nl] = slot;
                g_tgate[tok * 3 + nl] = gts[j];
                nl++;
            }
        }
        g_tcnt[tok] = nl;
    }
}

__global__ void zero_small() {
    int t = threadIdx.x;
    if (t < NEXP) g_cnt[t] = 0;
}
__global__ void aux_kernel(float* __restrict__ out, int out_size) {
    if (out_size <= OUT_MAIN) return;
    __shared__ float sm[32];
    int t = threadIdx.x;
    float total = 0.f;
    for (int e = 0; e < NEXP; e++) {
        float s = 0.f;
        for (int tok = t; tok < NTOK; tok += 256) s += g_probs[tok * NEXP + e];
        s = blk_reduce_sum(s, sm);
        if (t == 0) total += ((float)g_cnt[e] / (float)NTOK) * (s / (float)NTOK);
    }
    if (t == 0) out[OUT_MAIN] = COEF * (float)NEXP * total;
}

// ---------------- host launcher ----------------
#define GETSYM(var, sym) do { cudaGetSymbolAddress((void**)&(var), sym); } while (0)

extern "C" void kernel_launch(void* const* d_in, const int* in_sizes, int n_in,
                              void* d_out, int out_size)
{
    (void)in_sizes; (void)n_in;
    const float* query  = (const float*)d_in[0];
    const float* keyval = (const float*)d_in[1];
    const float* Wq = (const float*)d_in[2];  const float* bq = (const float*)d_in[3];
    const float* Wk = (const float*)d_in[4];  const float* bk = (const float*)d_in[5];
    const float* Wv = (const float*)d_in[6];  const float* bv = (const float*)d_in[7];
    const float* W_in  = (const float*)d_in[8];  const float* b_in  = (const float*)d_in[9];
    const float* W_out = (const float*)d_in[10]; const float* b_out = (const float*)d_in[11];
    const float* Wa = (const float*)d_in[12]; const float* ba = (const float*)d_in[13];
    const float* ln1g = (const float*)d_in[14]; const float* ln1b = (const float*)d_in[15];
    const float* Wg = (const float*)d_in[16];
    const float* ew1 = (const float*)d_in[17]; const float* eb1 = (const float*)d_in[18];
    const float* ew2 = (const float*)d_in[19]; const float* eb2 = (const float*)d_in[20];
    const float* ln2g = (const float*)d_in[21]; const float* ln2b = (const float*)d_in[22];
    float* out = (float*)d_out;

    float *qh, *kh, *vh, *ot, *a, *x, *e2p;
    GETSYM(qh, g_qh); GETSYM(kh, g_kh); GETSYM(vh, g_vh);
    GETSYM(ot, g_ot); GETSYM(a, g_a); GETSYM(x, g_x);
    GETSYM(e2p, g_e2);
    u16 *qyh,*qyl,*kvh,*kvl,*qsh,*qsl,*ksh,*ksl,*vsh,*vsl;
    u16 *qth,*qtl,*kth,*ktl,*vth,*vtl,*oh,*ol,*oph,*opl,*xh,*xl,*hhh,*hhl;
    u16 *wqh,*wql,*wkh,*wkl,*wvh,*wvl,*winh,*winl,*woh,*wol,*wah,*wal,*e1h,*e1l,*e2h,*e2l;
    GETSYM(qyh, s_query_h); GETSYM(qyl, s_query_l);
    GETSYM(kvh, s_kv_h);    GETSYM(kvl, s_kv_l);
    GETSYM(qsh, s_q_h);  GETSYM(qsl, s_q_l);
    GETSYM(ksh, s_k_h);  GETSYM(ksl, s_k_l);
    GETSYM(vsh, s_v_h);  GETSYM(vsl, s_v_l);
    GETSYM(qth, s_qt_h); GETSYM(qtl, s_qt_l);
    GETSYM(kth, s_kt_h); GETSYM(ktl, s_kt_l);
    GETSYM(vth, s_vt_h); GETSYM(vtl, s_vt_l);
    GETSYM(oh,  s_o_h);  GETSYM(ol,  s_o_l);
    GETSYM(oph, s_op_h); GETSYM(opl, s_op_l);
    GETSYM(xh,  s_x_h);  GETSYM(xl,  s_x_l);
    GETSYM(hhh, s_hh);   GETSYM(hhl, s_hl);
    GETSYM(wqh, s_wq_h); GETSYM(wql, s_wq_l);
    GETSYM(wkh, s_wk_h); GETSYM(wkl, s_wk_l);
    GETSYM(wvh, s_wv_h); GETSYM(wvl, s_wv_l);
    GETSYM(winh, s_win_h); GETSYM(winl, s_win_l);
    GETSYM(woh, s_wo_h); GETSYM(wol, s_wo_l);
    GETSYM(wah, s_wa_h); GETSYM(wal, s_wa_l);
    GETSYM(e1h, s_e1_h); GETSYM(e1l, s_e1_l);
    GETSYM(e2h, s_e2_h); GETSYM(e2l, s_e2_l);
    int *tokp; GETSYM(tokp, g_tok);
    int *cntp; GETSYM(cntp, g_cnt);

    const int S256_128 = 2 * 2 * (256 + 128) * RS * 2;          // 221184 B
    const int SFLASH   = (2 * 128 * RS + 2 * 4 * 64 * RS) * 2;  // 110592 B
    cudaFuncSetAttribute((const void*)gemm_tc<256,128,false,false,true ,false>, cudaFuncAttributeMaxDynamicSharedMemorySize, S256_128);
    cudaFuncSetAttribute((const void*)gemm_tc<256,128,false,true ,false,false>, cudaFuncAttributeMaxDynamicSharedMemorySize, S256_128);
    cudaFuncSetAttribute((const void*)gemm_tc<256,128,true ,false,true ,true >, cudaFuncAttributeMaxDynamicSharedMemorySize, S256_128);
    cudaFuncSetAttribute((const void*)flash_attn, cudaFuncAttributeMaxDynamicSharedMemorySize, SFLASH);

    const dim3 T512(512);
    const dim3 T256(256);
    const dim3 GLIN(DIM/128, NTOK/256, 1);

    // ---- ONE fused split for all fp32->bf16hi/lo conversions ----
    SplitSegs sg;
    const float* srcs[8] = { query, keyval, Wq, Wk, Wv, W_in, W_out, Wa };
    u16* dh[8] = { qyh, kvh, wqh, wkh, wvh, winh, woh, wah };
    u16* dl[8] = { qyl, kvl, wql, wkl, wvl, winl, wol, wal };
    int  ns[8] = { NTOK*DIM, NTOK*DIM, DIM*DIM, DIM*DIM, DIM*DIM, 3*DIM*DIM, DIM*DIM, DIM*DIM };
    int cum = 0;
    for (int i = 0; i < 8; i++) {
        sg.s[i] = (const float4*)srcs[i];
        sg.h[i] = (uint2*)dh[i];
        sg.l[i] = (uint2*)dl[i];
        cum += ns[i] / 4;
        sg.end4[i] = cum;
    }

    split_all<<<2048, 256>>>(sg);
    gemm_tc<256,128,false,false,true,false><<<GLIN, T512, S256_128>>>(
        qyh, qyl, wqh, wql, DIM, 0, 0, 0, nullptr, nullptr, bq, 0, 1.f, nullptr, qsh, qsl, DIM);
    gemm_tc<256,128,false,false,true,false><<<GLIN, T512, S256_128>>>(
        kvh, kvl, wkh, wkl, DIM, 0, 0, 0, nullptr, nullptr, bk, 0, 1.f, nullptr, ksh, ksl, DIM);
    gemm_tc<256,128,false,false,true,false><<<GLIN, T512, S256_128>>>(
        kvh, kvl, wvh, wvl, DIM, 0, 0, 0, nullptr, nullptr, bv, 0, 1.f, nullptr, vsh, vsl, DIM);
    gemm_tc<256,128,false,true,false,false><<<GLIN, T512, S256_128>>>(
        qsh, qsl, winh,              winl,              DIM, 0, 0, 0, nullptr, nullptr, b_in,        0, 1.f, qh, nullptr, nullptr, DIM);
    gemm_tc<256,128,false,true,false,false><<<GLIN, T512, S256_128>>>(
        ksh, ksl, winh + DIM*DIM,    winl + DIM*DIM,    DIM, 0, 0, 0, nullptr, nullptr, b_in + DIM,  0, 1.f, kh, nullptr, nullptr, DIM);
    gemm_tc<256,128,false,true,false,false><<<GLIN, T512, S256_128>>>(
        vsh, vsl, winh + 2*DIM*DIM,  winl + 2*DIM*DIM,  DIM, 0, 0, 0, nullptr, nullptr, b_in + 2*DIM,0, 1.f, vh, nullptr, nullptr, DIM);

    // ---- head reshape ----
    headsplit_qk<<<512, 256>>>(qh, qth, qtl);
    headsplit_qk<<<512, 256>>>(kh, kth, ktl);
    headsplit_vT<<<dim3(SQL/32, 2, BH), T256>>>(vh, vth, vtl);

    // ---- fused flash attention -> g_ot ----
    flash_attn<<<dim3(SQL/128, BH), T256, SFLASH>>>();

    head_merge_split<<<512, 256>>>(ot, oh, ol);

    // ---- out-projection + adapter ----
    gemm_tc<256,128,false,false,true,false><<<GLIN, T512, S256_128>>>(
        oh, ol, woh, wol, DIM, 0, 0, 0, nullptr, nullptr, b_out, 0, 1.f, nullptr, oph, opl, DIM);
    gemm_tc<256,128,false,true,false,false><<<GLIN, T512, S256_128>>>(
        oph, opl, wah, wal, DIM, 0, 0, 0, nullptr, nullptr, ba, 0, 1.f, a, nullptr, nullptr, DIM);

    // ---- LN1 (+residual) -> x fp32 + split ----
    ln_res_split<<<NTOK, T256>>>(a, query, ln1g, ln1b, x, xh, xl);

    // ---- gating ----
    zero_small<<<1, 32>>>();
    gating<<<NTOK, T256>>>(Wg);

    // ---- MoE expert weights + FFNs ----
    transpose_split<<<dim3(HDIM/32, DIM/32, NEXP), T256>>>(ew1, e1h, e1l, DIM, HDIM);
    transpose_split<<<dim3(DIM/32, HDIM/32, NEXP), T256>>>(ew2, e2h, e2l, HDIM, DIM);
    gemm_tc<256,128,true,false,true,true><<<dim3(HDIM/128, NTOK/256, NEXP), T512, S256_128>>>(
        xh, xl, e1h, e1l, DIM,
        0, (long long)HDIM*DIM, (long long)NTOK*HDIM,
        tokp, cntp, eb1, HDIM, 1.f, nullptr, hhh, hhl, HDIM);
    gemm_tc<256,128,false,true,false,false><<<dim3(DIM/128, NTOK/256, NEXP), T512, S256_128>>>(
        hhh, hhl, e2h, e2l, HDIM,
        (long long)NTOK*HDIM, (long long)DIM*HDIM, (long long)NTOK*DIM,
        nullptr, cntp, eb2, DIM, 1.f, e2p, nullptr, nullptr, DIM);

    // ---- fused combine + final LN -> output, then aux scalar ----
    combine_ln<<<NTOK, T256>>>(ln2g, ln2b, out);
    aux_kernel<<<1, 256>>>(out, out_size);
}

// round 14
// speedup vs baseline: 1.2492x; 1.2492x over previous
#include <cuda_runtime.h>
#include <cuda_fp16.h>
#include <math.h>
#include <stddef.h>
#include <stdint.h>

// ---------------- problem constants ----------------
#define BATCH 4
#define SQL   1024
#define SKV   1024
#define DIM   1024
#define NH    16
#define DH    64
#define NEXP  8
#define HDIM  4096
#define NTOK  (BATCH*SQL)       // 4096
#define BH    (BATCH*NH)        // 64
#define OUT_MAIN (NTOK*DIM)
#define THRESH 0.05f
#define COEF   0.01f
#define KCH   64                // K chunk
#define RS    72                // smem row stride in u16 (64 data + 8 pad)

typedef unsigned short u16;
typedef unsigned int   u32;

// ---------------- static device scratch (fp32) ----------------
__device__ float g_qh[NTOK*DIM];
__device__ float g_kh[NTOK*DIM];
__device__ float g_vh[NTOK*DIM];
__device__ float g_ot[NTOK*DIM];
__device__ float g_a [NTOK*DIM];
__device__ float g_x [NTOK*DIM];
__device__ float g_e2[(size_t)NEXP*NTOK*DIM];   // 128 MB
__device__ int   g_cnt[NEXP];
__device__ int   g_tok[NEXP*NTOK];
__device__ float g_probs[NTOK*NEXP];
__device__ int   g_tcnt[NTOK];
__device__ int   g_te  [NTOK*3];
__device__ int   g_tslot[NTOK*3];
__device__ float g_tgate[NTOK*3];
__device__ float g_bcq[DIM], g_bck[DIM], g_bcv[DIM], g_bcoa[DIM];

// ---------------- fp16 hi/lo split buffers ----------------
__device__ u16 s_query_h[NTOK*DIM], s_query_l[NTOK*DIM];
__device__ u16 s_kv_h[NTOK*DIM],    s_kv_l[NTOK*DIM];
__device__ u16 s_qt_h[NTOK*DIM],    s_qt_l[NTOK*DIM];    // [bh][sq][dh]
__device__ u16 s_kt_h[NTOK*DIM];                          // [bh][skv][dh]
__device__ u16 s_vt_h[NTOK*DIM];                          // [bh][dh][skv]
__device__ u16 s_o_h[NTOK*DIM],     s_o_l[NTOK*DIM];
__device__ u16 s_x_h[NTOK*DIM],     s_x_l[NTOK*DIM];
__device__ u16 s_hh [(size_t)NEXP*NTOK*HDIM], s_hl[(size_t)NEXP*NTOK*HDIM];
// weights (split)
__device__ u16 s_win_h[3*DIM*DIM], s_win_l[3*DIM*DIM];
__device__ u16 s_wa_h[DIM*DIM],    s_wa_l[DIM*DIM];
__device__ u16 s_wqT_h[DIM*DIM],   s_wqT_l[DIM*DIM];
__device__ u16 s_wkT_h[DIM*DIM],   s_wkT_l[DIM*DIM];
__device__ u16 s_wvT_h[DIM*DIM],   s_wvT_l[DIM*DIM];
__device__ u16 s_woT_h[DIM*DIM],   s_woT_l[DIM*DIM];
__device__ u16 s_wcq_h[DIM*DIM],   s_wcq_l[DIM*DIM];
__device__ u16 s_wck_h[DIM*DIM],   s_wck_l[DIM*DIM];
__device__ u16 s_wcv_h[DIM*DIM],   s_wcv_l[DIM*DIM];
__device__ u16 s_wcoa_h[DIM*DIM],  s_wcoa_l[DIM*DIM];
__device__ u16 s_e1_h[(size_t)NEXP*HDIM*DIM];   // [e][n=HDIM][k=DIM]
__device__ u16 s_e2_h[(size_t)NEXP*DIM*HDIM];   // [e][n=DIM][k=HDIM]

// ---------------- helpers ----------------
__device__ __forceinline__ u16 f2h(float v) { __half h = __float2half_rn(v); return *(u16*)&h; }
__device__ __forceinline__ float h2f(u16 u) { __half h; *(u16*)&h = u; return __half2float(h); }
__device__ __forceinline__ void split2(float v, u16& h, u16& l) {
    u16 hu = f2h(v); h = hu; l = f2h(v - h2f(hu));
}
__device__ __forceinline__ void split_pack2(float v0, float v1, u32& h, u32& l) {
    u16 h0, l0, h1, l1;
    split2(v0, h0, l0); split2(v1, h1, l1);
    h = (u32)h0 | ((u32)h1 << 16);
    l = (u32)l0 | ((u32)l1 << 16);
}
__device__ __forceinline__ float gelu_exact(float v) {
    return 0.5f * v * (1.0f + erff(v * 0.70710678118654752f));
}
__device__ __forceinline__ u32 smem_u32(const void* p) {
    u32 a;
    asm("{ .reg .u64 t; cvta.to.shared.u64 t, %1; cvt.u32.u64 %0, t; }" : "=r"(a) : "l"(p));
    return a;
}
__device__ __forceinline__ float blk_reduce_sum(float v, float* sm) {
    int lane = threadIdx.x & 31, w = threadIdx.x >> 5;
    #pragma unroll
    for (int o = 16; o; o >>= 1) v += __shfl_down_sync(0xffffffffu, v, o);
    if (!lane) sm[w] = v;
    __syncthreads();
    if (threadIdx.x < 32) {
        v = (threadIdx.x < 8) ? sm[threadIdx.x] : 0.f;
        #pragma unroll
        for (int o = 4; o; o >>= 1) v += __shfl_down_sync(0xffffffffu, v, o);
        if (!threadIdx.x) sm[0] = v;
    }
    __syncthreads();
    float r = sm[0];
    __syncthreads();
    return r;
}

__device__ __forceinline__ void mma_f16(float* c, const u32* a, const u32* b) {
    asm volatile(
        "mma.sync.aligned.m16n8k16.row.col.f32.f16.f16.f32 "
        "{%0,%1,%2,%3}, {%4,%5,%6,%7}, {%8,%9}, {%0,%1,%2,%3};"
        : "+f"(c[0]), "+f"(c[1]), "+f"(c[2]), "+f"(c[3])
        : "r"(a[0]), "r"(a[1]), "r"(a[2]), "r"(a[3]), "r"(b[0]), "r"(b[1]));
}

#define CP16(dst, src) \
    asm volatile("cp.async.cg.shared.global [%0], [%1], 16;" :: "r"(dst), "l"(src) : "memory")
#define CP_COMMIT() asm volatile("cp.async.commit_group;" ::: "memory")
#define CP_WAIT1()  asm volatile("cp.async.wait_group 1;" ::: "memory")
#define CP_WAIT2()  asm volatile("cp.async.wait_group 2;" ::: "memory")
#define LDMX4(r, addr) \
    asm volatile("ldmatrix.sync.aligned.m8n8.x4.shared.b16 {%0,%1,%2,%3}, [%4];" \
        : "=r"((r)[0]), "=r"((r)[1]), "=r"((r)[2]), "=r"((r)[3]) : "r"(addr))

// =====================================================================
// fp16-split tensor-core GEMM. C[z] = alpha*(A@B^T) + bias.
// NP=2: A split hi/lo, B single fp16 (2 products). NP=3: both split
// (3 products, for high-precision weight composition).
// 512 threads, 16 warps 8(M)x2(N), BM=256, BN=128, 2-stage cp.async.
// =====================================================================
template<int NP, int BM, int BN, bool GELU_, bool WF32, bool WSPLIT, bool GATHER>
__global__ __launch_bounds__(512, 1)
void gemm_tc(const u16* __restrict__ Ah_, const u16* __restrict__ Al_,
             const u16* __restrict__ Bh_, const u16* __restrict__ Bl_,
             int K, long long As, long long Bs, long long Cs,
             const int* __restrict__ rowmap, const int* __restrict__ cntArr,
             const float* __restrict__ bias, long long biasStride, float alpha,
             float* __restrict__ Cf, u16* __restrict__ Ch, u16* __restrict__ Cl, int ldc)
{
    extern __shared__ __align__(16) u16 smem[];
    const int z = blockIdx.z;
    const int cnt = cntArr ? cntArr[z] : 0x40000000;
    const int m0 = blockIdx.y * BM;
    if (m0 >= cnt) return;
    const int n0 = blockIdx.x * BN;

    const u16* Ah = Ah_ + (size_t)z * As;
    const u16* Al = Al_ + (size_t)z * As;
    const u16* Bh = Bh_ + (size_t)z * Bs;
    const u16* Bl = (NP == 3) ? (Bl_ + (size_t)z * Bs) : nullptr;
    if (WF32)   Cf += (size_t)z * Cs;
    if (WSPLIT) { Ch += (size_t)z * Cs; Cl += (size_t)z * Cs; }
    const float* bptr = bias ? bias + (size_t)z * biasStride : nullptr;
    const int* rmap = GATHER ? (rowmap + (size_t)z * NTOK) : nullptr;

    constexpr int ASZ = BM * RS;
    constexpr int BSZ = BN * RS;
    constexpr int NBT = (NP == 3) ? 2 : 1;
    constexpr int STG = 2 * ASZ + NBT * BSZ;
    constexpr int WMR = BM / 8;
    constexpr int MI  = WMR / 16;
    constexpr int WN  = BN / 2;
    constexpr int NF  = WN / 8;
    constexpr int AIT = BM / 64;
    constexpr int NBI = BN / 64;

    const int tid = threadIdx.x;
    const int wid = tid >> 5, lane = tid & 31;
    const int wm = wid & 7, wn = wid >> 3;
    const u32 sb = smem_u32(smem);

    u32 aOff[AIT], aDst[AIT];
    #pragma unroll
    for (int it = 0; it < AIT; it++) {
        int idx = tid + it * 512;
        int row = idx >> 3, blk = idx & 7;
        int srow;
        if (GATHER) { int gm = m0 + row; if (gm >= cnt) gm = cnt - 1; srow = rmap[gm]; }
        else srow = m0 + row;
        aOff[it] = (u32)srow * (u32)K + blk * 8;
        aDst[it] = (u32)(row * RS + blk * 8) * 2;
    }
    u32 bOff[NBI], bDst[NBI];
    #pragma unroll
    for (int it = 0; it < NBI; it++) {
        int idx = tid + it * 512;
        int row = idx >> 3, blk = idx & 7;
        bOff[it] = (u32)(n0 + row) * (u32)K + blk * 8;
        bDst[it] = (u32)(2 * ASZ + row * RS + blk * 8) * 2;
    }

    auto load_chunk = [&](int c, int s) {
        const int k0 = c * KCH;
        const u32 base = sb + (u32)(s * STG) * 2;
        #pragma unroll
        for (int it = 0; it < AIT; it++) {
            CP16(base + aDst[it],           Ah + aOff[it] + k0);
            CP16(base + aDst[it] + ASZ * 2, Al + aOff[it] + k0);
        }
        #pragma unroll
        for (int it = 0; it < NBI; it++) {
            CP16(base + bDst[it], Bh + bOff[it] + k0);
            if (NP == 3) CP16(base + bDst[it] + BSZ * 2, Bl + bOff[it] + k0);
        }
    };

    const int aRowO = ((lane >> 3) & 1) * 8 + (lane & 7);
    const int aKO   = ((lane >> 4) & 1) * 8;
    const int bRowO = ((lane >> 4) & 1) * 8 + (lane & 7);
    const int bKO   = ((lane >> 3) & 1) * 8;

    float acc[MI][NF][4];
    #pragma unroll
    for (int i = 0; i < MI; i++)
        #pragma unroll
        for (int j = 0; j < NF; j++)
            #pragma unroll
            for (int q = 0; q < 4; q++) acc[i][j][q] = 0.f;

    const int nch = K / KCH;

    load_chunk(0, 0);
    CP_COMMIT();
    if (nch > 1) load_chunk(1, 1);
    CP_COMMIT();

    for (int c = 0; c < nch; c++) {
        CP_WAIT1();
        __syncthreads();

        const u32 stB = sb + (u32)((c & 1) * STG) * 2;
        #pragma unroll
        for (int ks = 0; ks < 4; ks++) {
            u32 ah[MI][4], al[MI][4];
            #pragma unroll
            for (int mi = 0; mi < MI; mi++) {
                u32 ad = stB + (u32)((wm * WMR + mi * 16 + aRowO) * RS + ks * 16 + aKO) * 2;
                LDMX4(ah[mi], ad);
                LDMX4(al[mi], ad + ASZ * 2);
            }
            #pragma unroll
            for (int j = 0; j < NF / 2; j++) {
                u32 bd = stB + (u32)(2 * ASZ + (wn * WN + j * 16 + bRowO) * RS + ks * 16 + bKO) * 2;
                u32 th[4];
                LDMX4(th, bd);
                u32 b0h[2] = { th[0], th[1] }, b1h[2] = { th[2], th[3] };
                #pragma unroll
                for (int mi = 0; mi < MI; mi++) {
                    mma_f16(acc[mi][2*j],   ah[mi], b0h);
                    mma_f16(acc[mi][2*j+1], ah[mi], b1h);
                }
                #pragma unroll
                for (int mi = 0; mi < MI; mi++) {
                    mma_f16(acc[mi][2*j],   al[mi], b0h);
                    mma_f16(acc[mi][2*j+1], al[mi], b1h);
                }
                if (NP == 3) {
                    u32 tl[4];
                    LDMX4(tl, bd + BSZ * 2);
                    u32 b0l[2] = { tl[0], tl[1] }, b1l[2] = { tl[2], tl[3] };
                    #pragma unroll
                    for (int mi = 0; mi < MI; mi++) {
                        mma_f16(acc[mi][2*j],   ah[mi], b0l);
                        mma_f16(acc[mi][2*j+1], ah[mi], b1l);
                    }
                }
            }
        }
        __syncthreads();
        if (c + 2 < nch) load_chunk(c + 2, c & 1);
        CP_COMMIT();
    }

    const int gid = lane >> 2, tg = lane & 3;
    #pragma unroll
    for (int mi = 0; mi < MI; mi++) {
        #pragma unroll
        for (int nf = 0; nf < NF; nf++) {
            int mA  = m0 + wm * WMR + mi * 16 + gid;
            int col = n0 + wn * WN + nf * 8 + tg * 2;
            #pragma unroll
            for (int half = 0; half < 2; half++) {
                int m = mA + half * 8;
                if (m < cnt) {
                    float v0 = acc[mi][nf][half * 2 + 0] * alpha;
                    float v1 = acc[mi][nf][half * 2 + 1] * alpha;
                    if (bptr) { v0 += bptr[col]; v1 += bptr[col + 1]; }
                    if (GELU_) { v0 = gelu_exact(v0); v1 = gelu_exact(v1); }
                    size_t o = (size_t)m * ldc + col;
                    if (WF32) { Cf[o] = v0; Cf[o + 1] = v1; }
                    if (WSPLIT) {
                        u16 h0, l0, h1, l1;
                        split2(v0, h0, l0); split2(v1, h1, l1);
                        Ch[o] = h0; Ch[o + 1] = h1;
                        Cl[o] = l0; Cl[o + 1] = l1;
                    }
                }
            }
        }
    }
}

// =====================================================================
// Flash attention, fp16 2-product: Q split vs K single; P split vs V single.
// =====================================================================
__global__ __launch_bounds__(256, 1)
void flash_attn()
{
    extern __shared__ __align__(16) u16 smem[];
    const int z  = blockIdx.y;
    const int q0 = blockIdx.x * 128;
    const int tid = threadIdx.x, wid = tid >> 5, lane = tid & 31;
    const u32 sb = smem_u32(smem);

    constexpr int QSZ = 128 * RS;
    constexpr int KSZ = 64 * RS;
    constexpr int STG = 2 * KSZ;          // Kh, Vh
    const u32 kvB = 2 * QSZ;

    #pragma unroll
    for (int j = 0; j < 4; j++) {
        int idx = tid + j * 256;
        int row = idx >> 3, blk = idx & 7;
        size_t src = ((size_t)(z * 1024 + q0 + row)) * 64 + blk * 8;
        u32 dst = sb + (u32)(row * RS + blk * 8) * 2;
        CP16(dst,           s_qt_h + src);
        CP16(dst + QSZ * 2, s_qt_l + src);
    }
    CP_COMMIT();

    auto load_kv = [&](int c, int s) {
        const int kv0 = c * 64;
        const u32 base = sb + (kvB + (u32)s * STG) * 2;
        #pragma unroll
        for (int j = 0; j < 2; j++) {
            int idx = tid + j * 256;
            int row = idx >> 3, blk = idx & 7;
            size_t ksrc = ((size_t)(z * 1024 + kv0 + row)) * 64 + blk * 8;
            size_t vsrc = ((size_t)(z * 64 + row)) * 1024 + kv0 + blk * 8;
            u32 d = (u32)(row * RS + blk * 8) * 2;
            CP16(base + d,           s_kt_h + ksrc);
            CP16(base + d + KSZ * 2, s_vt_h + vsrc);
        }
    };

    load_kv(0, 0); CP_COMMIT();
    load_kv(1, 1); CP_COMMIT();

    const int aRowO = ((lane >> 3) & 1) * 8 + (lane & 7);
    const int aKO   = ((lane >> 4) & 1) * 8;
    const int bRowO = ((lane >> 4) & 1) * 8 + (lane & 7);
    const int bKO   = ((lane >> 3) & 1) * 8;

    CP_WAIT2();
    __syncthreads();
    u32 qhf[4][4], qlf[4][4];
    #pragma unroll
    for (int ks = 0; ks < 4; ks++) {
        u32 ad = sb + (u32)((wid * 16 + aRowO) * RS + ks * 16 + aKO) * 2;
        LDMX4(qhf[ks], ad);
        LDMX4(qlf[ks], ad + QSZ * 2);
    }

    float of[8][4];
    #pragma unroll
    for (int n = 0; n < 8; n++)
        #pragma unroll
        for (int q = 0; q < 4; q++) of[n][q] = 0.f;
    float m0 = -1e30f, m1 = -1e30f, l0 = 0.f, l1 = 0.f;

    for (int c = 0; c < 16; c++) {
        CP_WAIT1();
        __syncthreads();
        const u32 stB = sb + (kvB + (u32)((c & 1) * STG)) * 2;

        float sacc[8][4];
        #pragma unroll
        for (int n = 0; n < 8; n++)
            #pragma unroll
            for (int q = 0; q < 4; q++) sacc[n][q] = 0.f;

        #pragma unroll
        for (int ks = 0; ks < 4; ks++) {
            u32 b0h[4][2], b1h[4][2];
            #pragma unroll
            for (int j = 0; j < 4; j++) {
                u32 bd = stB + (u32)((j * 16 + bRowO) * RS + ks * 16 + bKO) * 2;
                u32 th[4];
                LDMX4(th, bd);
                b0h[j][0] = th[0]; b0h[j][1] = th[1];
                b1h[j][0] = th[2]; b1h[j][1] = th[3];
            }
            #pragma unroll
            for (int j = 0; j < 4; j++) {
                mma_f16(sacc[2*j],   qhf[ks], b0h[j]);
                mma_f16(sacc[2*j+1], qhf[ks], b1h[j]);
            }
            #pragma unroll
            for (int j = 0; j < 4; j++) {
                mma_f16(sacc[2*j],   qlf[ks], b0h[j]);
                mma_f16(sacc[2*j+1], qlf[ks], b1h[j]);
            }
        }

        float mx0 = -1e30f, mx1 = -1e30f;
        #pragma unroll
        for (int n = 0; n < 8; n++) {
            #pragma unroll
            for (int q = 0; q < 4; q++) sacc[n][q] *= 0.125f;
            mx0 = fmaxf(mx0, fmaxf(sacc[n][0], sacc[n][1]));
            mx1 = fmaxf(mx1, fmaxf(sacc[n][2], sacc[n][3]));
        }
        mx0 = fmaxf(mx0, __shfl_xor_sync(0xffffffffu, mx0, 1));
        mx0 = fmaxf(mx0, __shfl_xor_sync(0xffffffffu, mx0, 2));
        mx1 = fmaxf(mx1, __shfl_xor_sync(0xffffffffu, mx1, 1));
        mx1 = fmaxf(mx1, __shfl_xor_sync(0xffffffffu, mx1, 2));
        float mn0 = fmaxf(m0, mx0), mn1 = fmaxf(m1, mx1);
        float sc0 = __expf(m0 - mn0), sc1 = __expf(m1 - mn1);
        m0 = mn0; m1 = mn1;
        float ps0 = 0.f, ps1 = 0.f;
        #pragma unroll
        for (int n = 0; n < 8; n++) {
            sacc[n][0] = __expf(sacc[n][0] - mn0);
            sacc[n][1] = __expf(sacc[n][1] - mn0);
            sacc[n][2] = __expf(sacc[n][2] - mn1);
            sacc[n][3] = __expf(sacc[n][3] - mn1);
            ps0 += sacc[n][0] + sacc[n][1];
            ps1 += sacc[n][2] + sacc[n][3];
        }
        ps0 += __shfl_xor_sync(0xffffffffu, ps0, 1);
        ps0 += __shfl_xor_sync(0xffffffffu, ps0, 2);
        ps1 += __shfl_xor_sync(0xffffffffu, ps1, 1);
        ps1 += __shfl_xor_sync(0xffffffffu, ps1, 2);
        l0 = l0 * sc0 + ps0;
        l1 = l1 * sc1 + ps1;
        #pragma unroll
        for (int n = 0; n < 8; n++) {
            of[n][0] *= sc0; of[n][1] *= sc0;
            of[n][2] *= sc1; of[n][3] *= sc1;
        }

        #pragma unroll
        for (int kk = 0; kk < 4; kk++) {
            u32 ph[4], pl[4];
            split_pack2(sacc[2*kk][0],   sacc[2*kk][1],   ph[0], pl[0]);
            split_pack2(sacc[2*kk][2],   sacc[2*kk][3],   ph[1], pl[1]);
            split_pack2(sacc[2*kk+1][0], sacc[2*kk+1][1], ph[2], pl[2]);
            split_pack2(sacc[2*kk+1][2], sacc[2*kk+1][3], ph[3], pl[3]);
            u32 b0h[4][2], b1h[4][2];
            #pragma unroll
            for (int j2 = 0; j2 < 4; j2++) {
                u32 vd = stB + (u32)(KSZ) * 2
                       + (u32)((j2 * 16 + bRowO) * RS + kk * 16 + bKO) * 2;
                u32 th[4];
                LDMX4(th, vd);
                b0h[j2][0] = th[0]; b0h[j2][1] = th[1];
                b1h[j2][0] = th[2]; b1h[j2][1] = th[3];
            }
            #pragma unroll
            for (int j2 = 0; j2 < 4; j2++) {
                mma_f16(of[2*j2],   ph, b0h[j2]);
                mma_f16(of[2*j2+1], ph, b1h[j2]);
            }
            #pragma unroll
            for (int j2 = 0; j2 < 4; j2++) {
                mma_f16(of[2*j2],   pl, b0h[j2]);
                mma_f16(of[2*j2+1], pl, b1h[j2]);
            }
        }
        __syncthreads();
        if (c + 2 < 16) load_kv(c + 2, c & 1);
        CP_COMMIT();
    }

    const int gid = lane >> 2, tg = lane & 3;
    float inv0 = 1.f / l0, inv1 = 1.f / l1;
    int qr = q0 + wid * 16 + gid;
    #pragma unroll
    for (int n = 0; n < 8; n++) {
        int dh = n * 8 + tg * 2;
        float2 v0 = make_float2(of[n][0] * inv0, of[n][1] * inv0);
        float2 v1 = make_float2(of[n][2] * inv1, of[n][3] * inv1);
        *(float2*)&g_ot[((size_t)(z * 1024 + qr)) * 64 + dh]     = v0;
        *(float2*)&g_ot[((size_t)(z * 1024 + qr + 8)) * 64 + dh] = v1;
    }
}

// ---------------- fused conversion ----------------
struct SplitSegs {
    const float4* s[4];
    uint2* h[4];
    uint2* l[4];
    int end4[4];
};
__global__ void split_all(SplitSegs g) {
    const int total = g.end4[3];
    for (int i = blockIdx.x * blockDim.x + threadIdx.x; i < total; i += gridDim.x * blockDim.x) {
        int k = 0;
        #pragma unroll
        for (int t = 0; t < 3; t++) k += (i >= g.end4[t]) ? 1 : 0;
        int j = i - (k ? g.end4[k - 1] : 0);
        float4 v = g.s[k][j];
        u16 hh[4], ll[4];
        split2(v.x, hh[0], ll[0]); split2(v.y, hh[1], ll[1]);
        split2(v.z, hh[2], ll[2]); split2(v.w, hh[3], ll[3]);
        g.h[k][j] = *(uint2*)hh;
        g.l[k][j] = *(uint2*)ll;
    }
}

__global__ void transpose_split(const float* __restrict__ s, u16* __restrict__ oh, u16* __restrict__ ol,
                                int R, int C) {
    __shared__ float t[32][33];
    size_t zo = (size_t)blockIdx.z * R * C;
    const float* src = s + zo;
    int c0 = blockIdx.x * 32, r0 = blockIdx.y * 32;
    int tx = threadIdx.x & 31, ty = threadIdx.x >> 5;
    #pragma unroll
    for (int dy = 0; dy < 32; dy += 8)
        t[ty + dy][tx] = src[(size_t)(r0 + ty + dy) * C + c0 + tx];
    __syncthreads();
    #pragma unroll
    for (int dy = 0; dy < 32; dy += 8) {
        float v = t[tx][ty + dy];
        size_t o = zo + (size_t)(c0 + ty + dy) * R + r0 + tx;
        u16 hh, ll; split2(v, hh, ll);
        oh[o] = hh;
        if (ol) ol[o] = ll;
    }
}

// bc[i] = sum_m W[i,m]*bin[m] + badd[i]
__global__ void bias_comb(const float* __restrict__ W, const float* __restrict__ bin,
                          const float* __restrict__ badd, float* __restrict__ bc) {
    __shared__ float sm[32];
    int i = blockIdx.x, t = threadIdx.x;
    float s = 0.f;
    for (int m = t; m < DIM; m += 256) s += W[(size_t)i * DIM + m] * bin[m];
    s = blk_reduce_sum(s, sm);
    if (t == 0) bc[i] = s + badd[i];
}

__global__ void headsplit_qk(const float* __restrict__ in, u16* __restrict__ oh, u16* __restrict__ ol) {
    for (int i = blockIdx.x * blockDim.x + threadIdx.x; i < NTOK * DIM; i += gridDim.x * blockDim.x) {
        int d = i & 63, s = (i >> 6) & 1023, h = (i >> 16) & 15, b = i >> 20;
        float v = in[(size_t)((b << 10) + s) * DIM + (h << 6) + d];
        u16 hh, ll; split2(v, hh, ll);
        oh[i] = hh;
        if (ol) ol[i] = ll;
    }
}

__global__ void headsplit_vT(const float* __restrict__ in, u16* __restrict__ oh) {
    __shared__ float t[32][33];
    int z = blockIdx.z;
    int b = z >> 4, h = z & 15;
    int s0 = blockIdx.x * 32, d0 = blockIdx.y * 32;
    int tx = threadIdx.x & 31, ty = threadIdx.x >> 5;
    #pragma unroll
    for (int dy = 0; dy < 32; dy += 8)
        t[ty + dy][tx] = in[(size_t)((b << 10) + s0 + ty + dy) * DIM + h * 64 + d0 + tx];
    __syncthreads();
    #pragma unroll
    for (int dy = 0; dy < 32; dy += 8) {
        float v = t[tx][ty + dy];
        size_t o = (size_t)(z * 64 + d0 + ty + dy) * 1024 + s0 + tx;
        oh[o] = f2h(v);
    }
}

__global__ void head_merge_split(const float* __restrict__ in, u16* __restrict__ oh, u16* __restrict__ ol) {
    for (int i = blockIdx.x * blockDim.x + threadIdx.x; i < NTOK * DIM; i += gridDim.x * blockDim.x) {
        int col = i & 1023, h = col >> 6, d = col & 63;
        int s = (i >> 10) & 1023, b = i >> 20;
        float v = in[(size_t)(((b << 4) + h) * 1024 + s) * 64 + d];
        u16 hh, ll; split2(v, hh, ll);
        oh[i] = hh; ol[i] = ll;
    }
}

__global__ void ln_res_split(const float* __restrict__ a, const float* __restrict__ res,
                             const float* __restrict__ g, const float* __restrict__ b,
                             float* __restrict__ of, u16* __restrict__ oh, u16* __restrict__ ol) {
    __shared__ float sm[32];
    const size_t base = (size_t)blockIdx.x * DIM;
    int t = threadIdx.x;
    float v[4];
    float s = 0.f;
    #pragma unroll
    for (int j = 0; j < 4; j++) {
        int c = t + j * 256;
        v[j] = a[base + c] + res[base + c];
        s += v[j];
    }
    s = blk_reduce_sum(s, sm);
    float mean = s * (1.0f / DIM);
    float s2 = 0.f;
    #pragma unroll
    for (int j = 0; j < 4; j++) { float d = v[j] - mean; s2 += d * d; }
    s2 = blk_reduce_sum(s2, sm);
    float rs = rsqrtf(s2 * (1.0f / DIM) + 1e-5f);
    #pragma unroll
    for (int j = 0; j < 4; j++) {
        int c = t + j * 256;
        float o = (v[j] - mean) * rs * g[c] + b[c];
        of[base + c] = o;
        u16 hh, ll; split2(o, hh, ll);
        oh[base + c] = hh; ol[base + c] = ll;
    }
}

__global__ void combine_ln(const float* __restrict__ g, const float* __restrict__ b,
                           float* __restrict__ out) {
    __shared__ float sm[32];
    const int tok = blockIdx.x;
    const size_t base = (size_t)tok * DIM;
    int t = threadIdx.x;
    float v[4];
    #pragma unroll
    for (int j = 0; j < 4; j++) v[j] = g_x[base + t + j * 256];
    const int nl = g_tcnt[tok];
    for (int l = 0; l < nl; l++) {
        int   e    = g_te[tok * 3 + l];
        int   slot = g_tslot[tok * 3 + l];
        float gt   = g_tgate[tok * 3 + l];
        const float* row = g_e2 + ((size_t)e * NTOK + slot) * DIM;
        #pragma unroll
        for (int j = 0; j < 4; j++) v[j] += gt * row[t + j * 256];
    }
    float s = 0.f;
    #pragma unroll
    for (int j = 0; j < 4; j++) s += v[j];
    s = blk_reduce_sum(s, sm);
    float mean = s * (1.0f / DIM);
    float s2 = 0.f;
    #pragma unroll
    for (int j = 0; j < 4; j++) { float d = v[j] - mean; s2 += d * d; }
    s2 = blk_reduce_sum(s2, sm);
    float rs = rsqrtf(s2 * (1.0f / DIM) + 1e-5f);
    #pragma unroll
    for (int j = 0; j < 4; j++) {
        int c = t + j * 256;
        out[base + c] = (v[j] - mean) * rs * g[c] + b[c];
    }
}

__global__ void gating(const float* __restrict__ Wg) {
    __shared__ float logits[NEXP];
    const int tok = blockIdx.x;
    const float* xr = g_x + (size_t)tok * DIM;
    int w = threadIdx.x >> 5, lane = threadIdx.x & 31;
    float s = 0.f;
    for (int i = lane; i < DIM; i += 32) s += xr[i] * Wg[i * NEXP + w];
    #pragma unroll
    for (int o = 16; o; o >>= 1) s += __shfl_down_sync(0xffffffffu, s, o);
    if (!lane) logits[w] = s;
    __syncthreads();
    if (threadIdx.x == 0) {
        float p[NEXP];
        float mx = -1e30f;
        for (int e = 0; e < NEXP; e++) mx = fmaxf(mx, logits[e]);
        float sum = 0.f;
        for (int e = 0; e < NEXP; e++) { p[e] = __expf(logits[e] - mx); sum += p[e]; }
        float inv = 1.f / sum;
        for (int e = 0; e < NEXP; e++) { p[e] *= inv; g_probs[tok * NEXP + e] = p[e]; }
        int i0 = 0;
        for (int e = 1; e < NEXP; e++) if (p[e] > p[i0]) i0 = e;
        int i1 = -1;
        for (int e = 0; e < NEXP; e++) if (e != i0 && (i1 < 0 || p[e] > p[i1])) i1 = e;
        int i2 = -1;
        for (int e = 0; e < NEXP; e++) if (e != i0 && e != i1 && (i2 < 0 || p[e] > p[i2])) i2 = e;
        int   ids[3] = { i0, i1, i2 };
        float gts[3] = { p[i0],
                         (p[i1] >= THRESH) ? p[i1] : 0.f,
                         (p[i2] >= THRESH) ? p[i2] : 0.f };
        int nl = 0;
        #pragma unroll
        for (int j = 0; j < 3; j++) {
            if (gts[j] > 0.f) {
                int slot = atomicAdd(&g_cnt[ids[j]], 1);
                g_tok  [ids[j] * NTOK + slot] = tok;
                g_te   [tok * 3 + nl] = ids[j];
                g_tslot[tok * 3 + nl] = slot;
                g_tgate[tok * 3 + nl] = gts[j];
                nl++;
            }
        }
        g_tcnt[tok] = nl;
    }
}

__global__ void zero_small() {
    int t = threadIdx.x;
    if (t < NEXP) g_cnt[t] = 0;
}
__global__ void aux_kernel(float* __restrict__ out, int out_size) {
    if (out_size <= OUT_MAIN) return;
    __shared__ float sm[32];
    int t = threadIdx.x;
    float total = 0.f;
    for (int e = 0; e < NEXP; e++) {
        float s = 0.f;
        for (int tok = t; tok < NTOK; tok += 256) s += g_probs[tok * NEXP + e];
        s = blk_reduce_sum(s, sm);
        if (t == 0) total += ((float)g_cnt[e] / (float)NTOK) * (s / (float)NTOK);
    }
    if (t == 0) out[OUT_MAIN] = COEF * (float)NEXP * total;
}

// ---------------- host launcher ----------------
#define GETSYM(var, sym) do { cudaGetSymbolAddress((void**)&(var), sym); } while (0)

extern "C" void kernel_launch(void* const* d_in, const int* in_sizes, int n_in,
                              void* d_out, int out_size)
{
    (void)in_sizes; (void)n_in;
    const float* query  = (const float*)d_in[0];
    const float* keyval = (const float*)d_in[1];
    const float* Wq = (const float*)d_in[2];  const float* bq = (const float*)d_in[3];
    const float* Wk = (const float*)d_in[4];  const float* bk = (const float*)d_in[5];
    const float* Wv = (const float*)d_in[6];  const float* bv = (const float*)d_in[7];
    const float* W_in  = (const float*)d_in[8];  const float* b_in  = (const float*)d_in[9];
    const float* W_out = (const float*)d_in[10]; const float* b_out = (const float*)d_in[11];
    const float* Wa = (const float*)d_in[12]; const float* ba = (const float*)d_in[13];
    const float* ln1g = (const float*)d_in[14]; const float* ln1b = (const float*)d_in[15];
    const float* Wg = (const float*)d_in[16];
    const float* ew1 = (const float*)d_in[17]; const float* eb1 = (const float*)d_in[18];
    const float* ew2 = (const float*)d_in[19]; const float* eb2 = (const float*)d_in[20];
    const float* ln2g = (const float*)d_in[21]; const float* ln2b = (const float*)d_in[22];
    float* out = (float*)d_out;

    float *qh, *kh, *vh, *ot, *a, *x, *e2p, *bcq, *bck, *bcv, *bcoa;
    GETSYM(qh, g_qh); GETSYM(kh, g_kh); GETSYM(vh, g_vh);
    GETSYM(ot, g_ot); GETSYM(a, g_a); GETSYM(x, g_x);
    GETSYM(e2p, g_e2);
    GETSYM(bcq, g_bcq); GETSYM(bck, g_bck); GETSYM(bcv, g_bcv); GETSYM(bcoa, g_bcoa);
    u16 *qyh,*qyl,*kvh,*kvl,*qth,*qtl,*kth,*vth,*oh,*ol,*xh,*xl,*hhh,*hhl;
    u16 *winh,*winl,*wah,*wal;
    u16 *wqTh,*wqTl,*wkTh,*wkTl,*wvTh,*wvTl,*woTh,*woTl;
    u16 *wcqh,*wcql,*wckh,*wckl,*wcvh,*wcvl,*wcoah,*wcoal;
    u16 *e1h,*e2h;
    GETSYM(qyh, s_query_h); GETSYM(qyl, s_query_l);
    GETSYM(kvh, s_kv_h);    GETSYM(kvl, s_kv_l);
    GETSYM(qth, s_qt_h); GETSYM(qtl, s_qt_l);
    GETSYM(kth, s_kt_h);
    GETSYM(vth, s_vt_h);
    GETSYM(oh,  s_o_h);  GETSYM(ol,  s_o_l);
    GETSYM(xh,  s_x_h);  GETSYM(xl,  s_x_l);
    GETSYM(hhh, s_hh);   GETSYM(hhl, s_hl);
    GETSYM(winh, s_win_h); GETSYM(winl, s_win_l);
    GETSYM(wah, s_wa_h);   GETSYM(wal, s_wa_l);
    GETSYM(wqTh, s_wqT_h); GETSYM(wqTl, s_wqT_l);
    GETSYM(wkTh, s_wkT_h); GETSYM(wkTl, s_wkT_l);
    GETSYM(wvTh, s_wvT_h); GETSYM(wvTl, s_wvT_l);
    GETSYM(woTh, s_woT_h); GETSYM(woTl, s_woT_l);
    GETSYM(wcqh, s_wcq_h); GETSYM(wcql, s_wcq_l);
    GETSYM(wckh, s_wck_h); GETSYM(wckl, s_wck_l);
    GETSYM(wcvh, s_wcv_h); GETSYM(wcvl, s_wcv_l);
    GETSYM(wcoah, s_wcoa_h); GETSYM(wcoal, s_wcoa_l);
    GETSYM(e1h, s_e1_h); GETSYM(e2h, s_e2_h);
    int *tokp; GETSYM(tokp, g_tok);
    int *cntp; GETSYM(cntp, g_cnt);

    const int SM_NP2 = 2 * (2 * 256 + 128) * RS * 2;        // 184320 B
    const int SM_NP3 = 2 * (2 * 256 + 2 * 128) * RS * 2;    // 221184 B
    const int SFLASH = (2 * 128 + 2 * 2 * 64) * RS * 2;     // 73728 B
    cudaFuncSetAttribute((const void*)gemm_tc<2,256,128,false,true ,false,false>, cudaFuncAttributeMaxDynamicSharedMemorySize, SM_NP2);
    cudaFuncSetAttribute((const void*)gemm_tc<2,256,128,true ,false,true ,true >, cudaFuncAttributeMaxDynamicSharedMemorySize, SM_NP2);
    cudaFuncSetAttribute((const void*)gemm_tc<3,256,128,false,false,true ,false>, cudaFuncAttributeMaxDynamicSharedMemorySize, SM_NP3);
    cudaFuncSetAttribute((const void*)flash_attn, cudaFuncAttributeMaxDynamicSharedMemorySize, SFLASH);

    const dim3 T512(512);
    const dim3 T256(256);
    const dim3 GLIN(DIM/128, NTOK/256, 1);
    const dim3 GW(DIM/128, DIM/256, 1);      // 1024x1024 weight composition

    // ---- fused fp16 split of inputs + A-side weights ----
    SplitSegs sg;
    const float* srcs[4] = { query, keyval, W_in, Wa };
    u16* dh[4] = { qyh, kvh, winh, wah };
    u16* dl[4] = { qyl, kvl, winl, wal };
    int  ns[4] = { NTOK*DIM, NTOK*DIM, 3*DIM*DIM, DIM*DIM };
    int cum = 0;
    for (int i = 0; i < 4; i++) {
        sg.s[i] = (const float4*)srcs[i];
        sg.h[i] = (uint2*)dh[i];
        sg.l[i] = (uint2*)dl[i];
        cum += ns[i] / 4;
        sg.end4[i] = cum;
    }
    split_all<<<2048, 256>>>(sg);

    // ---- transposed splits of B-side weights ----
    transpose_split<<<dim3(DIM/32, DIM/32, 1), T256>>>(Wq, wqTh, wqTl, DIM, DIM);
    transpose_split<<<dim3(DIM/32, DIM/32, 1), T256>>>(Wk, wkTh, wkTl, DIM, DIM);
    transpose_split<<<dim3(DIM/32, DIM/32, 1), T256>>>(Wv, wvTh, wvTl, DIM, DIM);
    transpose_split<<<dim3(DIM/32, DIM/32, 1), T256>>>(W_out, woTh, woTl, DIM, DIM);

    // ---- weight composition (NP=3, high precision): Wc = Wi @ W ----
    gemm_tc<3,256,128,false,false,true,false><<<GW, T512, SM_NP3>>>(
        winh, winl, wqTh, wqTl, DIM, 0, 0, 0, nullptr, nullptr, nullptr, 0, 1.f,
        nullptr, wcqh, wcql, DIM);
    gemm_tc<3,256,128,false,false,true,false><<<GW, T512, SM_NP3>>>(
        winh + DIM*DIM, winl + DIM*DIM, wkTh, wkTl, DIM, 0, 0, 0, nullptr, nullptr, nullptr, 0, 1.f,
        nullptr, wckh, wckl, DIM);
    gemm_tc<3,256,128,false,false,true,false><<<GW, T512, SM_NP3>>>(
        winh + 2*DIM*DIM, winl + 2*DIM*DIM, wvTh, wvTl, DIM, 0, 0, 0, nullptr, nullptr, nullptr, 0, 1.f,
        nullptr, wcvh, wcvl, DIM);
    gemm_tc<3,256,128,false,false,true,false><<<GW, T512, SM_NP3>>>(
        wah, wal, woTh, woTl, DIM, 0, 0, 0, nullptr, nullptr, nullptr, 0, 1.f,
        nullptr, wcoah, wcoal, DIM);

    // ---- combined biases (fp32 exact) ----
    bias_comb<<<DIM, T256>>>(W_in,              bq, b_in,           bcq);
    bias_comb<<<DIM, T256>>>(W_in + DIM*DIM,    bk, b_in + DIM,     bck);
    bias_comb<<<DIM, T256>>>(W_in + 2*DIM*DIM,  bv, b_in + 2*DIM,   bcv);
    bias_comb<<<DIM, T256>>>(Wa,                b_out, ba,          bcoa);

    // ---- token linears (NP=2): qh/kh/vh direct from inputs ----
    gemm_tc<2,256,128,false,true,false,false><<<GLIN, T512, SM_NP2>>>(
        qyh, qyl, wcqh, nullptr, DIM, 0, 0, 0, nullptr, nullptr, bcq, 0, 1.f, qh, nullptr, nullptr, DIM);
    gemm_tc<2,256,128,false,true,false,false><<<GLIN, T512, SM_NP2>>>(
        kvh, kvl, wckh, nullptr, DIM, 0, 0, 0, nullptr, nullptr, bck, 0, 1.f, kh, nullptr, nullptr, DIM);
    gemm_tc<2,256,128,false,true,false,false><<<GLIN, T512, SM_NP2>>>(
        kvh, kvl, wcvh, nullptr, DIM, 0, 0, 0, nullptr, nullptr, bcv, 0, 1.f, vh, nullptr, nullptr, DIM);

    // ---- head reshape ----
    headsplit_qk<<<512, 256>>>(qh, qth, qtl);
    headsplit_qk<<<512, 256>>>(kh, kth, nullptr);
    headsplit_vT<<<dim3(SQL/32, 2, BH), T256>>>(vh, vth);

    // ---- fused flash attention -> g_ot ----
    flash_attn<<<dim3(SQL/128, BH), T256, SFLASH>>>();

    head_merge_split<<<512, 256>>>(ot, oh, ol);

    // ---- combined out-projection + adapter (NP=2) ----
    gemm_tc<2,256,128,false,true,false,false><<<GLIN, T512, SM_NP2>>>(
        oh, ol, wcoah, nullptr, DIM, 0, 0, 0, nullptr, nullptr, bcoa, 0, 1.f, a, nullptr, nullptr, DIM);

    // ---- LN1 (+residual) -> x fp32 + split ----
    ln_res_split<<<NTOK, T256>>>(a, query, ln1g, ln1b, x, xh, xl);

    // ---- gating ----
    zero_small<<<1, 32>>>();
    gating<<<NTOK, T256>>>(Wg);

    // ---- MoE expert weights (hi only) + FFNs (NP=2) ----
    transpose_split<<<dim3(HDIM/32, DIM/32, NEXP), T256>>>(ew1, e1h, nullptr, DIM, HDIM);
    transpose_split<<<dim3(DIM/32, HDIM/32, NEXP), T256>>>(ew2, e2h, nullptr, HDIM, DIM);
    gemm_tc<2,256,128,true,false,true,true><<<dim3(HDIM/128, NTOK/256, NEXP), T512, SM_NP2>>>(
        xh, xl, e1h, nullptr, DIM,
        0, (long long)HDIM*DIM, (long long)NTOK*HDIM,
        tokp, cntp, eb1, HDIM, 1.f, nullptr, hhh, hhl, HDIM);
    gemm_tc<2,256,128,false,true,false,false><<<dim3(DIM/128, NTOK/256, NEXP), T512, SM_NP2>>>(
        hhh, hhl, e2h, nullptr, HDIM,
        (long long)NTOK*HDIM, (long long)DIM*HDIM, (long long)NTOK*DIM,
        nullptr, cntp, eb2, DIM, 1.f, e2p, nullptr, nullptr, DIM);

    // ---- fused combine + final LN -> output, then aux scalar ----
    combine_ln<<<NTOK, T256>>>(ln2g, ln2b, out);
    aux_kernel<<<1, 256>>>(out, out_size);
}

// round 15
// speedup vs baseline: 1.4134x; 1.1315x over previous
#include <cuda_runtime.h>
#include <cuda_fp16.h>
#include <math.h>
#include <stddef.h>
#include <stdint.h>

// ---------------- problem constants ----------------
#define BATCH 4
#define SQL   1024
#define SKV   1024
#define DIM   1024
#define NH    16
#define DH    64
#define NEXP  8
#define HDIM  4096
#define NTOK  (BATCH*SQL)       // 4096
#define BH    (BATCH*NH)        // 64
#define OUT_MAIN (NTOK*DIM)
#define THRESH 0.05f
#define COEF   0.01f
#define KCH   64                // K chunk
#define RS    72                // smem row stride in u16 (64 data + 8 pad)

typedef unsigned short u16;
typedef unsigned int   u32;

// ---------------- static device scratch (fp32) ----------------
__device__ float g_qh[NTOK*DIM];
__device__ float g_kh[NTOK*DIM];
__device__ float g_vh[NTOK*DIM];
__device__ float g_ot[NTOK*DIM];
__device__ float g_a [NTOK*DIM];
__device__ float g_x [NTOK*DIM];
__device__ float g_e2[(size_t)NEXP*NTOK*DIM];   // 128 MB
__device__ int   g_cnt[NEXP];
__device__ int   g_tok[NEXP*NTOK];
__device__ float g_probs[NTOK*NEXP];
__device__ int   g_tcnt[NTOK];
__device__ int   g_te  [NTOK*3];
__device__ int   g_tslot[NTOK*3];
__device__ float g_tgate[NTOK*3];
__device__ float g_bc[4*DIM];          // combined biases: q,k,v,oa

// ---------------- fp16 hi/lo split buffers ----------------
__device__ u16 s_query_h[NTOK*DIM], s_query_l[NTOK*DIM];
__device__ u16 s_kv_h[NTOK*DIM],    s_kv_l[NTOK*DIM];
__device__ u16 s_qt_h[NTOK*DIM],    s_qt_l[NTOK*DIM];    // [bh][sq][dh]
__device__ u16 s_kt_h[NTOK*DIM];                          // [bh][skv][dh]
__device__ u16 s_vt_h[NTOK*DIM];                          // [bh][dh][skv]
__device__ u16 s_o_h[NTOK*DIM],     s_o_l[NTOK*DIM];
__device__ u16 s_x_h[NTOK*DIM],     s_x_l[NTOK*DIM];
__device__ u16 s_hh [(size_t)NEXP*NTOK*HDIM], s_hl[(size_t)NEXP*NTOK*HDIM];
// weights: packed 4x DIM^2 arrays for batched composition
__device__ u16 s_wA_h[4*DIM*DIM], s_wA_l[4*DIM*DIM];      // [Win q,k,v | Wa]
__device__ u16 s_wT_h[4*DIM*DIM], s_wT_l[4*DIM*DIM];      // [WqT,WkT,WvT,WoT]
__device__ u16 s_wc_h[4*DIM*DIM], s_wc_l[4*DIM*DIM];      // composed
__device__ u16 s_e1_h[(size_t)NEXP*HDIM*DIM];   // [e][n=HDIM][k=DIM]
__device__ u16 s_e2_h[(size_t)NEXP*DIM*HDIM];   // [e][n=DIM][k=HDIM]

// ---------------- helpers ----------------
__device__ __forceinline__ u16 f2h(float v) { __half h = __float2half_rn(v); return *(u16*)&h; }
__device__ __forceinline__ float h2f(u16 u) { __half h; *(u16*)&h = u; return __half2float(h); }
__device__ __forceinline__ void split2(float v, u16& h, u16& l) {
    u16 hu = f2h(v); h = hu; l = f2h(v - h2f(hu));
}
__device__ __forceinline__ void split_pack2(float v0, float v1, u32& h, u32& l) {
    u16 h0, l0, h1, l1;
    split2(v0, h0, l0); split2(v1, h1, l1);
    h = (u32)h0 | ((u32)h1 << 16);
    l = (u32)l0 | ((u32)l1 << 16);
}
__device__ __forceinline__ float gelu_exact(float v) {
    return 0.5f * v * (1.0f + erff(v * 0.70710678118654752f));
}
__device__ __forceinline__ u32 smem_u32(const void* p) {
    u32 a;
    asm("{ .reg .u64 t; cvta.to.shared.u64 t, %1; cvt.u32.u64 %0, t; }" : "=r"(a) : "l"(p));
    return a;
}
__device__ __forceinline__ float blk_reduce_sum(float v, float* sm) {
    int lane = threadIdx.x & 31, w = threadIdx.x >> 5;
    #pragma unroll
    for (int o = 16; o; o >>= 1) v += __shfl_down_sync(0xffffffffu, v, o);
    if (!lane) sm[w] = v;
    __syncthreads();
    if (threadIdx.x < 32) {
        v = (threadIdx.x < 8) ? sm[threadIdx.x] : 0.f;
        #pragma unroll
        for (int o = 4; o; o >>= 1) v += __shfl_down_sync(0xffffffffu, v, o);
        if (!threadIdx.x) sm[0] = v;
    }
    __syncthreads();
    float r = sm[0];
    __syncthreads();
    return r;
}

__device__ __forceinline__ void mma_f16(float* c, const u32* a, const u32* b) {
    asm volatile(
        "mma.sync.aligned.m16n8k16.row.col.f32.f16.f16.f32 "
        "{%0,%1,%2,%3}, {%4,%5,%6,%7}, {%8,%9}, {%0,%1,%2,%3};"
        : "+f"(c[0]), "+f"(c[1]), "+f"(c[2]), "+f"(c[3])
        : "r"(a[0]), "r"(a[1]), "r"(a[2]), "r"(a[3]), "r"(b[0]), "r"(b[1]));
}

#define CP16(dst, src) \
    asm volatile("cp.async.cg.shared.global [%0], [%1], 16;" :: "r"(dst), "l"(src) : "memory")
#define CP_COMMIT() asm volatile("cp.async.commit_group;" ::: "memory")
#define CP_WAIT1()  asm volatile("cp.async.wait_group 1;" ::: "memory")
#define CP_WAIT2()  asm volatile("cp.async.wait_group 2;" ::: "memory")
#define LDMX4(r, addr) \
    asm volatile("ldmatrix.sync.aligned.m8n8.x4.shared.b16 {%0,%1,%2,%3}, [%4];" \
        : "=r"((r)[0]), "=r"((r)[1]), "=r"((r)[2]), "=r"((r)[3]) : "r"(addr))

// =====================================================================
// fp16-split tensor-core GEMM. C[z] = alpha*(A@B^T) + bias.
// NP=2: A split hi/lo, B single fp16. NP=3: both split (3 products).
// 512 threads, 16 warps 8(M)x2(N), BM=256, BN=128, 2-stage cp.async.
// =====================================================================
template<int NP, int BM, int BN, bool GELU_, bool WF32, bool WSPLIT, bool GATHER>
__global__ __launch_bounds__(512, 1)
void gemm_tc(const u16* __restrict__ Ah_, const u16* __restrict__ Al_,
             const u16* __restrict__ Bh_, const u16* __restrict__ Bl_,
             int K, long long As, long long Bs, long long Cs,
             const int* __restrict__ rowmap, const int* __restrict__ cntArr,
             const float* __restrict__ bias, long long biasStride, float alpha,
             float* __restrict__ Cf, u16* __restrict__ Ch, u16* __restrict__ Cl, int ldc)
{
    extern __shared__ __align__(16) u16 smem[];
    const int z = blockIdx.z;
    const int cnt = cntArr ? cntArr[z] : 0x40000000;
    const int m0 = blockIdx.y * BM;
    if (m0 >= cnt) return;
    const int n0 = blockIdx.x * BN;

    const u16* Ah = Ah_ + (size_t)z * As;
    const u16* Al = Al_ + (size_t)z * As;
    const u16* Bh = Bh_ + (size_t)z * Bs;
    const u16* Bl = (NP == 3) ? (Bl_ + (size_t)z * Bs) : nullptr;
    if (WF32)   Cf += (size_t)z * Cs;
    if (WSPLIT) { Ch += (size_t)z * Cs; Cl += (size_t)z * Cs; }
    const float* bptr = bias ? bias + (size_t)z * biasStride : nullptr;
    const int* rmap = GATHER ? (rowmap + (size_t)z * NTOK) : nullptr;

    constexpr int ASZ = BM * RS;
    constexpr int BSZ = BN * RS;
    constexpr int NBT = (NP == 3) ? 2 : 1;
    constexpr int STG = 2 * ASZ + NBT * BSZ;
    constexpr int WMR = BM / 8;
    constexpr int MI  = WMR / 16;
    constexpr int WN  = BN / 2;
    constexpr int NF  = WN / 8;
    constexpr int AIT = BM / 64;
    constexpr int NBI = BN / 64;

    const int tid = threadIdx.x;
    const int wid = tid >> 5, lane = tid & 31;
    const int wm = wid & 7, wn = wid >> 3;
    const u32 sb = smem_u32(smem);

    u32 aOff[AIT], aDst[AIT];
    #pragma unroll
    for (int it = 0; it < AIT; it++) {
        int idx = tid + it * 512;
        int row = idx >> 3, blk = idx & 7;
        int srow;
        if (GATHER) { int gm = m0 + row; if (gm >= cnt) gm = cnt - 1; srow = rmap[gm]; }
        else srow = m0 + row;
        aOff[it] = (u32)srow * (u32)K + blk * 8;
        aDst[it] = (u32)(row * RS + blk * 8) * 2;
    }
    u32 bOff[NBI], bDst[NBI];
    #pragma unroll
    for (int it = 0; it < NBI; it++) {
        int idx = tid + it * 512;
        int row = idx >> 3, blk = idx & 7;
        bOff[it] = (u32)(n0 + row) * (u32)K + blk * 8;
        bDst[it] = (u32)(2 * ASZ + row * RS + blk * 8) * 2;
    }

    auto load_chunk = [&](int c, int s) {
        const int k0 = c * KCH;
        const u32 base = sb + (u32)(s * STG) * 2;
        #pragma unroll
        for (int it = 0; it < AIT; it++) {
            CP16(base + aDst[it],           Ah + aOff[it] + k0);
            CP16(base + aDst[it] + ASZ * 2, Al + aOff[it] + k0);
        }
        #pragma unroll
        for (int it = 0; it < NBI; it++) {
            CP16(base + bDst[it], Bh + bOff[it] + k0);
            if (NP == 3) CP16(base + bDst[it] + BSZ * 2, Bl + bOff[it] + k0);
        }
    };

    const int aRowO = ((lane >> 3) & 1) * 8 + (lane & 7);
    const int aKO   = ((lane >> 4) & 1) * 8;
    const int bRowO = ((lane >> 4) & 1) * 8 + (lane & 7);
    const int bKO   = ((lane >> 3) & 1) * 8;

    float acc[MI][NF][4];
    #pragma unroll
    for (int i = 0; i < MI; i++)
        #pragma unroll
        for (int j = 0; j < NF; j++)
            #pragma unroll
            for (int q = 0; q < 4; q++) acc[i][j][q] = 0.f;

    const int nch = K / KCH;

    load_chunk(0, 0);
    CP_COMMIT();
    if (nch > 1) load_chunk(1, 1);
    CP_COMMIT();

    for (int c = 0; c < nch; c++) {
        CP_WAIT1();
        __syncthreads();

        const u32 stB = sb + (u32)((c & 1) * STG) * 2;
        #pragma unroll
        for (int ks = 0; ks < 4; ks++) {
            u32 ah[MI][4], al[MI][4];
            #pragma unroll
            for (int mi = 0; mi < MI; mi++) {
                u32 ad = stB + (u32)((wm * WMR + mi * 16 + aRowO) * RS + ks * 16 + aKO) * 2;
                LDMX4(ah[mi], ad);
                LDMX4(al[mi], ad + ASZ * 2);
            }
            #pragma unroll
            for (int j = 0; j < NF / 2; j++) {
                u32 bd = stB + (u32)(2 * ASZ + (wn * WN + j * 16 + bRowO) * RS + ks * 16 + bKO) * 2;
                u32 th[4];
                LDMX4(th, bd);
                u32 b0h[2] = { th[0], th[1] }, b1h[2] = { th[2], th[3] };
                #pragma unroll
                for (int mi = 0; mi < MI; mi++) {
                    mma_f16(acc[mi][2*j],   ah[mi], b0h);
                    mma_f16(acc[mi][2*j+1], ah[mi], b1h);
                }
                #pragma unroll
                for (int mi = 0; mi < MI; mi++) {
                    mma_f16(acc[mi][2*j],   al[mi], b0h);
                    mma_f16(acc[mi][2*j+1], al[mi], b1h);
                }
                if (NP == 3) {
                    u32 tl[4];
                    LDMX4(tl, bd + BSZ * 2);
                    u32 b0l[2] = { tl[0], tl[1] }, b1l[2] = { tl[2], tl[3] };
                    #pragma unroll
                    for (int mi = 0; mi < MI; mi++) {
                        mma_f16(acc[mi][2*j],   ah[mi], b0l);
                        mma_f16(acc[mi][2*j+1], ah[mi], b1l);
                    }
                }
            }
        }
        __syncthreads();
        if (c + 2 < nch) load_chunk(c + 2, c & 1);
        CP_COMMIT();
    }

    const int gid = lane >> 2, tg = lane & 3;
    #pragma unroll
    for (int mi = 0; mi < MI; mi++) {
        #pragma unroll
        for (int nf = 0; nf < NF; nf++) {
            int mA  = m0 + wm * WMR + mi * 16 + gid;
            int col = n0 + wn * WN + nf * 8 + tg * 2;
            #pragma unroll
            for (int half = 0; half < 2; half++) {
                int m = mA + half * 8;
                if (m < cnt) {
                    float v0 = acc[mi][nf][half * 2 + 0] * alpha;
                    float v1 = acc[mi][nf][half * 2 + 1] * alpha;
                    if (bptr) { v0 += bptr[col]; v1 += bptr[col + 1]; }
                    if (GELU_) { v0 = gelu_exact(v0); v1 = gelu_exact(v1); }
                    size_t o = (size_t)m * ldc + col;
                    if (WF32) { Cf[o] = v0; Cf[o + 1] = v1; }
                    if (WSPLIT) {
                        u16 h0, l0, h1, l1;
                        split2(v0, h0, l0); split2(v1, h1, l1);
                        Ch[o] = h0; Ch[o + 1] = h1;
                        Cl[o] = l0; Cl[o + 1] = l1;
                    }
                }
            }
        }
    }
}

// =====================================================================
// Flash attention, fp16 2-product. 2 CTAs/SM for latency hiding.
// =====================================================================
__global__ __launch_bounds__(256, 2)
void flash_attn()
{
    extern __shared__ __align__(16) u16 smem[];
    const int z  = blockIdx.y;
    const int q0 = blockIdx.x * 128;
    const int tid = threadIdx.x, wid = tid >> 5, lane = tid & 31;
    const u32 sb = smem_u32(smem);

    constexpr int QSZ = 128 * RS;
    constexpr int KSZ = 64 * RS;
    constexpr int STG = 2 * KSZ;          // Kh, Vh
    const u32 kvB = 2 * QSZ;

    #pragma unroll
    for (int j = 0; j < 4; j++) {
        int idx = tid + j * 256;
        int row = idx >> 3, blk = idx & 7;
        size_t src = ((size_t)(z * 1024 + q0 + row)) * 64 + blk * 8;
        u32 dst = sb + (u32)(row * RS + blk * 8) * 2;
        CP16(dst,           s_qt_h + src);
        CP16(dst + QSZ * 2, s_qt_l + src);
    }
    CP_COMMIT();

    auto load_kv = [&](int c, int s) {
        const int kv0 = c * 64;
        const u32 base = sb + (kvB + (u32)s * STG) * 2;
        #pragma unroll
        for (int j = 0; j < 2; j++) {
            int idx = tid + j * 256;
            int row = idx >> 3, blk = idx & 7;
            size_t ksrc = ((size_t)(z * 1024 + kv0 + row)) * 64 + blk * 8;
            size_t vsrc = ((size_t)(z * 64 + row)) * 1024 + kv0 + blk * 8;
            u32 d = (u32)(row * RS + blk * 8) * 2;
            CP16(base + d,           s_kt_h + ksrc);
            CP16(base + d + KSZ * 2, s_vt_h + vsrc);
        }
    };

    load_kv(0, 0); CP_COMMIT();
    load_kv(1, 1); CP_COMMIT();

    const int aRowO = ((lane >> 3) & 1) * 8 + (lane & 7);
    const int aKO   = ((lane >> 4) & 1) * 8;
    const int bRowO = ((lane >> 4) & 1) * 8 + (lane & 7);
    const int bKO   = ((lane >> 3) & 1) * 8;

    CP_WAIT2();
    __syncthreads();
    u32 qhf[4][4], qlf[4][4];
    #pragma unroll
    for (int ks = 0; ks < 4; ks++) {
        u32 ad = sb + (u32)((wid * 16 + aRowO) * RS + ks * 16 + aKO) * 2;
        LDMX4(qhf[ks], ad);
        LDMX4(qlf[ks], ad + QSZ * 2);
    }

    float of[8][4];
    #pragma unroll
    for (int n = 0; n < 8; n++)
        #pragma unroll
        for (int q = 0; q < 4; q++) of[n][q] = 0.f;
    float m0 = -1e30f, m1 = -1e30f, l0 = 0.f, l1 = 0.f;

    for (int c = 0; c < 16; c++) {
        CP_WAIT1();
        __syncthreads();
        const u32 stB = sb + (kvB + (u32)((c & 1) * STG)) * 2;

        float sacc[8][4];
        #pragma unroll
        for (int n = 0; n < 8; n++)
            #pragma unroll
            for (int q = 0; q < 4; q++) sacc[n][q] = 0.f;

        #pragma unroll
        for (int ks = 0; ks < 4; ks++) {
            u32 b0h[4][2], b1h[4][2];
            #pragma unroll
            for (int j = 0; j < 4; j++) {
                u32 bd = stB + (u32)((j * 16 + bRowO) * RS + ks * 16 + bKO) * 2;
                u32 th[4];
                LDMX4(th, bd);
                b0h[j][0] = th[0]; b0h[j][1] = th[1];
                b1h[j][0] = th[2]; b1h[j][1] = th[3];
            }
            #pragma unroll
            for (int j = 0; j < 4; j++) {
                mma_f16(sacc[2*j],   qhf[ks], b0h[j]);
                mma_f16(sacc[2*j+1], qhf[ks], b1h[j]);
            }
            #pragma unroll
            for (int j = 0; j < 4; j++) {
                mma_f16(sacc[2*j],   qlf[ks], b0h[j]);
                mma_f16(sacc[2*j+1], qlf[ks], b1h[j]);
            }
        }

        float mx0 = -1e30f, mx1 = -1e30f;
        #pragma unroll
        for (int n = 0; n < 8; n++) {
            #pragma unroll
            for (int q = 0; q < 4; q++) sacc[n][q] *= 0.125f;
            mx0 = fmaxf(mx0, fmaxf(sacc[n][0], sacc[n][1]));
            mx1 = fmaxf(mx1, fmaxf(sacc[n][2], sacc[n][3]));
        }
        mx0 = fmaxf(mx0, __shfl_xor_sync(0xffffffffu, mx0, 1));
        mx0 = fmaxf(mx0, __shfl_xor_sync(0xffffffffu, mx0, 2));
        mx1 = fmaxf(mx1, __shfl_xor_sync(0xffffffffu, mx1, 1));
        mx1 = fmaxf(mx1, __shfl_xor_sync(0xffffffffu, mx1, 2));
        float mn0 = fmaxf(m0, mx0), mn1 = fmaxf(m1, mx1);
        float sc0 = __expf(m0 - mn0), sc1 = __expf(m1 - mn1);
        m0 = mn0; m1 = mn1;
        float ps0 = 0.f, ps1 = 0.f;
        #pragma unroll
        for (int n = 0; n < 8; n++) {
            sacc[n][0] = __expf(sacc[n][0] - mn0);
            sacc[n][1] = __expf(sacc[n][1] - mn0);
            sacc[n][2] = __expf(sacc[n][2] - mn1);
            sacc[n][3] = __expf(sacc[n][3] - mn1);
            ps0 += sacc[n][0] + sacc[n][1];
            ps1 += sacc[n][2] + sacc[n][3];
        }
        ps0 += __shfl_xor_sync(0xffffffffu, ps0, 1);
        ps0 += __shfl_xor_sync(0xffffffffu, ps0, 2);
        ps1 += __shfl_xor_sync(0xffffffffu, ps1, 1);
        ps1 += __shfl_xor_sync(0xffffffffu, ps1, 2);
        l0 = l0 * sc0 + ps0;
        l1 = l1 * sc1 + ps1;
        #pragma unroll
        for (int n = 0; n < 8; n++) {
            of[n][0] *= sc0; of[n][1] *= sc0;
            of[n][2] *= sc1; of[n][3] *= sc1;
        }

        #pragma unroll
        for (int kk = 0; kk < 4; kk++) {
            u32 ph[4], pl[4];
            split_pack2(sacc[2*kk][0],   sacc[2*kk][1],   ph[0], pl[0]);
            split_pack2(sacc[2*kk][2],   sacc[2*kk][3],   ph[1], pl[1]);
            split_pack2(sacc[2*kk+1][0], sacc[2*kk+1][1], ph[2], pl[2]);
            split_pack2(sacc[2*kk+1][2], sacc[2*kk+1][3], ph[3], pl[3]);
            u32 b0h[4][2], b1h[4][2];
            #pragma unroll
            for (int j2 = 0; j2 < 4; j2++) {
                u32 vd = stB + (u32)(KSZ) * 2
                       + (u32)((j2 * 16 + bRowO) * RS + kk * 16 + bKO) * 2;
                u32 th[4];
                LDMX4(th, vd);
                b0h[j2][0] = th[0]; b0h[j2][1] = th[1];
                b1h[j2][0] = th[2]; b1h[j2][1] = th[3];
            }
            #pragma unroll
            for (int j2 = 0; j2 < 4; j2++) {
                mma_f16(of[2*j2],   ph, b0h[j2]);
                mma_f16(of[2*j2+1], ph, b1h[j2]);
            }
            #pragma unroll
            for (int j2 = 0; j2 < 4; j2++) {
                mma_f16(of[2*j2],   pl, b0h[j2]);
                mma_f16(of[2*j2+1], pl, b1h[j2]);
            }
        }
        __syncthreads();
        if (c + 2 < 16) load_kv(c + 2, c & 1);
        CP_COMMIT();
    }

    const int gid = lane >> 2, tg = lane & 3;
    float inv0 = 1.f / l0, inv1 = 1.f / l1;
    int qr = q0 + wid * 16 + gid;
    #pragma unroll
    for (int n = 0; n < 8; n++) {
        int dh = n * 8 + tg * 2;
        float2 v0 = make_float2(of[n][0] * inv0, of[n][1] * inv0);
        float2 v1 = make_float2(of[n][2] * inv1, of[n][3] * inv1);
        *(float2*)&g_ot[((size_t)(z * 1024 + qr)) * 64 + dh]     = v0;
        *(float2*)&g_ot[((size_t)(z * 1024 + qr + 8)) * 64 + dh] = v1;
    }
}

// ---------------- fused conversion ----------------
struct SplitSegs {
    const float4* s[4];
    uint2* h[4];
    uint2* l[4];
    int end4[4];
};
__global__ void split_all(SplitSegs g) {
    const int total = g.end4[3];
    for (int i = blockIdx.x * blockDim.x + threadIdx.x; i < total; i += gridDim.x * blockDim.x) {
        int k = 0;
        #pragma unroll
        for (int t = 0; t < 3; t++) k += (i >= g.end4[t]) ? 1 : 0;
        int j = i - (k ? g.end4[k - 1] : 0);
        float4 v = g.s[k][j];
        u16 hh[4], ll[4];
        split2(v.x, hh[0], ll[0]); split2(v.y, hh[1], ll[1]);
        split2(v.z, hh[2], ll[2]); split2(v.w, hh[3], ll[3]);
        g.h[k][j] = *(uint2*)hh;
        g.l[k][j] = *(uint2*)ll;
    }
}

__global__ void transpose_split(const float* __restrict__ s, u16* __restrict__ oh, u16* __restrict__ ol,
                                int R, int C) {
    __shared__ float t[32][33];
    size_t zo = (size_t)blockIdx.z * R * C;
    const float* src = s + zo;
    int c0 = blockIdx.x * 32, r0 = blockIdx.y * 32;
    int tx = threadIdx.x & 31, ty = threadIdx.x >> 5;
    #pragma unroll
    for (int dy = 0; dy < 32; dy += 8)
        t[ty + dy][tx] = src[(size_t)(r0 + ty + dy) * C + c0 + tx];
    __syncthreads();
    #pragma unroll
    for (int dy = 0; dy < 32; dy += 8) {
        float v = t[tx][ty + dy];
        size_t o = zo + (size_t)(c0 + ty + dy) * R + r0 + tx;
        u16 hh, ll; split2(v, hh, ll);
        oh[o] = hh;
        if (ol) ol[o] = ll;
    }
}

// bc[i] = sum_m W[i,m]*bin[m] + badd[i]
__global__ void bias_comb(const float* __restrict__ W, const float* __restrict__ bin,
                          const float* __restrict__ badd, float* __restrict__ bc) {
    __shared__ float sm[32];
    int i = blockIdx.x, t = threadIdx.x;
    float s = 0.f;
    for (int m = t; m < DIM; m += 256) s += W[(size_t)i * DIM + m] * bin[m];
    s = blk_reduce_sum(s, sm);
    if (t == 0) bc[i] = s + badd[i];
}

__global__ void headsplit_qk(const float* __restrict__ in, u16* __restrict__ oh, u16* __restrict__ ol) {
    for (int i = blockIdx.x * blockDim.x + threadIdx.x; i < NTOK * DIM; i += gridDim.x * blockDim.x) {
        int d = i & 63, s = (i >> 6) & 1023, h = (i >> 16) & 15, b = i >> 20;
        float v = in[(size_t)((b << 10) + s) * DIM + (h << 6) + d];
        u16 hh, ll; split2(v, hh, ll);
        oh[i] = hh;
        if (ol) ol[i] = ll;
    }
}

__global__ void headsplit_vT(const float* __restrict__ in, u16* __restrict__ oh) {
    __shared__ float t[32][33];
    int z = blockIdx.z;
    int b = z >> 4, h = z & 15;
    int s0 = blockIdx.x * 32, d0 = blockIdx.y * 32;
    int tx = threadIdx.x & 31, ty = threadIdx.x >> 5;
    #pragma unroll
    for (int dy = 0; dy < 32; dy += 8)
        t[ty + dy][tx] = in[(size_t)((b << 10) + s0 + ty + dy) * DIM + h * 64 + d0 + tx];
    __syncthreads();
    #pragma unroll
    for (int dy = 0; dy < 32; dy += 8) {
        float v = t[tx][ty + dy];
        size_t o = (size_t)(z * 64 + d0 + ty + dy) * 1024 + s0 + tx;
        oh[o] = f2h(v);
    }
}

__global__ void head_merge_split(const float* __restrict__ in, u16* __restrict__ oh, u16* __restrict__ ol) {
    for (int i = blockIdx.x * blockDim.x + threadIdx.x; i < NTOK * DIM; i += gridDim.x * blockDim.x) {
        int col = i & 1023, h = col >> 6, d = col & 63;
        int s = (i >> 10) & 1023, b = i >> 20;
        float v = in[(size_t)(((b << 4) + h) * 1024 + s) * 64 + d];
        u16 hh, ll; split2(v, hh, ll);
        oh[i] = hh; ol[i] = ll;
    }
}

__global__ void ln_res_split(const float* __restrict__ a, const float* __restrict__ res,
                             const float* __restrict__ g, const float* __restrict__ b,
                             float* __restrict__ of, u16* __restrict__ oh, u16* __restrict__ ol) {
    __shared__ float sm[32];
    const size_t base = (size_t)blockIdx.x * DIM;
    int t = threadIdx.x;
    float v[4];
    float s = 0.f;
    #pragma unroll
    for (int j = 0; j < 4; j++) {
        int c = t + j * 256;
        v[j] = a[base + c] + res[base + c];
        s += v[j];
    }
    s = blk_reduce_sum(s, sm);
    float mean = s * (1.0f / DIM);
    float s2 = 0.f;
    #pragma unroll
    for (int j = 0; j < 4; j++) { float d = v[j] - mean; s2 += d * d; }
    s2 = blk_reduce_sum(s2, sm);
    float rs = rsqrtf(s2 * (1.0f / DIM) + 1e-5f);
    #pragma unroll
    for (int j = 0; j < 4; j++) {
        int c = t + j * 256;
        float o = (v[j] - mean) * rs * g[c] + b[c];
        of[base + c] = o;
        u16 hh, ll; split2(o, hh, ll);
        oh[base + c] = hh; ol[base + c] = ll;
    }
}

__global__ void combine_ln(const float* __restrict__ g, const float* __restrict__ b,
                           float* __restrict__ out) {
    __shared__ float sm[32];
    const int tok = blockIdx.x;
    const size_t base = (size_t)tok * DIM;
    int t = threadIdx.x;
    float v[4];
    #pragma unroll
    for (int j = 0; j < 4; j++) v[j] = g_x[base + t + j * 256];
    const int nl = g_tcnt[tok];
    for (int l = 0; l < nl; l++) {
        int   e    = g_te[tok * 3 + l];
        int   slot = g_tslot[tok * 3 + l];
        float gt   = g_tgate[tok * 3 + l];
        const float* row = g_e2 + ((size_t)e * NTOK + slot) * DIM;
        #pragma unroll
        for (int j = 0; j < 4; j++) v[j] += gt * row[t + j * 256];
    }
    float s = 0.f;
    #pragma unroll
    for (int j = 0; j < 4; j++) s += v[j];
    s = blk_reduce_sum(s, sm);
    float mean = s * (1.0f / DIM);
    float s2 = 0.f;
    #pragma unroll
    for (int j = 0; j < 4; j++) { float d = v[j] - mean; s2 += d * d; }
    s2 = blk_reduce_sum(s2, sm);
    float rs = rsqrtf(s2 * (1.0f / DIM) + 1e-5f);
    #pragma unroll
    for (int j = 0; j < 4; j++) {
        int c = t + j * 256;
        out[base + c] = (v[j] - mean) * rs * g[c] + b[c];
    }
}

__global__ void gating(const float* __restrict__ Wg) {
    __shared__ float logits[NEXP];
    const int tok = blockIdx.x;
    const float* xr = g_x + (size_t)tok * DIM;
    int w = threadIdx.x >> 5, lane = threadIdx.x & 31;
    float s = 0.f;
    for (int i = lane; i < DIM; i += 32) s += xr[i] * Wg[i * NEXP + w];
    #pragma unroll
    for (int o = 16; o; o >>= 1) s += __shfl_down_sync(0xffffffffu, s, o);
    if (!lane) logits[w] = s;
    __syncthreads();
    if (threadIdx.x == 0) {
        float p[NEXP];
        float mx = -1e30f;
        for (int e = 0; e < NEXP; e++) mx = fmaxf(mx, logits[e]);
        float sum = 0.f;
        for (int e = 0; e < NEXP; e++) { p[e] = __expf(logits[e] - mx); sum += p[e]; }
        float inv = 1.f / sum;
        for (int e = 0; e < NEXP; e++) { p[e] *= inv; g_probs[tok * NEXP + e] = p[e]; }
        int i0 = 0;
        for (int e = 1; e < NEXP; e++) if (p[e] > p[i0]) i0 = e;
        int i1 = -1;
        for (int e = 0; e < NEXP; e++) if (e != i0 && (i1 < 0 || p[e] > p[i1])) i1 = e;
        int i2 = -1;
        for (int e = 0; e < NEXP; e++) if (e != i0 && e != i1 && (i2 < 0 || p[e] > p[i2])) i2 = e;
        int   ids[3] = { i0, i1, i2 };
        float gts[3] = { p[i0],
                         (p[i1] >= THRESH) ? p[i1] : 0.f,
                         (p[i2] >= THRESH) ? p[i2] : 0.f };
        int nl = 0;
        #pragma unroll
        for (int j = 0; j < 3; j++) {
            if (gts[j] > 0.f) {
                int slot = atomicAdd(&g_cnt[ids[j]], 1);
                g_tok  [ids[j] * NTOK + slot] = tok;
                g_te   [tok * 3 + nl] = ids[j];
                g_tslot[tok * 3 + nl] = slot;
                g_tgate[tok * 3 + nl] = gts[j];
                nl++;
            }
        }
        g_tcnt[tok] = nl;
    }
}

__global__ void zero_small() {
    int t = threadIdx.x;
    if (t < NEXP) g_cnt[t] = 0;
}
__global__ void aux_kernel(float* __restrict__ out, int out_size) {
    if (out_size <= OUT_MAIN) return;
    __shared__ float sm[32];
    int t = threadIdx.x;
    float total = 0.f;
    for (int e = 0; e < NEXP; e++) {
        float s = 0.f;
        for (int tok = t; tok < NTOK; tok += 256) s += g_probs[tok * NEXP + e];
        s = blk_reduce_sum(s, sm);
        if (t == 0) total += ((float)g_cnt[e] / (float)NTOK) * (s / (float)NTOK);
    }
    if (t == 0) out[OUT_MAIN] = COEF * (float)NEXP * total;
}

// ---------------- host launcher ----------------
#define GETSYM(var, sym) do { cudaGetSymbolAddress((void**)&(var), sym); } while (0)

extern "C" void kernel_launch(void* const* d_in, const int* in_sizes, int n_in,
                              void* d_out, int out_size)
{
    (void)in_sizes; (void)n_in;
    const float* query  = (const float*)d_in[0];
    const float* keyval = (const float*)d_in[1];
    const float* Wq = (const float*)d_in[2];  const float* bq = (const float*)d_in[3];
    const float* Wk = (const float*)d_in[4];  const float* bk = (const float*)d_in[5];
    const float* Wv = (const float*)d_in[6];  const float* bv = (const float*)d_in[7];
    const float* W_in  = (const float*)d_in[8];  const float* b_in  = (const float*)d_in[9];
    const float* W_out = (const float*)d_in[10]; const float* b_out = (const float*)d_in[11];
    const float* Wa = (const float*)d_in[12]; const float* ba = (const float*)d_in[13];
    const float* ln1g = (const float*)d_in[14]; const float* ln1b = (const float*)d_in[15];
    const float* Wg = (const float*)d_in[16];
    const float* ew1 = (const float*)d_in[17]; const float* eb1 = (const float*)d_in[18];
    const float* ew2 = (const float*)d_in[19]; const float* eb2 = (const float*)d_in[20];
    const float* ln2g = (const float*)d_in[21]; const float* ln2b = (const float*)d_in[22];
    float* out = (float*)d_out;

    float *qh, *kh, *vh, *ot, *a, *x, *e2p, *bc;
    GETSYM(qh, g_qh); GETSYM(kh, g_kh); GETSYM(vh, g_vh);
    GETSYM(ot, g_ot); GETSYM(a, g_a); GETSYM(x, g_x);
    GETSYM(e2p, g_e2); GETSYM(bc, g_bc);
    u16 *qyh,*qyl,*kvh,*kvl,*qth,*qtl,*kth,*vth,*oh,*ol,*xh,*xl,*hhh,*hhl;
    u16 *wAh,*wAl,*wTh,*wTl,*wch,*wcl,*e1h,*e2h;
    GETSYM(qyh, s_query_h); GETSYM(qyl, s_query_l);
    GETSYM(kvh, s_kv_h);    GETSYM(kvl, s_kv_l);
    GETSYM(qth, s_qt_h); GETSYM(qtl, s_qt_l);
    GETSYM(kth, s_kt_h);
    GETSYM(vth, s_vt_h);
    GETSYM(oh,  s_o_h);  GETSYM(ol,  s_o_l);
    GETSYM(xh,  s_x_h);  GETSYM(xl,  s_x_l);
    GETSYM(hhh, s_hh);   GETSYM(hhl, s_hl);
    GETSYM(wAh, s_wA_h); GETSYM(wAl, s_wA_l);
    GETSYM(wTh, s_wT_h); GETSYM(wTl, s_wT_l);
    GETSYM(wch, s_wc_h); GETSYM(wcl, s_wc_l);
    GETSYM(e1h, s_e1_h); GETSYM(e2h, s_e2_h);
    int *tokp; GETSYM(tokp, g_tok);
    int *cntp; GETSYM(cntp, g_cnt);

    const int SM_NP2 = 2 * (2 * 256 + 128) * RS * 2;        // 184320 B
    const int SM_NP3 = 2 * (2 * 256 + 2 * 128) * RS * 2;    // 221184 B
    const int SFLASH = (2 * 128 + 2 * 2 * 64) * RS * 2;     // 73728 B
    cudaFuncSetAttribute((const void*)gemm_tc<2,256,128,false,true ,false,false>, cudaFuncAttributeMaxDynamicSharedMemorySize, SM_NP2);
    cudaFuncSetAttribute((const void*)gemm_tc<2,256,128,true ,false,true ,true >, cudaFuncAttributeMaxDynamicSharedMemorySize, SM_NP2);
    cudaFuncSetAttribute((const void*)gemm_tc<3,256,128,false,false,true ,false>, cudaFuncAttributeMaxDynamicSharedMemorySize, SM_NP3);
    cudaFuncSetAttribute((const void*)flash_attn, cudaFuncAttributeMaxDynamicSharedMemorySize, SFLASH);

    const dim3 T512(512);
    const dim3 T256(256);
    const dim3 GLIN(DIM/128, NTOK/256, 1);

    // ---- fused fp16 split of inputs + A-side weights (Win x3 | Wa packed) ----
    SplitSegs sg;
    sg.s[0] = (const float4*)query;  sg.h[0] = (uint2*)qyh;  sg.l[0] = (uint2*)qyl;
    sg.s[1] = (const float4*)keyval; sg.h[1] = (uint2*)kvh;  sg.l[1] = (uint2*)kvl;
    sg.s[2] = (const float4*)W_in;   sg.h[2] = (uint2*)wAh;  sg.l[2] = (uint2*)wAl;
    sg.s[3] = (const float4*)Wa;     sg.h[3] = (uint2*)(wAh + 3*DIM*DIM);
    sg.l[3] = (uint2*)(wAl + 3*DIM*DIM);
    sg.end4[0] = NTOK*DIM/4;
    sg.end4[1] = sg.end4[0] + NTOK*DIM/4;
    sg.end4[2] = sg.end4[1] + 3*DIM*DIM/4;
    sg.end4[3] = sg.end4[2] + DIM*DIM/4;
    split_all<<<2048, 256>>>(sg);

    // ---- transposed splits of B-side weights into packed array ----
    transpose_split<<<dim3(DIM/32, DIM/32, 1), T256>>>(Wq,    wTh,             wTl,             DIM, DIM);
    transpose_split<<<dim3(DIM/32, DIM/32, 1), T256>>>(Wk,    wTh + DIM*DIM,   wTl + DIM*DIM,   DIM, DIM);
    transpose_split<<<dim3(DIM/32, DIM/32, 1), T256>>>(Wv,    wTh + 2*DIM*DIM, wTl + 2*DIM*DIM, DIM, DIM);
    transpose_split<<<dim3(DIM/32, DIM/32, 1), T256>>>(W_out, wTh + 3*DIM*DIM, wTl + 3*DIM*DIM, DIM, DIM);

    // ---- BATCHED weight composition (z=0..3): Wc[z] = WA[z] @ WT[z]^T ----
    gemm_tc<3,256,128,false,false,true,false><<<dim3(DIM/128, DIM/256, 4), T512, SM_NP3>>>(
        wAh, wAl, wTh, wTl, DIM,
        (long long)DIM*DIM, (long long)DIM*DIM, (long long)DIM*DIM,
        nullptr, nullptr, nullptr, 0, 1.f, nullptr, wch, wcl, DIM);

    // ---- combined biases (fp32 exact) ----
    bias_comb<<<DIM, T256>>>(W_in,              bq,    b_in,           bc);
    bias_comb<<<DIM, T256>>>(W_in + DIM*DIM,    bk,    b_in + DIM,     bc + DIM);
    bias_comb<<<DIM, T256>>>(W_in + 2*DIM*DIM,  bv,    b_in + 2*DIM,   bc + 2*DIM);
    bias_comb<<<DIM, T256>>>(Wa,                b_out, ba,             bc + 3*DIM);

    // ---- token linears (NP=2) ----
    gemm_tc<2,256,128,false,true,false,false><<<GLIN, T512, SM_NP2>>>(
        qyh, qyl, wch,             nullptr, DIM, 0, 0, 0, nullptr, nullptr, bc,         0, 1.f, qh, nullptr, nullptr, DIM);
    gemm_tc<2,256,128,false,true,false,false><<<GLIN, T512, SM_NP2>>>(
        kvh, kvl, wch + DIM*DIM,   nullptr, DIM, 0, 0, 0, nullptr, nullptr, bc + DIM,   0, 1.f, kh, nullptr, nullptr, DIM);
    gemm_tc<2,256,128,false,true,false,false><<<GLIN, T512, SM_NP2>>>(
        kvh, kvl, wch + 2*DIM*DIM, nullptr, DIM, 0, 0, 0, nullptr, nullptr, bc + 2*DIM, 0, 1.f, vh, nullptr, nullptr, DIM);

    // ---- head reshape ----
    headsplit_qk<<<512, 256>>>(qh, qth, qtl);
    headsplit_qk<<<512, 256>>>(kh, kth, nullptr);
    headsplit_vT<<<dim3(SQL/32, 2, BH), T256>>>(vh, vth);

    // ---- fused flash attention -> g_ot ----
    flash_attn<<<dim3(SQL/128, BH), T256, SFLASH>>>();

    head_merge_split<<<512, 256>>>(ot, oh, ol);

    // ---- combined out-projection + adapter (NP=2) ----
    gemm_tc<2,256,128,false,true,false,false><<<GLIN, T512, SM_NP2>>>(
        oh, ol, wch + 3*DIM*DIM, nullptr, DIM, 0, 0, 0, nullptr, nullptr, bc + 3*DIM, 0, 1.f, a, nullptr, nullptr, DIM);

    // ---- LN1 (+residual) -> x fp32 + split ----
    ln_res_split<<<NTOK, T256>>>(a, query, ln1g, ln1b, x, xh, xl);

    // ---- gating ----
    zero_small<<<1, 32>>>();
    gating<<<NTOK, T256>>>(Wg);

    // ---- MoE expert weights (hi only) + FFNs (NP=2) ----
    transpose_split<<<dim3(HDIM/32, DIM/32, NEXP), T256>>>(ew1, e1h, nullptr, DIM, HDIM);
    transpose_split<<<dim3(DIM/32, HDIM/32, NEXP), T256>>>(ew2, e2h, nullptr, HDIM, DIM);
    gemm_tc<2,256,128,true,false,true,true><<<dim3(HDIM/128, NTOK/256, NEXP), T512, SM_NP2>>>(
        xh, xl, e1h, nullptr, DIM,
        0, (long long)HDIM*DIM, (long long)NTOK*HDIM,
        tokp, cntp, eb1, HDIM, 1.f, nullptr, hhh, hhl, HDIM);
    gemm_tc<2,256,128,false,true,false,false><<<dim3(DIM/128, NTOK/256, NEXP), T512, SM_NP2>>>(
        hhh, hhl, e2h, nullptr, HDIM,
        (long long)NTOK*HDIM, (long long)DIM*HDIM, (long long)NTOK*DIM,
        nullptr, cntp, eb2, DIM, 1.f, e2p, nullptr, nullptr, DIM);

    // ---- fused combine + final LN -> output, then aux scalar ----
    combine_ln<<<NTOK, T256>>>(ln2g, ln2b, out);
    aux_kernel<<<1, 256>>>(out, out_size);
}

// round 16
// speedup vs baseline: 1.9707x; 1.3943x over previous
#include <cuda_runtime.h>
#include <cuda_fp16.h>
#include <math.h>
#include <stddef.h>
#include <stdint.h>

// ---------------- problem constants ----------------
#define BATCH 4
#define SQL   1024
#define SKV   1024
#define DIM   1024
#define NH    16
#define DH    64
#define NEXP  8
#define HDIM  4096
#define NTOK  (BATCH*SQL)       // 4096
#define BH    (BATCH*NH)        // 64
#define OUT_MAIN (NTOK*DIM)
#define THRESH 0.05f
#define COEF   0.01f
#define KCH   64                // K chunk
#define RS    72                // smem row stride in u16 (64 data + 8 pad)

typedef unsigned short u16;
typedef unsigned int   u32;

// ---------------- static device scratch (fp32) ----------------
__device__ float g_qh[NTOK*DIM];
__device__ float g_kh[NTOK*DIM];
__device__ float g_vh[NTOK*DIM];
__device__ float g_ot[NTOK*DIM];
__device__ float g_a [NTOK*DIM];
__device__ float g_x [NTOK*DIM];
__device__ float g_e2[(size_t)NEXP*NTOK*DIM];   // 128 MB
__device__ int   g_cnt[NEXP];
__device__ int   g_tok[NEXP*NTOK];
__device__ float g_probs[NTOK*NEXP];
__device__ int   g_tcnt[NTOK];
__device__ int   g_te  [NTOK*3];
__device__ int   g_tslot[NTOK*3];
__device__ float g_tgate[NTOK*3];
__device__ float g_bc[4*DIM];          // combined biases: q,k,v,oa

// ---------------- fp16 hi/lo split buffers ----------------
__device__ u16 s_query_h[NTOK*DIM], s_query_l[NTOK*DIM];
__device__ u16 s_kv_h[NTOK*DIM],    s_kv_l[NTOK*DIM];
__device__ u16 s_qt_h[NTOK*DIM],    s_qt_l[NTOK*DIM];    // [bh][sq][dh]
__device__ u16 s_kt_h[NTOK*DIM];                          // [bh][skv][dh]
__device__ u16 s_vt_h[NTOK*DIM];                          // [bh][dh][skv]
__device__ u16 s_o_h[NTOK*DIM],     s_o_l[NTOK*DIM];
__device__ u16 s_x_h[NTOK*DIM];
__device__ u16 s_hh [(size_t)NEXP*NTOK*HDIM];             // expert hidden (fp16)
// weights: packed 4x DIM^2 arrays for batched composition
__device__ u16 s_wA_h[4*DIM*DIM], s_wA_l[4*DIM*DIM];      // [Win q,k,v | Wa]
__device__ u16 s_wT_h[4*DIM*DIM], s_wT_l[4*DIM*DIM];      // [WqT,WkT,WvT,WoT]
__device__ u16 s_wc_h[4*DIM*DIM], s_wc_l[4*DIM*DIM];      // composed
__device__ u16 s_e1_h[(size_t)NEXP*HDIM*DIM];   // [e][n=HDIM][k=DIM]
__device__ u16 s_e2_h[(size_t)NEXP*DIM*HDIM];   // [e][n=DIM][k=HDIM]

// ---------------- helpers ----------------
__device__ __forceinline__ u16 f2h(float v) { __half h = __float2half_rn(v); return *(u16*)&h; }
__device__ __forceinline__ float h2f(u16 u) { __half h; *(u16*)&h = u; return __half2float(h); }
__device__ __forceinline__ void split2(float v, u16& h, u16& l) {
    u16 hu = f2h(v); h = hu; l = f2h(v - h2f(hu));
}
__device__ __forceinline__ void split_pack2(float v0, float v1, u32& h, u32& l) {
    u16 h0, l0, h1, l1;
    split2(v0, h0, l0); split2(v1, h1, l1);
    h = (u32)h0 | ((u32)h1 << 16);
    l = (u32)l0 | ((u32)l1 << 16);
}
__device__ __forceinline__ float gelu_exact(float v) {
    return 0.5f * v * (1.0f + erff(v * 0.70710678118654752f));
}
__device__ __forceinline__ u32 smem_u32(const void* p) {
    u32 a;
    asm("{ .reg .u64 t; cvta.to.shared.u64 t, %1; cvt.u32.u64 %0, t; }" : "=r"(a) : "l"(p));
    return a;
}
__device__ __forceinline__ float blk_reduce_sum(float v, float* sm) {
    int lane = threadIdx.x & 31, w = threadIdx.x >> 5;
    #pragma unroll
    for (int o = 16; o; o >>= 1) v += __shfl_down_sync(0xffffffffu, v, o);
    if (!lane) sm[w] = v;
    __syncthreads();
    if (threadIdx.x < 32) {
        v = (threadIdx.x < 8) ? sm[threadIdx.x] : 0.f;
        #pragma unroll
        for (int o = 4; o; o >>= 1) v += __shfl_down_sync(0xffffffffu, v, o);
        if (!threadIdx.x) sm[0] = v;
    }
    __syncthreads();
    float r = sm[0];
    __syncthreads();
    return r;
}

__device__ __forceinline__ void mma_f16(float* c, const u32* a, const u32* b) {
    asm volatile(
        "mma.sync.aligned.m16n8k16.row.col.f32.f16.f16.f32 "
        "{%0,%1,%2,%3}, {%4,%5,%6,%7}, {%8,%9}, {%0,%1,%2,%3};"
        : "+f"(c[0]), "+f"(c[1]), "+f"(c[2]), "+f"(c[3])
        : "r"(a[0]), "r"(a[1]), "r"(a[2]), "r"(a[3]), "r"(b[0]), "r"(b[1]));
}

#define CP16(dst, src) \
    asm volatile("cp.async.cg.shared.global [%0], [%1], 16;" :: "r"(dst), "l"(src) : "memory")
#define CP_COMMIT() asm volatile("cp.async.commit_group;" ::: "memory")
#define CP_WAIT1()  asm volatile("cp.async.wait_group 1;" ::: "memory")
#define CP_WAIT2()  asm volatile("cp.async.wait_group 2;" ::: "memory")
#define LDMX4(r, addr) \
    asm volatile("ldmatrix.sync.aligned.m8n8.x4.shared.b16 {%0,%1,%2,%3}, [%4];" \
        : "=r"((r)[0]), "=r"((r)[1]), "=r"((r)[2]), "=r"((r)[3]) : "r"(addr))

// =====================================================================
// fp16-split tensor-core GEMM. C[z] = alpha*(A@B^T) + bias.
// NP=1: plain fp16 x fp16 (1 product). NP=2: A split hi/lo (2 products).
// NP=3: both split (3 products). 512 threads, 16 warps 8(M)x2(N),
// BM=256, BN=128, 2-stage cp.async.
// =====================================================================
template<int NP, int BM, int BN, bool GELU_, bool WF32, bool WSPLIT, bool GATHER>
__global__ __launch_bounds__(512, 1)
void gemm_tc(const u16* __restrict__ Ah_, const u16* __restrict__ Al_,
             const u16* __restrict__ Bh_, const u16* __restrict__ Bl_,
             int K, long long As, long long Bs, long long Cs,
             const int* __restrict__ rowmap, const int* __restrict__ cntArr,
             const float* __restrict__ bias, long long biasStride, float alpha,
             float* __restrict__ Cf, u16* __restrict__ Ch, u16* __restrict__ Cl, int ldc)
{
    extern __shared__ __align__(16) u16 smem[];
    const int z = blockIdx.z;
    const int cnt = cntArr ? cntArr[z] : 0x40000000;
    const int m0 = blockIdx.y * BM;
    if (m0 >= cnt) return;
    const int n0 = blockIdx.x * BN;

    const u16* Ah = Ah_ + (size_t)z * As;
    const u16* Al = (NP >= 2) ? (Al_ + (size_t)z * As) : nullptr;
    const u16* Bh = Bh_ + (size_t)z * Bs;
    const u16* Bl = (NP == 3) ? (Bl_ + (size_t)z * Bs) : nullptr;
    if (WF32)   Cf += (size_t)z * Cs;
    if (WSPLIT) { Ch += (size_t)z * Cs; if (Cl) Cl += (size_t)z * Cs; }
    const float* bptr = bias ? bias + (size_t)z * biasStride : nullptr;
    const int* rmap = GATHER ? (rowmap + (size_t)z * NTOK) : nullptr;

    constexpr int ASZ = BM * RS;
    constexpr int BSZ = BN * RS;
    constexpr int NAT = (NP >= 2) ? 2 : 1;
    constexpr int NBT = (NP == 3) ? 2 : 1;
    constexpr int STG = NAT * ASZ + NBT * BSZ;
    constexpr int WMR = BM / 8;
    constexpr int MI  = WMR / 16;
    constexpr int WN  = BN / 2;
    constexpr int NF  = WN / 8;
    constexpr int AIT = BM / 64;
    constexpr int NBI = BN / 64;

    const int tid = threadIdx.x;
    const int wid = tid >> 5, lane = tid & 31;
    const int wm = wid & 7, wn = wid >> 3;
    const u32 sb = smem_u32(smem);

    u32 aOff[AIT], aDst[AIT];
    #pragma unroll
    for (int it = 0; it < AIT; it++) {
        int idx = tid + it * 512;
        int row = idx >> 3, blk = idx & 7;
        int srow;
        if (GATHER) { int gm = m0 + row; if (gm >= cnt) gm = cnt - 1; srow = rmap[gm]; }
        else srow = m0 + row;
        aOff[it] = (u32)srow * (u32)K + blk * 8;
        aDst[it] = (u32)(row * RS + blk * 8) * 2;
    }
    u32 bOff[NBI], bDst[NBI];
    #pragma unroll
    for (int it = 0; it < NBI; it++) {
        int idx = tid + it * 512;
        int row = idx >> 3, blk = idx & 7;
        bOff[it] = (u32)(n0 + row) * (u32)K + blk * 8;
        bDst[it] = (u32)(NAT * ASZ + row * RS + blk * 8) * 2;
    }

    auto load_chunk = [&](int c, int s) {
        const int k0 = c * KCH;
        const u32 base = sb + (u32)(s * STG) * 2;
        #pragma unroll
        for (int it = 0; it < AIT; it++) {
            CP16(base + aDst[it], Ah + aOff[it] + k0);
            if (NP >= 2) CP16(base + aDst[it] + ASZ * 2, Al + aOff[it] + k0);
        }
        #pragma unroll
        for (int it = 0; it < NBI; it++) {
            CP16(base + bDst[it], Bh + bOff[it] + k0);
            if (NP == 3) CP16(base + bDst[it] + BSZ * 2, Bl + bOff[it] + k0);
        }
    };

    const int aRowO = ((lane >> 3) & 1) * 8 + (lane & 7);
    const int aKO   = ((lane >> 4) & 1) * 8;
    const int bRowO = ((lane >> 4) & 1) * 8 + (lane & 7);
    const int bKO   = ((lane >> 3) & 1) * 8;

    float acc[MI][NF][4];
    #pragma unroll
    for (int i = 0; i < MI; i++)
        #pragma unroll
        for (int j = 0; j < NF; j++)
            #pragma unroll
            for (int q = 0; q < 4; q++) acc[i][j][q] = 0.f;

    const int nch = K / KCH;

    load_chunk(0, 0);
    CP_COMMIT();
    if (nch > 1) load_chunk(1, 1);
    CP_COMMIT();

    for (int c = 0; c < nch; c++) {
        CP_WAIT1();
        __syncthreads();

        const u32 stB = sb + (u32)((c & 1) * STG) * 2;
        #pragma unroll
        for (int ks = 0; ks < 4; ks++) {
            u32 ah[MI][4], al[MI][4];
            #pragma unroll
            for (int mi = 0; mi < MI; mi++) {
                u32 ad = stB + (u32)((wm * WMR + mi * 16 + aRowO) * RS + ks * 16 + aKO) * 2;
                LDMX4(ah[mi], ad);
                if (NP >= 2) LDMX4(al[mi], ad + ASZ * 2);
            }
            #pragma unroll
            for (int j = 0; j < NF / 2; j++) {
                u32 bd = stB + (u32)(NAT * ASZ + (wn * WN + j * 16 + bRowO) * RS + ks * 16 + bKO) * 2;
                u32 th[4];
                LDMX4(th, bd);
                u32 b0h[2] = { th[0], th[1] }, b1h[2] = { th[2], th[3] };
                #pragma unroll
                for (int mi = 0; mi < MI; mi++) {
                    mma_f16(acc[mi][2*j],   ah[mi], b0h);
                    mma_f16(acc[mi][2*j+1], ah[mi], b1h);
                }
                if (NP >= 2) {
                    #pragma unroll
                    for (int mi = 0; mi < MI; mi++) {
                        mma_f16(acc[mi][2*j],   al[mi], b0h);
                        mma_f16(acc[mi][2*j+1], al[mi], b1h);
                    }
                }
                if (NP == 3) {
                    u32 tl[4];
                    LDMX4(tl, bd + BSZ * 2);
                    u32 b0l[2] = { tl[0], tl[1] }, b1l[2] = { tl[2], tl[3] };
                    #pragma unroll
                    for (int mi = 0; mi < MI; mi++) {
                        mma_f16(acc[mi][2*j],   ah[mi], b0l);
                        mma_f16(acc[mi][2*j+1], ah[mi], b1l);
                    }
                }
            }
        }
        __syncthreads();
        if (c + 2 < nch) load_chunk(c + 2, c & 1);
        CP_COMMIT();
    }

    const int gid = lane >> 2, tg = lane & 3;
    #pragma unroll
    for (int mi = 0; mi < MI; mi++) {
        #pragma unroll
        for (int nf = 0; nf < NF; nf++) {
            int mA  = m0 + wm * WMR + mi * 16 + gid;
            int col = n0 + wn * WN + nf * 8 + tg * 2;
            #pragma unroll
            for (int half = 0; half < 2; half++) {
                int m = mA + half * 8;
                if (m < cnt) {
                    float v0 = acc[mi][nf][half * 2 + 0] * alpha;
                    float v1 = acc[mi][nf][half * 2 + 1] * alpha;
                    if (bptr) { v0 += bptr[col]; v1 += bptr[col + 1]; }
                    if (GELU_) { v0 = gelu_exact(v0); v1 = gelu_exact(v1); }
                    size_t o = (size_t)m * ldc + col;
                    if (WF32) { Cf[o] = v0; Cf[o + 1] = v1; }
                    if (WSPLIT) {
                        u16 h0, l0, h1, l1;
                        split2(v0, h0, l0); split2(v1, h1, l1);
                        Ch[o] = h0; Ch[o + 1] = h1;
                        if (Cl) { Cl[o] = l0; Cl[o + 1] = l1; }
                    }
                }
            }
        }
    }
}

// =====================================================================
// Flash attention, fp16 2-product. 2 CTAs/SM.
// =====================================================================
__global__ __launch_bounds__(256, 2)
void flash_attn()
{
    extern __shared__ __align__(16) u16 smem[];
    const int z  = blockIdx.y;
    const int q0 = blockIdx.x * 128;
    const int tid = threadIdx.x, wid = tid >> 5, lane = tid & 31;
    const u32 sb = smem_u32(smem);

    constexpr int QSZ = 128 * RS;
    constexpr int KSZ = 64 * RS;
    constexpr int STG = 2 * KSZ;          // Kh, Vh
    const u32 kvB = 2 * QSZ;

    #pragma unroll
    for (int j = 0; j < 4; j++) {
        int idx = tid + j * 256;
        int row = idx >> 3, blk = idx & 7;
        size_t src = ((size_t)(z * 1024 + q0 + row)) * 64 + blk * 8;
        u32 dst = sb + (u32)(row * RS + blk * 8) * 2;
        CP16(dst,           s_qt_h + src);
        CP16(dst + QSZ * 2, s_qt_l + src);
    }
    CP_COMMIT();

    auto load_kv = [&](int c, int s) {
        const int kv0 = c * 64;
        const u32 base = sb + (kvB + (u32)s * STG) * 2;
        #pragma unroll
        for (int j = 0; j < 2; j++) {
            int idx = tid + j * 256;
            int row = idx >> 3, blk = idx & 7;
            size_t ksrc = ((size_t)(z * 1024 + kv0 + row)) * 64 + blk * 8;
            size_t vsrc = ((size_t)(z * 64 + row)) * 1024 + kv0 + blk * 8;
            u32 d = (u32)(row * RS + blk * 8) * 2;
            CP16(base + d,           s_kt_h + ksrc);
            CP16(base + d + KSZ * 2, s_vt_h + vsrc);
        }
    };

    load_kv(0, 0); CP_COMMIT();
    load_kv(1, 1); CP_COMMIT();

    const int aRowO = ((lane >> 3) & 1) * 8 + (lane & 7);
    const int aKO   = ((lane >> 4) & 1) * 8;
    const int bRowO = ((lane >> 4) & 1) * 8 + (lane & 7);
    const int bKO   = ((lane >> 3) & 1) * 8;

    CP_WAIT2();
    __syncthreads();
    u32 qhf[4][4], qlf[4][4];
    #pragma unroll
    for (int ks = 0; ks < 4; ks++) {
        u32 ad = sb + (u32)((wid * 16 + aRowO) * RS + ks * 16 + aKO) * 2;
        LDMX4(qhf[ks], ad);
        LDMX4(qlf[ks], ad + QSZ * 2);
    }

    float of[8][4];
    #pragma unroll
    for (int n = 0; n < 8; n++)
        #pragma unroll
        for (int q = 0; q < 4; q++) of[n][q] = 0.f;
    float m0 = -1e30f, m1 = -1e30f, l0 = 0.f, l1 = 0.f;

    for (int c = 0; c < 16; c++) {
        CP_WAIT1();
        __syncthreads();
        const u32 stB = sb + (kvB + (u32)((c & 1) * STG)) * 2;

        float sacc[8][4];
        #pragma unroll
        for (int n = 0; n < 8; n++)
            #pragma unroll
            for (int q = 0; q < 4; q++) sacc[n][q] = 0.f;

        #pragma unroll
        for (int ks = 0; ks < 4; ks++) {
            u32 b0h[4][2], b1h[4][2];
            #pragma unroll
            for (int j = 0; j < 4; j++) {
                u32 bd = stB + (u32)((j * 16 + bRowO) * RS + ks * 16 + bKO) * 2;
                u32 th[4];
                LDMX4(th, bd);
                b0h[j][0] = th[0]; b0h[j][1] = th[1];
                b1h[j][0] = th[2]; b1h[j][1] = th[3];
            }
            #pragma unroll
            for (int j = 0; j < 4; j++) {
                mma_f16(sacc[2*j],   qhf[ks], b0h[j]);
                mma_f16(sacc[2*j+1], qhf[ks], b1h[j]);
            }
            #pragma unroll
            for (int j = 0; j < 4; j++) {
                mma_f16(sacc[2*j],   qlf[ks], b0h[j]);
                mma_f16(sacc[2*j+1], qlf[ks], b1h[j]);
            }
        }

        float mx0 = -1e30f, mx1 = -1e30f;
        #pragma unroll
        for (int n = 0; n < 8; n++) {
            #pragma unroll
            for (int q = 0; q < 4; q++) sacc[n][q] *= 0.125f;
            mx0 = fmaxf(mx0, fmaxf(sacc[n][0], sacc[n][1]));
            mx1 = fmaxf(mx1, fmaxf(sacc[n][2], sacc[n][3]));
        }
        mx0 = fmaxf(mx0, __shfl_xor_sync(0xffffffffu, mx0, 1));
        mx0 = fmaxf(mx0, __shfl_xor_sync(0xffffffffu, mx0, 2));
        mx1 = fmaxf(mx1, __shfl_xor_sync(0xffffffffu, mx1, 1));
        mx1 = fmaxf(mx1, __shfl_xor_sync(0xffffffffu, mx1, 2));
        float mn0 = fmaxf(m0, mx0), mn1 = fmaxf(m1, mx1);
        float sc0 = __expf(m0 - mn0), sc1 = __expf(m1 - mn1);
        m0 = mn0; m1 = mn1;
        float ps0 = 0.f, ps1 = 0.f;
        #pragma unroll
        for (int n = 0; n < 8; n++) {
            sacc[n][0] = __expf(sacc[n][0] - mn0);
            sacc[n][1] = __expf(sacc[n][1] - mn0);
            sacc[n][2] = __expf(sacc[n][2] - mn1);
            sacc[n][3] = __expf(sacc[n][3] - mn1);
            ps0 += sacc[n][0] + sacc[n][1];
            ps1 += sacc[n][2] + sacc[n][3];
        }
        ps0 += __shfl_xor_sync(0xffffffffu, ps0, 1);
        ps0 += __shfl_xor_sync(0xffffffffu, ps0, 2);
        ps1 += __shfl_xor_sync(0xffffffffu, ps1, 1);
        ps1 += __shfl_xor_sync(0xffffffffu, ps1, 2);
        l0 = l0 * sc0 + ps0;
        l1 = l1 * sc1 + ps1;
        #pragma unroll
        for (int n = 0; n < 8; n++) {
            of[n][0] *= sc0; of[n][1] *= sc0;
            of[n][2] *= sc1; of[n][3] *= sc1;
        }

        #pragma unroll
        for (int kk = 0; kk < 4; kk++) {
            u32 ph[4], pl[4];
            split_pack2(sacc[2*kk][0],   sacc[2*kk][1],   ph[0], pl[0]);
            split_pack2(sacc[2*kk][2],   sacc[2*kk][3],   ph[1], pl[1]);
            split_pack2(sacc[2*kk+1][0], sacc[2*kk+1][1], ph[2], pl[2]);
            split_pack2(sacc[2*kk+1][2], sacc[2*kk+1][3], ph[3], pl[3]);
            u32 b0h[4][2], b1h[4][2];
            #pragma unroll
            for (int j2 = 0; j2 < 4; j2++) {
                u32 vd = stB + (u32)(KSZ) * 2
                       + (u32)((j2 * 16 + bRowO) * RS + kk * 16 + bKO) * 2;
                u32 th[4];
                LDMX4(th, vd);
                b0h[j2][0] = th[0]; b0h[j2][1] = th[1];
                b1h[j2][0] = th[2]; b1h[j2][1] = th[3];
            }
            #pragma unroll
            for (int j2 = 0; j2 < 4; j2++) {
                mma_f16(of[2*j2],   ph, b0h[j2]);
                mma_f16(of[2*j2+1], ph, b1h[j2]);
            }
            #pragma unroll
            for (int j2 = 0; j2 < 4; j2++) {
                mma_f16(of[2*j2],   pl, b0h[j2]);
                mma_f16(of[2*j2+1], pl, b1h[j2]);
            }
        }
        __syncthreads();
        if (c + 2 < 16) load_kv(c + 2, c & 1);
        CP_COMMIT();
    }

    const int gid = lane >> 2, tg = lane & 3;
    float inv0 = 1.f / l0, inv1 = 1.f / l1;
    int qr = q0 + wid * 16 + gid;
    #pragma unroll
    for (int n = 0; n < 8; n++) {
        int dh = n * 8 + tg * 2;
        float2 v0 = make_float2(of[n][0] * inv0, of[n][1] * inv0);
        float2 v1 = make_float2(of[n][2] * inv1, of[n][3] * inv1);
        *(float2*)&g_ot[((size_t)(z * 1024 + qr)) * 64 + dh]     = v0;
        *(float2*)&g_ot[((size_t)(z * 1024 + qr + 8)) * 64 + dh] = v1;
    }
}

// ---------------- fused conversion ----------------
struct SplitSegs {
    const float4* s[4];
    uint2* h[4];
    uint2* l[4];
    int end4[4];
};
__global__ void split_all(SplitSegs g) {
    const int total = g.end4[3];
    for (int i = blockIdx.x * blockDim.x + threadIdx.x; i < total; i += gridDim.x * blockDim.x) {
        int k = 0;
        #pragma unroll
        for (int t = 0; t < 3; t++) k += (i >= g.end4[t]) ? 1 : 0;
        int j = i - (k ? g.end4[k - 1] : 0);
        float4 v = g.s[k][j];
        u16 hh[4], ll[4];
        split2(v.x, hh[0], ll[0]); split2(v.y, hh[1], ll[1]);
        split2(v.z, hh[2], ll[2]); split2(v.w, hh[3], ll[3]);
        g.h[k][j] = *(uint2*)hh;
        g.l[k][j] = *(uint2*)ll;
    }
}

__global__ void transpose_split(const float* __restrict__ s, u16* __restrict__ oh, u16* __restrict__ ol,
                                int R, int C) {
    __shared__ float t[32][33];
    size_t zo = (size_t)blockIdx.z * R * C;
    const float* src = s + zo;
    int c0 = blockIdx.x * 32, r0 = blockIdx.y * 32;
    int tx = threadIdx.x & 31, ty = threadIdx.x >> 5;
    #pragma unroll
    for (int dy = 0; dy < 32; dy += 8)
        t[ty + dy][tx] = src[(size_t)(r0 + ty + dy) * C + c0 + tx];
    __syncthreads();
    #pragma unroll
    for (int dy = 0; dy < 32; dy += 8) {
        float v = t[tx][ty + dy];
        size_t o = zo + (size_t)(c0 + ty + dy) * R + r0 + tx;
        u16 hh, ll; split2(v, hh, ll);
        oh[o] = hh;
        if (ol) ol[o] = ll;
    }
}

// bc[i] = sum_m W[i,m]*bin[m] + badd[i]
__global__ void bias_comb(const float* __restrict__ W, const float* __restrict__ bin,
                          const float* __restrict__ badd, float* __restrict__ bc) {
    __shared__ float sm[32];
    int i = blockIdx.x, t = threadIdx.x;
    float s = 0.f;
    for (int m = t; m < DIM; m += 256) s += W[(size_t)i * DIM + m] * bin[m];
    s = blk_reduce_sum(s, sm);
    if (t == 0) bc[i] = s + badd[i];
}

__global__ void headsplit_qk(const float* __restrict__ in, u16* __restrict__ oh, u16* __restrict__ ol) {
    for (int i = blockIdx.x * blockDim.x + threadIdx.x; i < NTOK * DIM; i += gridDim.x * blockDim.x) {
        int d = i & 63, s = (i >> 6) & 1023, h = (i >> 16) & 15, b = i >> 20;
        float v = in[(size_t)((b << 10) + s) * DIM + (h << 6) + d];
        u16 hh, ll; split2(v, hh, ll);
        oh[i] = hh;
        if (ol) ol[i] = ll;
    }
}

__global__ void headsplit_vT(const float* __restrict__ in, u16* __restrict__ oh) {
    __shared__ float t[32][33];
    int z = blockIdx.z;
    int b = z >> 4, h = z & 15;
    int s0 = blockIdx.x * 32, d0 = blockIdx.y * 32;
    int tx = threadIdx.x & 31, ty = threadIdx.x >> 5;
    #pragma unroll
    for (int dy = 0; dy < 32; dy += 8)
        t[ty + dy][tx] = in[(size_t)((b << 10) + s0 + ty + dy) * DIM + h * 64 + d0 + tx];
    __syncthreads();
    #pragma unroll
    for (int dy = 0; dy < 32; dy += 8) {
        float v = t[tx][ty + dy];
        size_t o = (size_t)(z * 64 + d0 + ty + dy) * 1024 + s0 + tx;
        oh[o] = f2h(v);
    }
}

__global__ void head_merge_split(const float* __restrict__ in, u16* __restrict__ oh, u16* __restrict__ ol) {
    for (int i = blockIdx.x * blockDim.x + threadIdx.x; i < NTOK * DIM; i += gridDim.x * blockDim.x) {
        int col = i & 1023, h = col >> 6, d = col & 63;
        int s = (i >> 10) & 1023, b = i >> 20;
        float v = in[(size_t)(((b << 4) + h) * 1024 + s) * 64 + d];
        u16 hh, ll; split2(v, hh, ll);
        oh[i] = hh; ol[i] = ll;
    }
}

// LN(a+res) -> fp32 + single fp16
__global__ void ln_res_split(const float* __restrict__ a, const float* __restrict__ res,
                             const float* __restrict__ g, const float* __restrict__ b,
                             float* __restrict__ of, u16* __restrict__ oh) {
    __shared__ float sm[32];
    const size_t base = (size_t)blockIdx.x * DIM;
    int t = threadIdx.x;
    float v[4];
    float s = 0.f;
    #pragma unroll
    for (int j = 0; j < 4; j++) {
        int c = t + j * 256;
        v[j] = a[base + c] + res[base + c];
        s += v[j];
    }
    s = blk_reduce_sum(s, sm);
    float mean = s * (1.0f / DIM);
    float s2 = 0.f;
    #pragma unroll
    for (int j = 0; j < 4; j++) { float d = v[j] - mean; s2 += d * d; }
    s2 = blk_reduce_sum(s2, sm);
    float rs = rsqrtf(s2 * (1.0f / DIM) + 1e-5f);
    #pragma unroll
    for (int j = 0; j < 4; j++) {
        int c = t + j * 256;
        float o = (v[j] - mean) * rs * g[c] + b[c];
        of[base + c] = o;
        oh[base + c] = f2h(o);
    }
}

__global__ void combine_ln(const float* __restrict__ g, const float* __restrict__ b,
                           float* __restrict__ out) {
    __shared__ float sm[32];
    const int tok = blockIdx.x;
    const size_t base = (size_t)tok * DIM;
    int t = threadIdx.x;
    float v[4];
    #pragma unroll
    for (int j = 0; j < 4; j++) v[j] = g_x[base + t + j * 256];
    const int nl = g_tcnt[tok];
    for (int l = 0; l < nl; l++) {
        int   e    = g_te[tok * 3 + l];
        int   slot = g_tslot[tok * 3 + l];
        float gt   = g_tgate[tok * 3 + l];
        const float* row = g_e2 + ((size_t)e * NTOK + slot) * DIM;
        #pragma unroll
        for (int j = 0; j < 4; j++) v[j] += gt * row[t + j * 256];
    }
    float s = 0.f;
    #pragma unroll
    for (int j = 0; j < 4; j++) s += v[j];
    s = blk_reduce_sum(s, sm);
    float mean = s * (1.0f / DIM);
    float s2 = 0.f;
    #pragma unroll
    for (int j = 0; j < 4; j++) { float d = v[j] - mean; s2 += d * d; }
    s2 = blk_reduce_sum(s2, sm);
    float rs = rsqrtf(s2 * (1.0f / DIM) + 1e-5f);
    #pragma unroll
    for (int j = 0; j < 4; j++) {
        int c = t + j * 256;
        out[base + c] = (v[j] - mean) * rs * g[c] + b[c];
    }
}

__global__ void gating(const float* __restrict__ Wg) {
    __shared__ float logits[NEXP];
    const int tok = blockIdx.x;
    const float* xr = g_x + (size_t)tok * DIM;
    int w = threadIdx.x >> 5, lane = threadIdx.x & 31;
    float s = 0.f;
    for (int i = lane; i < DIM; i += 32) s += xr[i] * Wg[i * NEXP + w];
    #pragma unroll
    for (int o = 16; o; o >>= 1) s += __shfl_down_sync(0xffffffffu, s, o);
    if (!lane) logits[w] = s;
    __syncthreads();
    if (threadIdx.x == 0) {
        float p[NEXP];
        float mx = -1e30f;
        for (int e = 0; e < NEXP; e++) mx = fmaxf(mx, logits[e]);
        float sum = 0.f;
        for (int e = 0; e < NEXP; e++) { p[e] = __expf(logits[e] - mx); sum += p[e]; }
        float inv = 1.f / sum;
        for (int e = 0; e < NEXP; e++) { p[e] *= inv; g_probs[tok * NEXP + e] = p[e]; }
        int i0 = 0;
        for (int e = 1; e < NEXP; e++) if (p[e] > p[i0]) i0 = e;
        int i1 = -1;
        for (int e = 0; e < NEXP; e++) if (e != i0 && (i1 < 0 || p[e] > p[i1])) i1 = e;
        int i2 = -1;
        for (int e = 0; e < NEXP; e++) if (e != i0 && e != i1 && (i2 < 0 || p[e] > p[i2])) i2 = e;
        int   ids[3] = { i0, i1, i2 };
        float gts[3] = { p[i0],
                         (p[i1] >= THRESH) ? p[i1] : 0.f,
                         (p[i2] >= THRESH) ? p[i2] : 0.f };
        int nl = 0;
        #pragma unroll
        for (int j = 0; j < 3; j++) {
            if (gts[j] > 0.f) {
                int slot = atomicAdd(&g_cnt[ids[j]], 1);
                g_tok  [ids[j] * NTOK + slot] = tok;
                g_te   [tok * 3 + nl] = ids[j];
                g_tslot[tok * 3 + nl] = slot;
                g_tgate[tok * 3 + nl] = gts[j];
                nl++;
            }
        }
        g_tcnt[tok] = nl;
    }
}

__global__ void zero_small() {
    int t = threadIdx.x;
    if (t < NEXP) g_cnt[t] = 0;
}
__global__ void aux_kernel(float* __restrict__ out, int out_size) {
    if (out_size <= OUT_MAIN) return;
    __shared__ float sm[32];
    int t = threadIdx.x;
    float total = 0.f;
    for (int e = 0; e < NEXP; e++) {
        float s = 0.f;
        for (int tok = t; tok < NTOK; tok += 256) s += g_probs[tok * NEXP + e];
        s = blk_reduce_sum(s, sm);
        if (t == 0) total += ((float)g_cnt[e] / (float)NTOK) * (s / (float)NTOK);
    }
    if (t == 0) out[OUT_MAIN] = COEF * (float)NEXP * total;
}

// ---------------- host launcher ----------------
#define GETSYM(var, sym) do { cudaGetSymbolAddress((void**)&(var), sym); } while (0)

extern "C" void kernel_launch(void* const* d_in, const int* in_sizes, int n_in,
                              void* d_out, int out_size)
{
    (void)in_sizes; (void)n_in;
    const float* query  = (const float*)d_in[0];
    const float* keyval = (const float*)d_in[1];
    const float* Wq = (const float*)d_in[2];  const float* bq = (const float*)d_in[3];
    const float* Wk = (const float*)d_in[4];  const float* bk = (const float*)d_in[5];
    const float* Wv = (const float*)d_in[6];  const float* bv = (const float*)d_in[7];
    const float* W_in  = (const float*)d_in[8];  const float* b_in  = (const float*)d_in[9];
    const float* W_out = (const float*)d_in[10]; const float* b_out = (const float*)d_in[11];
    const float* Wa = (const float*)d_in[12]; const float* ba = (const float*)d_in[13];
    const float* ln1g = (const float*)d_in[14]; const float* ln1b = (const float*)d_in[15];
    const float* Wg = (const float*)d_in[16];
    const float* ew1 = (const float*)d_in[17]; const float* eb1 = (const float*)d_in[18];
    const float* ew2 = (const float*)d_in[19]; const float* eb2 = (const float*)d_in[20];
    const float* ln2g = (const float*)d_in[21]; const float* ln2b = (const float*)d_in[22];
    float* out = (float*)d_out;

    float *qh, *kh, *vh, *ot, *a, *x, *e2p, *bc;
    GETSYM(qh, g_qh); GETSYM(kh, g_kh); GETSYM(vh, g_vh);
    GETSYM(ot, g_ot); GETSYM(a, g_a); GETSYM(x, g_x);
    GETSYM(e2p, g_e2); GETSYM(bc, g_bc);
    u16 *qyh,*qyl,*kvh,*kvl,*qth,*qtl,*kth,*vth,*oh,*ol,*xh,*hhh;
    u16 *wAh,*wAl,*wTh,*wTl,*wch,*wcl,*e1h,*e2h;
    GETSYM(qyh, s_query_h); GETSYM(qyl, s_query_l);
    GETSYM(kvh, s_kv_h);    GETSYM(kvl, s_kv_l);
    GETSYM(qth, s_qt_h); GETSYM(qtl, s_qt_l);
    GETSYM(kth, s_kt_h);
    GETSYM(vth, s_vt_h);
    GETSYM(oh,  s_o_h);  GETSYM(ol,  s_o_l);
    GETSYM(xh,  s_x_h);
    GETSYM(hhh, s_hh);
    GETSYM(wAh, s_wA_h); GETSYM(wAl, s_wA_l);
    GETSYM(wTh, s_wT_h); GETSYM(wTl, s_wT_l);
    GETSYM(wch, s_wc_h); GETSYM(wcl, s_wc_l);
    GETSYM(e1h, s_e1_h); GETSYM(e2h, s_e2_h);
    int *tokp; GETSYM(tokp, g_tok);
    int *cntp; GETSYM(cntp, g_cnt);

    const int SM_NP1 = 2 * (256 + 128) * RS * 2;            // 110592 B
    const int SM_NP2 = 2 * (2 * 256 + 128) * RS * 2;        // 184320 B
    const int SM_NP3 = 2 * (2 * 256 + 2 * 128) * RS * 2;    // 221184 B
    const int SFLASH = (2 * 128 + 2 * 2 * 64) * RS * 2;     // 73728 B
    cudaFuncSetAttribute((const void*)gemm_tc<2,256,128,false,true ,false,false>, cudaFuncAttributeMaxDynamicSharedMemorySize, SM_NP2);
    cudaFuncSetAttribute((const void*)gemm_tc<1,256,128,true ,false,true ,true >, cudaFuncAttributeMaxDynamicSharedMemorySize, SM_NP1);
    cudaFuncSetAttribute((const void*)gemm_tc<1,256,128,false,true ,false,false>, cudaFuncAttributeMaxDynamicSharedMemorySize, SM_NP1);
    cudaFuncSetAttribute((const void*)gemm_tc<3,256,128,false,false,true ,false>, cudaFuncAttributeMaxDynamicSharedMemorySize, SM_NP3);
    cudaFuncSetAttribute((const void*)flash_attn, cudaFuncAttributeMaxDynamicSharedMemorySize, SFLASH);

    const dim3 T512(512);
    const dim3 T256(256);
    const dim3 GLIN(DIM/128, NTOK/256, 1);

    // ---- fused fp16 split of inputs + A-side weights (Win x3 | Wa packed) ----
    SplitSegs sg;
    sg.s[0] = (const float4*)query;  sg.h[0] = (uint2*)qyh;  sg.l[0] = (uint2*)qyl;
    sg.s[1] = (const float4*)keyval; sg.h[1] = (uint2*)kvh;  sg.l[1] = (uint2*)kvl;
    sg.s[2] = (const float4*)W_in;   sg.h[2] = (uint2*)wAh;  sg.l[2] = (uint2*)wAl;
    sg.s[3] = (const float4*)Wa;     sg.h[3] = (uint2*)(wAh + 3*DIM*DIM);
    sg.l[3] = (uint2*)(wAl + 3*DIM*DIM);
    sg.end4[0] = NTOK*DIM/4;
    sg.end4[1] = sg.end4[0] + NTOK*DIM/4;
    sg.end4[2] = sg.end4[1] + 3*DIM*DIM/4;
    sg.end4[3] = sg.end4[2] + DIM*DIM/4;
    split_all<<<2048, 256>>>(sg);

    // ---- transposed splits of B-side weights into packed array ----
    transpose_split<<<dim3(DIM/32, DIM/32, 1), T256>>>(Wq,    wTh,             wTl,             DIM, DIM);
    transpose_split<<<dim3(DIM/32, DIM/32, 1), T256>>>(Wk,    wTh + DIM*DIM,   wTl + DIM*DIM,   DIM, DIM);
    transpose_split<<<dim3(DIM/32, DIM/32, 1), T256>>>(Wv,    wTh + 2*DIM*DIM, wTl + 2*DIM*DIM, DIM, DIM);
    transpose_split<<<dim3(DIM/32, DIM/32, 1), T256>>>(W_out, wTh + 3*DIM*DIM, wTl + 3*DIM*DIM, DIM, DIM);

    // ---- BATCHED weight composition (z=0..3): Wc[z] = WA[z] @ WT[z]^T ----
    gemm_tc<3,256,128,false,false,true,false><<<dim3(DIM/128, DIM/256, 4), T512, SM_NP3>>>(
        wAh, wAl, wTh, wTl, DIM,
        (long long)DIM*DIM, (long long)DIM*DIM, (long long)DIM*DIM,
        nullptr, nullptr, nullptr, 0, 1.f, nullptr, wch, wcl, DIM);

    // ---- combined biases (fp32 exact) ----
    bias_comb<<<DIM, T256>>>(W_in,              bq,    b_in,           bc);
    bias_comb<<<DIM, T256>>>(W_in + DIM*DIM,    bk,    b_in + DIM,     bc + DIM);
    bias_comb<<<DIM, T256>>>(W_in + 2*DIM*DIM,  bv,    b_in + 2*DIM,   bc + 2*DIM);
    bias_comb<<<DIM, T256>>>(Wa,                b_out, ba,             bc + 3*DIM);

    // ---- token linears (NP=2) ----
    gemm_tc<2,256,128,false,true,false,false><<<GLIN, T512, SM_NP2>>>(
        qyh, qyl, wch,             nullptr, DIM, 0, 0, 0, nullptr, nullptr, bc,         0, 1.f, qh, nullptr, nullptr, DIM);
    gemm_tc<2,256,128,false,true,false,false><<<GLIN, T512, SM_NP2>>>(
        kvh, kvl, wch + DIM*DIM,   nullptr, DIM, 0, 0, 0, nullptr, nullptr, bc + DIM,   0, 1.f, kh, nullptr, nullptr, DIM);
    gemm_tc<2,256,128,false,true,false,false><<<GLIN, T512, SM_NP2>>>(
        kvh, kvl, wch + 2*DIM*DIM, nullptr, DIM, 0, 0, 0, nullptr, nullptr, bc + 2*DIM, 0, 1.f, vh, nullptr, nullptr, DIM);

    // ---- head reshape ----
    headsplit_qk<<<512, 256>>>(qh, qth, qtl);
    headsplit_qk<<<512, 256>>>(kh, kth, nullptr);
    headsplit_vT<<<dim3(SQL/32, 2, BH), T256>>>(vh, vth);

    // ---- fused flash attention -> g_ot ----
    flash_attn<<<dim3(SQL/128, BH), T256, SFLASH>>>();

    head_merge_split<<<512, 256>>>(ot, oh, ol);

    // ---- combined out-projection + adapter (NP=2) ----
    gemm_tc<2,256,128,false,true,false,false><<<GLIN, T512, SM_NP2>>>(
        oh, ol, wch + 3*DIM*DIM, nullptr, DIM, 0, 0, 0, nullptr, nullptr, bc + 3*DIM, 0, 1.f, a, nullptr, nullptr, DIM);

    // ---- LN1 (+residual) -> x fp32 + fp16 ----
    ln_res_split<<<NTOK, T256>>>(a, query, ln1g, ln1b, x, xh);

    // ---- gating ----
    zero_small<<<1, 32>>>();
    gating<<<NTOK, T256>>>(Wg);

    // ---- MoE expert weights (hi only) + FFNs (NP=1, pure fp16) ----
    transpose_split<<<dim3(HDIM/32, DIM/32, NEXP), T256>>>(ew1, e1h, nullptr, DIM, HDIM);
    transpose_split<<<dim3(DIM/32, HDIM/32, NEXP), T256>>>(ew2, e2h, nullptr, HDIM, DIM);
    gemm_tc<1,256,128,true,false,true,true><<<dim3(HDIM/128, NTOK/256, NEXP), T512, SM_NP1>>>(
        xh, nullptr, e1h, nullptr, DIM,
        0, (long long)HDIM*DIM, (long long)NTOK*HDIM,
        tokp, cntp, eb1, HDIM, 1.f, nullptr, hhh, nullptr, HDIM);
    gemm_tc<1,256,128,false,true,false,false><<<dim3(DIM/128, NTOK/256, NEXP), T512, SM_NP1>>>(
        hhh, nullptr, e2h, nullptr, HDIM,
        (long long)NTOK*HDIM, (long long)DIM*HDIM, (long long)NTOK*DIM,
        nullptr, cntp, eb2, DIM, 1.f, e2p, nullptr, nullptr, DIM);

    // ---- fused combine + final LN -> output, then aux scalar ----
    combine_ln<<<NTOK, T256>>>(ln2g, ln2b, out);
    aux_kernel<<<1, 256>>>(out, out_size);
}

// round 17
// speedup vs baseline: 2.1124x; 1.0719x over previous
#include <cuda_runtime.h>
#include <cuda_fp16.h>
#include <math.h>
#include <stddef.h>
#include <stdint.h>

// ---------------- problem constants ----------------
#define BATCH 4
#define SQL   1024
#define SKV   1024
#define DIM   1024
#define NH    16
#define DH    64
#define NEXP  8
#define HDIM  4096
#define NTOK  (BATCH*SQL)       // 4096
#define BH    (BATCH*NH)        // 64
#define OUT_MAIN (NTOK*DIM)
#define THRESH 0.05f
#define COEF   0.01f
#define KCH   64                // K chunk
#define RS    72                // smem row stride in u16 (64 data + 8 pad)

typedef unsigned short u16;
typedef unsigned int   u32;

// ---------------- static device scratch (fp32) ----------------
__device__ float g_vh[NTOK*DIM];
__device__ float g_a [NTOK*DIM];
__device__ float g_x [NTOK*DIM];
__device__ float g_e2[(size_t)NEXP*NTOK*DIM];   // 128 MB
__device__ int   g_cnt[NEXP];
__device__ int   g_tok[NEXP*NTOK];
__device__ float g_probs[NTOK*NEXP];
__device__ int   g_tcnt[NTOK];
__device__ int   g_te  [NTOK*3];
__device__ int   g_tslot[NTOK*3];
__device__ float g_tgate[NTOK*3];
__device__ float g_bc[4*DIM];          // combined biases: q,k,v,oa

// ---------------- fp16 hi/lo split buffers ----------------
__device__ u16 s_query_h[NTOK*DIM];
__device__ u16 s_kv_h[NTOK*DIM];
__device__ u16 s_qt_h[NTOK*DIM],    s_qt_l[NTOK*DIM];    // [bh][sq][dh]
__device__ u16 s_kt_h[NTOK*DIM];                          // [bh][skv][dh]
__device__ u16 s_vt_h[NTOK*DIM];                          // [bh][dh][skv]
__device__ u16 s_o_h[NTOK*DIM],     s_o_l[NTOK*DIM];      // [tok][DIM] (from flash)
__device__ u16 s_x_h[NTOK*DIM];
__device__ u16 s_hh [(size_t)NEXP*NTOK*HDIM];             // expert hidden (fp16)
// weights: packed 4x DIM^2 arrays for batched composition
__device__ u16 s_wA_h[4*DIM*DIM], s_wA_l[4*DIM*DIM];      // [Win q,k,v | Wa]
__device__ u16 s_wT_h[4*DIM*DIM], s_wT_l[4*DIM*DIM];      // [WqT,WkT,WvT,WoT]
__device__ u16 s_wc_h[4*DIM*DIM], s_wc_l[4*DIM*DIM];      // composed
__device__ u16 s_e1_h[(size_t)NEXP*HDIM*DIM];   // [e][n=HDIM][k=DIM]
__device__ u16 s_e2_h[(size_t)NEXP*DIM*HDIM];   // [e][n=DIM][k=HDIM]

// ---------------- helpers ----------------
__device__ __forceinline__ u16 f2h(float v) { __half h = __float2half_rn(v); return *(u16*)&h; }
__device__ __forceinline__ float h2f(u16 u) { __half h; *(u16*)&h = u; return __half2float(h); }
__device__ __forceinline__ void split2(float v, u16& h, u16& l) {
    u16 hu = f2h(v); h = hu; l = f2h(v - h2f(hu));
}
__device__ __forceinline__ void split_pack2(float v0, float v1, u32& h, u32& l) {
    u16 h0, l0, h1, l1;
    split2(v0, h0, l0); split2(v1, h1, l1);
    h = (u32)h0 | ((u32)h1 << 16);
    l = (u32)l0 | ((u32)l1 << 16);
}
__device__ __forceinline__ float gelu_exact(float v) {
    return 0.5f * v * (1.0f + erff(v * 0.70710678118654752f));
}
__device__ __forceinline__ u32 smem_u32(const void* p) {
    u32 a;
    asm("{ .reg .u64 t; cvta.to.shared.u64 t, %1; cvt.u32.u64 %0, t; }" : "=r"(a) : "l"(p));
    return a;
}
__device__ __forceinline__ float blk_reduce_sum(float v, float* sm) {
    int lane = threadIdx.x & 31, w = threadIdx.x >> 5;
    #pragma unroll
    for (int o = 16; o; o >>= 1) v += __shfl_down_sync(0xffffffffu, v, o);
    if (!lane) sm[w] = v;
    __syncthreads();
    if (threadIdx.x < 32) {
        v = (threadIdx.x < 8) ? sm[threadIdx.x] : 0.f;
        #pragma unroll
        for (int o = 4; o; o >>= 1) v += __shfl_down_sync(0xffffffffu, v, o);
        if (!threadIdx.x) sm[0] = v;
    }
    __syncthreads();
    float r = sm[0];
    __syncthreads();
    return r;
}

__device__ __forceinline__ void mma_f16(float* c, const u32* a, const u32* b) {
    asm volatile(
        "mma.sync.aligned.m16n8k16.row.col.f32.f16.f16.f32 "
        "{%0,%1,%2,%3}, {%4,%5,%6,%7}, {%8,%9}, {%0,%1,%2,%3};"
        : "+f"(c[0]), "+f"(c[1]), "+f"(c[2]), "+f"(c[3])
        : "r"(a[0]), "r"(a[1]), "r"(a[2]), "r"(a[3]), "r"(b[0]), "r"(b[1]));
}

#define CP16(dst, src) \
    asm volatile("cp.async.cg.shared.global [%0], [%1], 16;" :: "r"(dst), "l"(src) : "memory")
#define CP_COMMIT() asm volatile("cp.async.commit_group;" ::: "memory")
#define CP_WAIT1()  asm volatile("cp.async.wait_group 1;" ::: "memory")
#define CP_WAIT2()  asm volatile("cp.async.wait_group 2;" ::: "memory")
#define LDMX4(r, addr) \
    asm volatile("ldmatrix.sync.aligned.m8n8.x4.shared.b16 {%0,%1,%2,%3}, [%4];" \
        : "=r"((r)[0]), "=r"((r)[1]), "=r"((r)[2]), "=r"((r)[3]) : "r"(addr))

// =====================================================================
// fp16-split tensor-core GEMM. C[z] = alpha*(A@B^T) + bias.
// NP=1/2/3 precision products. PERM: write split output permuted
// [tok,DIM] -> [bh][s][dh]. 512 threads, 16 warps 8(M)x2(N),
// BM=256, BN=128, 2-stage cp.async.
// =====================================================================
template<int NP, int BM, int BN, bool GELU_, bool WF32, bool WSPLIT, bool GATHER, bool PERM>
__global__ __launch_bounds__(512, 1)
void gemm_tc(const u16* __restrict__ Ah_, const u16* __restrict__ Al_,
             const u16* __restrict__ Bh_, const u16* __restrict__ Bl_,
             int K, long long As, long long Bs, long long Cs,
             const int* __restrict__ rowmap, const int* __restrict__ cntArr,
             const float* __restrict__ bias, long long biasStride, float alpha,
             float* __restrict__ Cf, u16* __restrict__ Ch, u16* __restrict__ Cl, int ldc)
{
    extern __shared__ __align__(16) u16 smem[];
    const int z = blockIdx.z;
    const int cnt = cntArr ? cntArr[z] : 0x40000000;
    const int m0 = blockIdx.y * BM;
    if (m0 >= cnt) return;
    const int n0 = blockIdx.x * BN;

    const u16* Ah = Ah_ + (size_t)z * As;
    const u16* Al = (NP >= 2) ? (Al_ + (size_t)z * As) : nullptr;
    const u16* Bh = Bh_ + (size_t)z * Bs;
    const u16* Bl = (NP == 3) ? (Bl_ + (size_t)z * Bs) : nullptr;
    if (WF32)   Cf += (size_t)z * Cs;
    if (WSPLIT && !PERM) { Ch += (size_t)z * Cs; if (Cl) Cl += (size_t)z * Cs; }
    const float* bptr = bias ? bias + (size_t)z * biasStride : nullptr;
    const int* rmap = GATHER ? (rowmap + (size_t)z * NTOK) : nullptr;

    constexpr int ASZ = BM * RS;
    constexpr int BSZ = BN * RS;
    constexpr int NAT = (NP >= 2) ? 2 : 1;
    constexpr int NBT = (NP == 3) ? 2 : 1;
    constexpr int STG = NAT * ASZ + NBT * BSZ;
    constexpr int WMR = BM / 8;
    constexpr int MI  = WMR / 16;
    constexpr int WN  = BN / 2;
    constexpr int NF  = WN / 8;
    constexpr int AIT = BM / 64;
    constexpr int NBI = BN / 64;

    const int tid = threadIdx.x;
    const int wid = tid >> 5, lane = tid & 31;
    const int wm = wid & 7, wn = wid >> 3;
    const u32 sb = smem_u32(smem);

    u32 aOff[AIT], aDst[AIT];
    #pragma unroll
    for (int it = 0; it < AIT; it++) {
        int idx = tid + it * 512;
        int row = idx >> 3, blk = idx & 7;
        int srow;
        if (GATHER) { int gm = m0 + row; if (gm >= cnt) gm = cnt - 1; srow = rmap[gm]; }
        else srow = m0 + row;
        aOff[it] = (u32)srow * (u32)K + blk * 8;
        aDst[it] = (u32)(row * RS + blk * 8) * 2;
    }
    u32 bOff[NBI], bDst[NBI];
    #pragma unroll
    for (int it = 0; it < NBI; it++) {
        int idx = tid + it * 512;
        int row = idx >> 3, blk = idx & 7;
        bOff[it] = (u32)(n0 + row) * (u32)K + blk * 8;
        bDst[it] = (u32)(NAT * ASZ + row * RS + blk * 8) * 2;
    }

    auto load_chunk = [&](int c, int s) {
        const int k0 = c * KCH;
        const u32 base = sb + (u32)(s * STG) * 2;
        #pragma unroll
        for (int it = 0; it < AIT; it++) {
            CP16(base + aDst[it], Ah + aOff[it] + k0);
            if (NP >= 2) CP16(base + aDst[it] + ASZ * 2, Al + aOff[it] + k0);
        }
        #pragma unroll
        for (int it = 0; it < NBI; it++) {
            CP16(base + bDst[it], Bh + bOff[it] + k0);
            if (NP == 3) CP16(base + bDst[it] + BSZ * 2, Bl + bOff[it] + k0);
        }
    };

    const int aRowO = ((lane >> 3) & 1) * 8 + (lane & 7);
    const int aKO   = ((lane >> 4) & 1) * 8;
    const int bRowO = ((lane >> 4) & 1) * 8 + (lane & 7);
    const int bKO   = ((lane >> 3) & 1) * 8;

    float acc[MI][NF][4];
    #pragma unroll
    for (int i = 0; i < MI; i++)
        #pragma unroll
        for (int j = 0; j < NF; j++)
            #pragma unroll
            for (int q = 0; q < 4; q++) acc[i][j][q] = 0.f;

    const int nch = K / KCH;

    load_chunk(0, 0);
    CP_COMMIT();
    if (nch > 1) load_chunk(1, 1);
    CP_COMMIT();

    for (int c = 0; c < nch; c++) {
        CP_WAIT1();
        __syncthreads();

        const u32 stB = sb + (u32)((c & 1) * STG) * 2;
        #pragma unroll
        for (int ks = 0; ks < 4; ks++) {
            u32 ah[MI][4], al[MI][4];
            #pragma unroll
            for (int mi = 0; mi < MI; mi++) {
                u32 ad = stB + (u32)((wm * WMR + mi * 16 + aRowO) * RS + ks * 16 + aKO) * 2;
                LDMX4(ah[mi], ad);
                if (NP >= 2) LDMX4(al[mi], ad + ASZ * 2);
            }
            #pragma unroll
            for (int j = 0; j < NF / 2; j++) {
                u32 bd = stB + (u32)(NAT * ASZ + (wn * WN + j * 16 + bRowO) * RS + ks * 16 + bKO) * 2;
                u32 th[4];
                LDMX4(th, bd);
                u32 b0h[2] = { th[0], th[1] }, b1h[2] = { th[2], th[3] };
                #pragma unroll
                for (int mi = 0; mi < MI; mi++) {
                    mma_f16(acc[mi][2*j],   ah[mi], b0h);
                    mma_f16(acc[mi][2*j+1], ah[mi], b1h);
                }
                if (NP >= 2) {
                    #pragma unroll
                    for (int mi = 0; mi < MI; mi++) {
                        mma_f16(acc[mi][2*j],   al[mi], b0h);
                        mma_f16(acc[mi][2*j+1], al[mi], b1h);
                    }
                }
                if (NP == 3) {
                    u32 tl[4];
                    LDMX4(tl, bd + BSZ * 2);
                    u32 b0l[2] = { tl[0], tl[1] }, b1l[2] = { tl[2], tl[3] };
                    #pragma unroll
                    for (int mi = 0; mi < MI; mi++) {
                        mma_f16(acc[mi][2*j],   ah[mi], b0l);
                        mma_f16(acc[mi][2*j+1], ah[mi], b1l);
                    }
                }
            }
        }
        __syncthreads();
        if (c + 2 < nch) load_chunk(c + 2, c & 1);
        CP_COMMIT();
    }

    const int gid = lane >> 2, tg = lane & 3;
    #pragma unroll
    for (int mi = 0; mi < MI; mi++) {
        #pragma unroll
        for (int nf = 0; nf < NF; nf++) {
            int mA  = m0 + wm * WMR + mi * 16 + gid;
            int col = n0 + wn * WN + nf * 8 + tg * 2;
            #pragma unroll
            for (int half = 0; half < 2; half++) {
                int m = mA + half * 8;
                if (m < cnt) {
                    float v0 = acc[mi][nf][half * 2 + 0] * alpha;
                    float v1 = acc[mi][nf][half * 2 + 1] * alpha;
                    if (bptr) { v0 += bptr[col]; v1 += bptr[col + 1]; }
                    if (GELU_) { v0 = gelu_exact(v0); v1 = gelu_exact(v1); }
                    if (WF32) {
                        size_t o = (size_t)m * ldc + col;
                        Cf[o] = v0; Cf[o + 1] = v1;
                    }
                    if (WSPLIT) {
                        u16 h0, l0, h1, l1;
                        split2(v0, h0, l0); split2(v1, h1, l1);
                        size_t o;
                        if (PERM) {
                            int b = m >> 10, s = m & 1023, hh = col >> 6, d = col & 63;
                            o = ((size_t)((b * 16 + hh) * 1024 + s)) * 64 + d;
                        } else {
                            o = (size_t)m * ldc + col;
                        }
                        Ch[o] = h0; Ch[o + 1] = h1;
                        if (Cl) { Cl[o] = l0; Cl[o + 1] = l1; }
                    }
                }
            }
        }
    }
}

// =====================================================================
// Flash attention, fp16 2-product. 2 CTAs/SM. Writes O split directly
// into s_o_h / s_o_l in [tok, DIM] layout (head-merge fused).
// =====================================================================
__global__ __launch_bounds__(256, 2)
void flash_attn()
{
    extern __shared__ __align__(16) u16 smem[];
    const int z  = blockIdx.y;
    const int q0 = blockIdx.x * 128;
    const int tid = threadIdx.x, wid = tid >> 5, lane = tid & 31;
    const u32 sb = smem_u32(smem);

    constexpr int QSZ = 128 * RS;
    constexpr int KSZ = 64 * RS;
    constexpr int STG = 2 * KSZ;          // Kh, Vh
    const u32 kvB = 2 * QSZ;

    #pragma unroll
    for (int j = 0; j < 4; j++) {
        int idx = tid + j * 256;
        int row = idx >> 3, blk = idx & 7;
        size_t src = ((size_t)(z * 1024 + q0 + row)) * 64 + blk * 8;
        u32 dst = sb + (u32)(row * RS + blk * 8) * 2;
        CP16(dst,           s_qt_h + src);
        CP16(dst + QSZ * 2, s_qt_l + src);
    }
    CP_COMMIT();

    auto load_kv = [&](int c, int s) {
        const int kv0 = c * 64;
        const u32 base = sb + (kvB + (u32)s * STG) * 2;
        #pragma unroll
        for (int j = 0; j < 2; j++) {
            int idx = tid + j * 256;
            int row = idx >> 3, blk = idx & 7;
            size_t ksrc = ((size_t)(z * 1024 + kv0 + row)) * 64 + blk * 8;
            size_t vsrc = ((size_t)(z * 64 + row)) * 1024 + kv0 + blk * 8;
            u32 d = (u32)(row * RS + blk * 8) * 2;
            CP16(base + d,           s_kt_h + ksrc);
            CP16(base + d + KSZ * 2, s_vt_h + vsrc);
        }
    };

    load_kv(0, 0); CP_COMMIT();
    load_kv(1, 1); CP_COMMIT();

    const int aRowO = ((lane >> 3) & 1) * 8 + (lane & 7);
    const int aKO   = ((lane >> 4) & 1) * 8;
    const int bRowO = ((lane >> 4) & 1) * 8 + (lane & 7);
    const int bKO   = ((lane >> 3) & 1) * 8;

    CP_WAIT2();
    __syncthreads();
    u32 qhf[4][4], qlf[4][4];
    #pragma unroll
    for (int ks = 0; ks < 4; ks++) {
        u32 ad = sb + (u32)((wid * 16 + aRowO) * RS + ks * 16 + aKO) * 2;
        LDMX4(qhf[ks], ad);
        LDMX4(qlf[ks], ad + QSZ * 2);
    }

    float of[8][4];
    #pragma unroll
    for (int n = 0; n < 8; n++)
        #pragma unroll
        for (int q = 0; q < 4; q++) of[n][q] = 0.f;
    float m0 = -1e30f, m1 = -1e30f, l0 = 0.f, l1 = 0.f;

    for (int c = 0; c < 16; c++) {
        CP_WAIT1();
        __syncthreads();
        const u32 stB = sb + (kvB + (u32)((c & 1) * STG)) * 2;

        float sacc[8][4];
        #pragma unroll
        for (int n = 0; n < 8; n++)
            #pragma unroll
            for (int q = 0; q < 4; q++) sacc[n][q] = 0.f;

        #pragma unroll
        for (int ks = 0; ks < 4; ks++) {
            u32 b0h[4][2], b1h[4][2];
            #pragma unroll
            for (int j = 0; j < 4; j++) {
                u32 bd = stB + (u32)((j * 16 + bRowO) * RS + ks * 16 + bKO) * 2;
                u32 th[4];
                LDMX4(th, bd);
                b0h[j][0] = th[0]; b0h[j][1] = th[1];
                b1h[j][0] = th[2]; b1h[j][1] = th[3];
            }
            #pragma unroll
            for (int j = 0; j < 4; j++) {
                mma_f16(sacc[2*j],   qhf[ks], b0h[j]);
                mma_f16(sacc[2*j+1], qhf[ks], b1h[j]);
            }
            #pragma unroll
            for (int j = 0; j < 4; j++) {
                mma_f16(sacc[2*j],   qlf[ks], b0h[j]);
                mma_f16(sacc[2*j+1], qlf[ks], b1h[j]);
            }
        }

        float mx0 = -1e30f, mx1 = -1e30f;
        #pragma unroll
        for (int n = 0; n < 8; n++) {
            #pragma unroll
            for (int q = 0; q < 4; q++) sacc[n][q] *= 0.125f;
            mx0 = fmaxf(mx0, fmaxf(sacc[n][0], sacc[n][1]));
            mx1 = fmaxf(mx1, fmaxf(sacc[n][2], sacc[n][3]));
        }
        mx0 = fmaxf(mx0, __shfl_xor_sync(0xffffffffu, mx0, 1));
        mx0 = fmaxf(mx0, __shfl_xor_sync(0xffffffffu, mx0, 2));
        mx1 = fmaxf(mx1, __shfl_xor_sync(0xffffffffu, mx1, 1));
        mx1 = fmaxf(mx1, __shfl_xor_sync(0xffffffffu, mx1, 2));
        float mn0 = fmaxf(m0, mx0), mn1 = fmaxf(m1, mx1);
        float sc0 = __expf(m0 - mn0), sc1 = __expf(m1 - mn1);
        m0 = mn0; m1 = mn1;
        float ps0 = 0.f, ps1 = 0.f;
        #pragma unroll
        for (int n = 0; n < 8; n++) {
            sacc[n][0] = __expf(sacc[n][0] - mn0);
            sacc[n][1] = __expf(sacc[n][1] - mn0);
            sacc[n][2] = __expf(sacc[n][2] - mn1);
            sacc[n][3] = __expf(sacc[n][3] - mn1);
            ps0 += sacc[n][0] + sacc[n][1];
            ps1 += sacc[n][2] + sacc[n][3];
        }
        ps0 += __shfl_xor_sync(0xffffffffu, ps0, 1);
        ps0 += __shfl_xor_sync(0xffffffffu, ps0, 2);
        ps1 += __shfl_xor_sync(0xffffffffu, ps1, 1);
        ps1 += __shfl_xor_sync(0xffffffffu, ps1, 2);
        l0 = l0 * sc0 + ps0;
        l1 = l1 * sc1 + ps1;
        #pragma unroll
        for (int n = 0; n < 8; n++) {
            of[n][0] *= sc0; of[n][1] *= sc0;
            of[n][2] *= sc1; of[n][3] *= sc1;
        }

        #pragma unroll
        for (int kk = 0; kk < 4; kk++) {
            u32 ph[4], pl[4];
            split_pack2(sacc[2*kk][0],   sacc[2*kk][1],   ph[0], pl[0]);
            split_pack2(sacc[2*kk][2],   sacc[2*kk][3],   ph[1], pl[1]);
            split_pack2(sacc[2*kk+1][0], sacc[2*kk+1][1], ph[2], pl[2]);
            split_pack2(sacc[2*kk+1][2], sacc[2*kk+1][3], ph[3], pl[3]);
            u32 b0h[4][2], b1h[4][2];
            #pragma unroll
            for (int j2 = 0; j2 < 4; j2++) {
                u32 vd = stB + (u32)(KSZ) * 2
                       + (u32)((j2 * 16 + bRowO) * RS + kk * 16 + bKO) * 2;
                u32 th[4];
                LDMX4(th, vd);
                b0h[j2][0] = th[0]; b0h[j2][1] = th[1];
                b1h[j2][0] = th[2]; b1h[j2][1] = th[3];
            }
            #pragma unroll
            for (int j2 = 0; j2 < 4; j2++) {
                mma_f16(of[2*j2],   ph, b0h[j2]);
                mma_f16(of[2*j2+1], ph, b1h[j2]);
            }
            #pragma unroll
            for (int j2 = 0; j2 < 4; j2++) {
                mma_f16(of[2*j2],   pl, b0h[j2]);
                mma_f16(of[2*j2+1], pl, b1h[j2]);
            }
        }
        __syncthreads();
        if (c + 2 < 16) load_kv(c + 2, c & 1);
        CP_COMMIT();
    }

    // ---- epilogue: write O split directly in [tok, DIM] layout ----
    const int gid = lane >> 2, tg = lane & 3;
    float inv0 = 1.f / l0, inv1 = 1.f / l1;
    const int b = z >> 4, h = z & 15;
    const int qr = q0 + wid * 16 + gid;
    const size_t base0 = ((size_t)((b << 10) + qr)) * 1024 + h * 64;
    const size_t base1 = ((size_t)((b << 10) + qr + 8)) * 1024 + h * 64;
    #pragma unroll
    for (int n = 0; n < 8; n++) {
        int dh = n * 8 + tg * 2;
        u32 h0, lo0, h1, lo1;
        split_pack2(of[n][0] * inv0, of[n][1] * inv0, h0, lo0);
        split_pack2(of[n][2] * inv1, of[n][3] * inv1, h1, lo1);
        *(u32*)&s_o_h[base0 + dh] = h0;
        *(u32*)&s_o_l[base0 + dh] = lo0;
        *(u32*)&s_o_h[base1 + dh] = h1;
        *(u32*)&s_o_l[base1 + dh] = lo1;
    }
}

// ---------------- fused conversion ----------------
struct SplitSegs {
    const float4* s[4];
    uint2* h[4];
    uint2* l[4];
    int end4[4];
};
__global__ void split_all(SplitSegs g) {
    const int total = g.end4[3];
    for (int i = blockIdx.x * blockDim.x + threadIdx.x; i < total; i += gridDim.x * blockDim.x) {
        int k = 0;
        #pragma unroll
        for (int t = 0; t < 3; t++) k += (i >= g.end4[t]) ? 1 : 0;
        int j = i - (k ? g.end4[k - 1] : 0);
        float4 v = g.s[k][j];
        u16 hh[4], ll[4];
        split2(v.x, hh[0], ll[0]); split2(v.y, hh[1], ll[1]);
        split2(v.z, hh[2], ll[2]); split2(v.w, hh[3], ll[3]);
        g.h[k][j] = *(uint2*)hh;
        if (g.l[k]) g.l[k][j] = *(uint2*)ll;
    }
}

__global__ void transpose_split(const float* __restrict__ s, u16* __restrict__ oh, u16* __restrict__ ol,
                                int R, int C) {
    __shared__ float t[32][33];
    size_t zo = (size_t)blockIdx.z * R * C;
    const float* src = s + zo;
    int c0 = blockIdx.x * 32, r0 = blockIdx.y * 32;
    int tx = threadIdx.x & 31, ty = threadIdx.x >> 5;
    #pragma unroll
    for (int dy = 0; dy < 32; dy += 8)
        t[ty + dy][tx] = src[(size_t)(r0 + ty + dy) * C + c0 + tx];
    __syncthreads();
    #pragma unroll
    for (int dy = 0; dy < 32; dy += 8) {
        float v = t[tx][ty + dy];
        size_t o = zo + (size_t)(c0 + ty + dy) * R + r0 + tx;
        u16 hh, ll; split2(v, hh, ll);
        oh[o] = hh;
        if (ol) ol[o] = ll;
    }
}

// bc[i] = sum_m W[i,m]*bin[m] + badd[i]
__global__ void bias_comb(const float* __restrict__ W, const float* __restrict__ bin,
                          const float* __restrict__ badd, float* __restrict__ bc) {
    __shared__ float sm[32];
    int i = blockIdx.x, t = threadIdx.x;
    float s = 0.f;
    for (int m = t; m < DIM; m += 256) s += W[(size_t)i * DIM + m] * bin[m];
    s = blk_reduce_sum(s, sm);
    if (t == 0) bc[i] = s + badd[i];
}

__global__ void headsplit_vT(const float* __restrict__ in, u16* __restrict__ oh) {
    __shared__ float t[32][33];
    int z = blockIdx.z;
    int b = z >> 4, h = z & 15;
    int s0 = blockIdx.x * 32, d0 = blockIdx.y * 32;
    int tx = threadIdx.x & 31, ty = threadIdx.x >> 5;
    #pragma unroll
    for (int dy = 0; dy < 32; dy += 8)
        t[ty + dy][tx] = in[(size_t)((b << 10) + s0 + ty + dy) * DIM + h * 64 + d0 + tx];
    __syncthreads();
    #pragma unroll
    for (int dy = 0; dy < 32; dy += 8) {
        float v = t[tx][ty + dy];
        size_t o = (size_t)(z * 64 + d0 + ty + dy) * 1024 + s0 + tx;
        oh[o] = f2h(v);
    }
}

// LN(a+res) -> fp32 + single fp16
__global__ void ln_res_split(const float* __restrict__ a, const float* __restrict__ res,
                             const float* __restrict__ g, const float* __restrict__ b,
                             float* __restrict__ of, u16* __restrict__ oh) {
    __shared__ float sm[32];
    const size_t base = (size_t)blockIdx.x * DIM;
    int t = threadIdx.x;
    float v[4];
    float s = 0.f;
    #pragma unroll
    for (int j = 0; j < 4; j++) {
        int c = t + j * 256;
        v[j] = a[base + c] + res[base + c];
        s += v[j];
    }
    s = blk_reduce_sum(s, sm);
    float mean = s * (1.0f / DIM);
    float s2 = 0.f;
    #pragma unroll
    for (int j = 0; j < 4; j++) { float d = v[j] - mean; s2 += d * d; }
    s2 = blk_reduce_sum(s2, sm);
    float rs = rsqrtf(s2 * (1.0f / DIM) + 1e-5f);
    #pragma unroll
    for (int j = 0; j < 4; j++) {
        int c = t + j * 256;
        float o = (v[j] - mean) * rs * g[c] + b[c];
        of[base + c] = o;
        oh[base + c] = f2h(o);
    }
}

__global__ void combine_ln(const float* __restrict__ g, const float* __restrict__ b,
                           float* __restrict__ out) {
    __shared__ float sm[32];
    const int tok = blockIdx.x;
    const size_t base = (size_t)tok * DIM;
    int t = threadIdx.x;
    float v[4];
    #pragma unroll
    for (int j = 0; j < 4; j++) v[j] = g_x[base + t + j * 256];
    const int nl = g_tcnt[tok];
    for (int l = 0; l < nl; l++) {
        int   e    = g_te[tok * 3 + l];
        int   slot = g_tslot[tok * 3 + l];
        float gt   = g_tgate[tok * 3 + l];
        const float* row = g_e2 + ((size_t)e * NTOK + slot) * DIM;
        #pragma unroll
        for (int j = 0; j < 4; j++) v[j] += gt * row[t + j * 256];
    }
    float s = 0.f;
    #pragma unroll
    for (int j = 0; j < 4; j++) s += v[j];
    s = blk_reduce_sum(s, sm);
    float mean = s * (1.0f / DIM);
    float s2 = 0.f;
    #pragma unroll
    for (int j = 0; j < 4; j++) { float d = v[j] - mean; s2 += d * d; }
    s2 = blk_reduce_sum(s2, sm);
    float rs = rsqrtf(s2 * (1.0f / DIM) + 1e-5f);
    #pragma unroll
    for (int j = 0; j < 4; j++) {
        int c = t + j * 256;
        out[base + c] = (v[j] - mean) * rs * g[c] + b[c];
    }
}

__global__ void gating(const float* __restrict__ Wg) {
    __shared__ float logits[NEXP];
    const int tok = blockIdx.x;
    const float* xr = g_x + (size_t)tok * DIM;
    int w = threadIdx.x >> 5, lane = threadIdx.x & 31;
    float s = 0.f;
    for (int i = lane; i < DIM; i += 32) s += xr[i] * Wg[i * NEXP + w];
    #pragma unroll
    for (int o = 16; o; o >>= 1) s += __shfl_down_sync(0xffffffffu, s, o);
    if (!lane) logits[w] = s;
    __syncthreads();
    if (threadIdx.x == 0) {
        float p[NEXP];
        float mx = -1e30f;
        for (int e = 0; e < NEXP; e++) mx = fmaxf(mx, logits[e]);
        float sum = 0.f;
        for (int e = 0; e < NEXP; e++) { p[e] = __expf(logits[e] - mx); sum += p[e]; }
        float inv = 1.f / sum;
        for (int e = 0; e < NEXP; e++) { p[e] *= inv; g_probs[tok * NEXP + e] = p[e]; }
        int i0 = 0;
        for (int e = 1; e < NEXP; e++) if (p[e] > p[i0]) i0 = e;
        int i1 = -1;
        for (int e = 0; e < NEXP; e++) if (e != i0 && (i1 < 0 || p[e] > p[i1])) i1 = e;
        int i2 = -1;
        for (int e = 0; e < NEXP; e++) if (e != i0 && e != i1 && (i2 < 0 || p[e] > p[i2])) i2 = e;
        int   ids[3] = { i0, i1, i2 };
        float gts[3] = { p[i0],
                         (p[i1] >= THRESH) ? p[i1] : 0.f,
                         (p[i2] >= THRESH) ? p[i2] : 0.f };
        int nl = 0;
        #pragma unroll
        for (int j = 0; j < 3; j++) {
            if (gts[j] > 0.f) {
                int slot = atomicAdd(&g_cnt[ids[j]], 1);
                g_tok  [ids[j] * NTOK + slot] = tok;
                g_te   [tok * 3 + nl] = ids[j];
                g_tslot[tok * 3 + nl] = slot;
                g_tgate[tok * 3 + nl] = gts[j];
                nl++;
            }
        }
        g_tcnt[tok] = nl;
    }
}

__global__ void zero_small() {
    int t = threadIdx.x;
    if (t < NEXP) g_cnt[t] = 0;
}
__global__ void aux_kernel(float* __restrict__ out, int out_size) {
    if (out_size <= OUT_MAIN) return;
    __shared__ float sm[32];
    int t = threadIdx.x;
    float total = 0.f;
    for (int e = 0; e < NEXP; e++) {
        float s = 0.f;
        for (int tok = t; tok < NTOK; tok += 256) s += g_probs[tok * NEXP + e];
        s = blk_reduce_sum(s, sm);
        if (t == 0) total += ((float)g_cnt[e] / (float)NTOK) * (s / (float)NTOK);
    }
    if (t == 0) out[OUT_MAIN] = COEF * (float)NEXP * total;
}

// ---------------- host launcher ----------------
#define GETSYM(var, sym) do { cudaGetSymbolAddress((void**)&(var), sym); } while (0)

extern "C" void kernel_launch(void* const* d_in, const int* in_sizes, int n_in,
                              void* d_out, int out_size)
{
    (void)in_sizes; (void)n_in;
    const float* query  = (const float*)d_in[0];
    const float* keyval = (const float*)d_in[1];
    const float* Wq = (const float*)d_in[2];  const float* bq = (const float*)d_in[3];
    const float* Wk = (const float*)d_in[4];  const float* bk = (const float*)d_in[5];
    const float* Wv = (const float*)d_in[6];  const float* bv = (const float*)d_in[7];
    const float* W_in  = (const float*)d_in[8];  const float* b_in  = (const float*)d_in[9];
    const float* W_out = (const float*)d_in[10]; const float* b_out = (const float*)d_in[11];
    const float* Wa = (const float*)d_in[12]; const float* ba = (const float*)d_in[13];
    const float* ln1g = (const float*)d_in[14]; const float* ln1b = (const float*)d_in[15];
    const float* Wg = (const float*)d_in[16];
    const float* ew1 = (const float*)d_in[17]; const float* eb1 = (const float*)d_in[18];
    const float* ew2 = (const float*)d_in[19]; const float* eb2 = (const float*)d_in[20];
    const float* ln2g = (const float*)d_in[21]; const float* ln2b = (const float*)d_in[22];
    float* out = (float*)d_out;

    float *vh, *a, *x, *e2p, *bc;
    GETSYM(vh, g_vh); GETSYM(a, g_a); GETSYM(x, g_x);
    GETSYM(e2p, g_e2); GETSYM(bc, g_bc);
    u16 *qyh,*kvh,*qth,*qtl,*kth,*vth,*oh,*ol,*xh,*hhh;
    u16 *wAh,*wAl,*wTh,*wTl,*wch,*wcl,*e1h,*e2h;
    GETSYM(qyh, s_query_h);
    GETSYM(kvh, s_kv_h);
    GETSYM(qth, s_qt_h); GETSYM(qtl, s_qt_l);
    GETSYM(kth, s_kt_h);
    GETSYM(vth, s_vt_h);
    GETSYM(oh,  s_o_h);  GETSYM(ol,  s_o_l);
    GETSYM(xh,  s_x_h);
    GETSYM(hhh, s_hh);
    GETSYM(wAh, s_wA_h); GETSYM(wAl, s_wA_l);
    GETSYM(wTh, s_wT_h); GETSYM(wTl, s_wT_l);
    GETSYM(wch, s_wc_h); GETSYM(wcl, s_wc_l);
    GETSYM(e1h, s_e1_h); GETSYM(e2h, s_e2_h);
    int *tokp; GETSYM(tokp, g_tok);
    int *cntp; GETSYM(cntp, g_cnt);

    const int SM_NP1 = 2 * (256 + 128) * RS * 2;            // 110592 B
    const int SM_NP2 = 2 * (2 * 256 + 128) * RS * 2;        // 184320 B
    const int SM_NP3 = 2 * (2 * 256 + 2 * 128) * RS * 2;    // 221184 B
    const int SFLASH = (2 * 128 + 2 * 2 * 64) * RS * 2;     // 73728 B
    cudaFuncSetAttribute((const void*)gemm_tc<1,256,128,false,false,true ,false,true >, cudaFuncAttributeMaxDynamicSharedMemorySize, SM_NP1);
    cudaFuncSetAttribute((const void*)gemm_tc<1,256,128,false,true ,false,false,false>, cudaFuncAttributeMaxDynamicSharedMemorySize, SM_NP1);
    cudaFuncSetAttribute((const void*)gemm_tc<1,256,128,true ,false,true ,true ,false>, cudaFuncAttributeMaxDynamicSharedMemorySize, SM_NP1);
    cudaFuncSetAttribute((const void*)gemm_tc<2,256,128,false,true ,false,false,false>, cudaFuncAttributeMaxDynamicSharedMemorySize, SM_NP2);
    cudaFuncSetAttribute((const void*)gemm_tc<3,256,128,false,false,true ,false,false>, cudaFuncAttributeMaxDynamicSharedMemorySize, SM_NP3);
    cudaFuncSetAttribute((const void*)flash_attn, cudaFuncAttributeMaxDynamicSharedMemorySize, SFLASH);

    const dim3 T512(512);
    const dim3 T256(256);
    const dim3 GLIN(DIM/128, NTOK/256, 1);

    // ---- fused fp16 split: inputs hi-only, A-side weights hi+lo ----
    SplitSegs sg;
    sg.s[0] = (const float4*)query;  sg.h[0] = (uint2*)qyh;  sg.l[0] = nullptr;
    sg.s[1] = (const float4*)keyval; sg.h[1] = (uint2*)kvh;  sg.l[1] = nullptr;
    sg.s[2] = (const float4*)W_in;   sg.h[2] = (uint2*)wAh;  sg.l[2] = (uint2*)wAl;
    sg.s[3] = (const float4*)Wa;     sg.h[3] = (uint2*)(wAh + 3*DIM*DIM);
    sg.l[3] = (uint2*)(wAl + 3*DIM*DIM);
    sg.end4[0] = NTOK*DIM/4;
    sg.end4[1] = sg.end4[0] + NTOK*DIM/4;
    sg.end4[2] = sg.end4[1] + 3*DIM*DIM/4;
    sg.end4[3] = sg.end4[2] + DIM*DIM/4;
    split_all<<<2048, 256>>>(sg);

    // ---- transposed splits of B-side weights into packed array ----
    transpose_split<<<dim3(DIM/32, DIM/32, 1), T256>>>(Wq,    wTh,             wTl,             DIM, DIM);
    transpose_split<<<dim3(DIM/32, DIM/32, 1), T256>>>(Wk,    wTh + DIM*DIM,   wTl + DIM*DIM,   DIM, DIM);
    transpose_split<<<dim3(DIM/32, DIM/32, 1), T256>>>(Wv,    wTh + 2*DIM*DIM, wTl + 2*DIM*DIM, DIM, DIM);
    transpose_split<<<dim3(DIM/32, DIM/32, 1), T256>>>(W_out, wTh + 3*DIM*DIM, wTl + 3*DIM*DIM, DIM, DIM);

    // ---- BATCHED weight composition (z=0..3): Wc[z] = WA[z] @ WT[z]^T ----
    gemm_tc<3,256,128,false,false,true,false,false><<<dim3(DIM/128, DIM/256, 4), T512, SM_NP3>>>(
        wAh, wAl, wTh, wTl, DIM,
        (long long)DIM*DIM, (long long)DIM*DIM, (long long)DIM*DIM,
        nullptr, nullptr, nullptr, 0, 1.f, nullptr, wch, wcl, DIM);

    // ---- combined biases (fp32 exact) ----
    bias_comb<<<DIM, T256>>>(W_in,              bq,    b_in,           bc);
    bias_comb<<<DIM, T256>>>(W_in + DIM*DIM,    bk,    b_in + DIM,     bc + DIM);
    bias_comb<<<DIM, T256>>>(W_in + 2*DIM*DIM,  bv,    b_in + 2*DIM,   bc + 2*DIM);
    bias_comb<<<DIM, T256>>>(Wa,                b_out, ba,             bc + 3*DIM);

    // ---- token linears (NP=1); q/k write permuted split directly ----
    gemm_tc<1,256,128,false,false,true,false,true><<<GLIN, T512, SM_NP1>>>(
        qyh, nullptr, wch,             nullptr, DIM, 0, 0, 0, nullptr, nullptr, bc,         0, 1.f, nullptr, qth, qtl, DIM);
    gemm_tc<1,256,128,false,false,true,false,true><<<GLIN, T512, SM_NP1>>>(
        kvh, nullptr, wch + DIM*DIM,   nullptr, DIM, 0, 0, 0, nullptr, nullptr, bc + DIM,   0, 1.f, nullptr, kth, nullptr, DIM);
    gemm_tc<1,256,128,false,true,false,false,false><<<GLIN, T512, SM_NP1>>>(
        kvh, nullptr, wch + 2*DIM*DIM, nullptr, DIM, 0, 0, 0, nullptr, nullptr, bc + 2*DIM, 0, 1.f, vh, nullptr, nullptr, DIM);

    // ---- v transpose reshape ----
    headsplit_vT<<<dim3(SQL/32, 2, BH), T256>>>(vh, vth);

    // ---- fused flash attention -> s_o_h/s_o_l directly ----
    flash_attn<<<dim3(SQL/128, BH), T256, SFLASH>>>();

    // ---- combined out-projection + adapter (NP=2) ----
    gemm_tc<2,256,128,false,true,false,false,false><<<GLIN, T512, SM_NP2>>>(
        oh, ol, wch + 3*DIM*DIM, nullptr, DIM, 0, 0, 0, nullptr, nullptr, bc + 3*DIM, 0, 1.f, a, nullptr, nullptr, DIM);

    // ---- LN1 (+residual) -> x fp32 + fp16 ----
    ln_res_split<<<NTOK, T256>>>(a, query, ln1g, ln1b, x, xh);

    // ---- gating ----
    zero_small<<<1, 32>>>();
    gating<<<NTOK, T256>>>(Wg);

    // ---- MoE expert weights (hi only) + FFNs (NP=1, pure fp16) ----
    transpose_split<<<dim3(HDIM/32, DIM/32, NEXP), T256>>>(ew1, e1h, nullptr, DIM, HDIM);
    transpose_split<<<dim3(DIM/32, HDIM/32, NEXP), T256>>>(ew2, e2h, nullptr, HDIM, DIM);
    gemm_tc<1,256,128,true,false,true,true,false><<<dim3(HDIM/128, NTOK/256, NEXP), T512, SM_NP1>>>(
        xh, nullptr, e1h, nullptr, DIM,
        0, (long long)HDIM*DIM, (long long)NTOK*HDIM,
        tokp, cntp, eb1, HDIM, 1.f, nullptr, hhh, nullptr, HDIM);
    gemm_tc<1,256,128,false,true,false,false,false><<<dim3(DIM/128, NTOK/256, NEXP), T512, SM_NP1>>>(
        hhh, nullptr, e2h, nullptr, HDIM,
        (long long)NTOK*HDIM, (long long)DIM*HDIM, (long long)NTOK*DIM,
        nullptr, cntp, eb2, DIM, 1.f, e2p, nullptr, nullptr, DIM);

    // ---- fused combine + final LN -> output, then aux scalar ----
    combine_ln<<<NTOK, T256>>>(ln2g, ln2b, out);
    aux_kernel<<<1, 256>>>(out, out_size);
}